// round 8
// baseline (speedup 1.0000x reference)
#include <cuda_runtime.h>
#include <math.h>

#define CB 2
#define CN 512
#define CF 1024
#define CH 4
#define CDH 256
#define CAH 256
#define CHID 512
#define COUT 128
#define CNCLS 10
#define CNN (CN*CN)
#define RSEL 52429u   /* NN - int(0.8*NN) = 262144 - 209715 */

// ---------------- scratch (static device memory; no allocations) ----------------
__device__ float g_hp[CB*CN*CF];
__device__ float g_si[CB*CH*CN];
__device__ float g_sj[CB*CH*CN];
__device__ float g_alpha[CB*CH*CN*CN];
__device__ float g_nf[CB*CN*CF];
__device__ float g_pij[2*CB*CN*CAH];
__device__ float g_edge[CB*CNN];
__device__ float g_cm[CB*CNN];
__device__ float g_h1[CB*CN*CF];
__device__ float g_h2[CB*CN*CHID];
__device__ float g_h3[CB*CN*CHID];
__device__ float g_h4[CB*CN*COUT];
__device__ float g_h4p[4*CB*CN*COUT];
__device__ float g_feat[CB*COUT];
__device__ unsigned g_hist[CB*65536];
__device__ unsigned g_selhi[CB];
__device__ unsigned g_rank2[CB];
__device__ unsigned g_maxkey[CB];
__device__ float g_thr[CB];
__device__ float g_msum[CB];
__device__ float g_bs1[CHID], g_bq1[CHID], g_sc1[CHID], g_sh1[CHID];
__device__ float g_bs2[COUT], g_bq2[COUT], g_sc2[COUT], g_sh2[COUT];

// ---------------- helpers ----------------
__device__ __forceinline__ unsigned key_of(float x) {
    unsigned u = __float_as_uint(x);
    return (u & 0x80000000u) ? ~u : (u | 0x80000000u);
}
__device__ __forceinline__ float key_inv(unsigned key) {
    unsigned u = (key & 0x80000000u) ? (key ^ 0x80000000u) : ~key;
    return __uint_as_float(u);
}
__device__ __forceinline__ unsigned long long pk2(float lo, float hi) {
    unsigned long long r;
    asm("mov.b64 %0, {%1, %2};" : "=l"(r) : "f"(lo), "f"(hi));
    return r;
}
__device__ __forceinline__ void fma2(unsigned long long& d, unsigned long long a, unsigned long long b) {
    asm("fma.rn.f32x2 %0, %1, %2, %0;" : "+l"(d) : "l"(a), "l"(b));
}
__device__ __forceinline__ float2 up2(unsigned long long v) {
    float2 f;
    asm("mov.b64 {%0, %1}, %2;" : "=f"(f.x), "=f"(f.y) : "l"(v));
    return f;
}

// ---------------- zero scratch (must run every launch; graph replays) ----------------
__global__ void k_zero() {
    int i = blockIdx.x * 256 + threadIdx.x;       // grid = 512 blocks -> 131072 threads
    g_hist[i] = 0;
    if (i < CHID) { g_bs1[i] = 0.f; g_bq1[i] = 0.f; }
    if (i < COUT) { g_bs2[i] = 0.f; g_bq2[i] = 0.f; }
    if (i < CB)   { g_msum[i] = 0.f; g_maxkey[i] = 0u; }
}

// ====== f32x2 SGEMM: tile M64 x N128, 128 threads, 8x8 microtile, double-buffered ======
// C[m,n] = scale * sum_k A[m,k]*B'[k,n].
// BT=true : B given as [n][k] row-major (ld=ldb), i.e. C = A @ B^T
// BT=false: B given as [k][n] row-major (ld=ldb)
// batch z: zo=z/bdiv, zi=z%bdiv; pointers offset by zo*s?o + zi*s?i
// scale = scalep ? scalep[zo] : 1
template<bool BT>
__global__ void __launch_bounds__(128) gemm_t(
    const float* __restrict__ A, const float* __restrict__ Bm, float* __restrict__ C,
    int K, int lda, int ldb, int ldc,
    int bdiv, long long sAo, long long sAi, long long sBo, long long sBi,
    long long sCo, long long sCi, const float* __restrict__ scalep)
{
    int z = blockIdx.z;
    int zo = z / bdiv, zi = z - zo * bdiv;
    A  += zo * sAo + zi * sAi;
    Bm += zo * sBo + zi * sBi;
    C  += zo * sCo + zi * sCi;

    __shared__ __align__(16) float As[2][16][68];
    __shared__ __align__(16) float Bs[2][16][128];

    int t = threadIdx.x;
    int tx = t & 15, ty = t >> 4;
    int m0 = blockIdx.y * 64, n0 = blockIdx.x * 128;

    // A: thread handles row m0 + (t>>1), k-range (t&1)*8 .. +8 (2 float4)
    int am = t >> 1;
    int ak = (t & 1) * 8;
    const float* Ap = A + (size_t)(m0 + am) * lda + ak;

    // B load pointers
    const float* Bp0 = 0;       // BT path
    const float* BqBase[4];     // non-BT path
    int bnc[4];
    if (BT) {
        Bp0 = Bm + (size_t)(n0 + t) * ldb;          // 4 float4 along k per chunk
    } else {
        #pragma unroll
        for (int c = 0; c < 4; c++) {
            int q = t + 128 * c;
            bnc[c] = (q & 31) * 4;
            BqBase[c] = Bm + (size_t)(q >> 5) * ldb + n0 + bnc[c];
        }
    }

    float4 ra[2], rb[4];
    // chunk 0 loads
    ra[0] = *(const float4*)(Ap);
    ra[1] = *(const float4*)(Ap + 4);
    if (BT) {
        #pragma unroll
        for (int c = 0; c < 4; c++) rb[c] = *(const float4*)(Bp0 + c * 4);
    } else {
        #pragma unroll
        for (int c = 0; c < 4; c++) rb[c] = *(const float4*)(BqBase[c]);
    }

    unsigned long long acc[8][4];
    #pragma unroll
    for (int i = 0; i < 8; i++)
        #pragma unroll
        for (int j = 0; j < 4; j++) acc[i][j] = 0ull;

    // store chunk 0 into buffer 0
    #pragma unroll
    for (int c = 0; c < 2; c++) {
        float v[4] = {ra[c].x, ra[c].y, ra[c].z, ra[c].w};
        #pragma unroll
        for (int e = 0; e < 4; e++) As[0][ak + c * 4 + e][am] = v[e];
    }
    if (BT) {
        #pragma unroll
        for (int c = 0; c < 4; c++) {
            float v[4] = {rb[c].x, rb[c].y, rb[c].z, rb[c].w};
            #pragma unroll
            for (int e = 0; e < 4; e++) Bs[0][c * 4 + e][t] = v[e];
        }
    } else {
        #pragma unroll
        for (int c = 0; c < 4; c++) {
            int q = t + 128 * c;
            *(float4*)&Bs[0][q >> 5][bnc[c]] = rb[c];
        }
    }
    __syncthreads();

    int buf = 0;
    int k0 = 16;
    for (;;) {
        bool more = k0 < K;
        if (more) {
            // prefetch next chunk into registers
            ra[0] = *(const float4*)(Ap + k0);
            ra[1] = *(const float4*)(Ap + k0 + 4);
            if (BT) {
                #pragma unroll
                for (int c = 0; c < 4; c++) rb[c] = *(const float4*)(Bp0 + k0 + c * 4);
            } else {
                #pragma unroll
                for (int c = 0; c < 4; c++)
                    rb[c] = *(const float4*)(BqBase[c] + (size_t)k0 * ldb);
            }
        }

        // compute on current buffer
        #pragma unroll
        for (int kk = 0; kk < 16; kk++) {
            float4 a0 = *(const float4*)&As[buf][kk][ty * 4];
            float4 a1 = *(const float4*)&As[buf][kk][32 + ty * 4];
            ulonglong2 b0 = *(const ulonglong2*)&Bs[buf][kk][tx * 4];
            ulonglong2 b1 = *(const ulonglong2*)&Bs[buf][kk][64 + tx * 4];
            unsigned long long ap[8] = {
                pk2(a0.x, a0.x), pk2(a0.y, a0.y), pk2(a0.z, a0.z), pk2(a0.w, a0.w),
                pk2(a1.x, a1.x), pk2(a1.y, a1.y), pk2(a1.z, a1.z), pk2(a1.w, a1.w)};
            unsigned long long bp[4] = {b0.x, b0.y, b1.x, b1.y};
            #pragma unroll
            for (int i = 0; i < 8; i++)
                #pragma unroll
                for (int j = 0; j < 4; j++)
                    fma2(acc[i][j], ap[i], bp[j]);
        }
        if (!more) break;

        // store prefetched chunk into the other buffer
        int nb = buf ^ 1;
        #pragma unroll
        for (int c = 0; c < 2; c++) {
            float v[4] = {ra[c].x, ra[c].y, ra[c].z, ra[c].w};
            #pragma unroll
            for (int e = 0; e < 4; e++) As[nb][ak + c * 4 + e][am] = v[e];
        }
        if (BT) {
            #pragma unroll
            for (int c = 0; c < 4; c++) {
                float v[4] = {rb[c].x, rb[c].y, rb[c].z, rb[c].w};
                #pragma unroll
                for (int e = 0; e < 4; e++) Bs[nb][c * 4 + e][t] = v[e];
            }
        } else {
            #pragma unroll
            for (int c = 0; c < 4; c++) {
                int q = t + 128 * c;
                *(float4*)&Bs[nb][q >> 5][bnc[c]] = rb[c];
            }
        }
        buf = nb;
        k0 += 16;
        __syncthreads();
    }

    float sc = scalep ? scalep[zo] : 1.0f;
    #pragma unroll
    for (int g = 0; g < 2; g++)
        #pragma unroll
        for (int r = 0; r < 4; r++) {
            int i = g * 4 + r;
            int row = m0 + g * 32 + ty * 4 + r;
            float2 x0 = up2(acc[i][0]), x1 = up2(acc[i][1]);
            float2 x2 = up2(acc[i][2]), x3 = up2(acc[i][3]);
            *(float4*)&C[(size_t)row * ldc + n0 + tx * 4] =
                make_float4(x0.x * sc, x0.y * sc, x1.x * sc, x1.y * sc);
            *(float4*)&C[(size_t)row * ldc + n0 + 64 + tx * 4] =
                make_float4(x2.x * sc, x2.y * sc, x3.x * sc, x3.y * sc);
        }
}

// ---------------- attention scores s_i/s_j ----------------
__global__ void k_sij(const float* __restrict__ attn) {
    int bn = blockIdx.x;                      // b*512 + n
    __shared__ float row[CF];
    for (int i = threadIdx.x; i < CF; i += 256) row[i] = g_hp[(size_t)bn * CF + i];
    __syncthreads();
    int w = threadIdx.x >> 5, lane = threadIdx.x & 31;
    int h = w >> 1, part = w & 1;             // 8 warps: 4 heads x {i,j}
    const float* av = attn + h * (2*CDH) + part * CDH;
    float s = 0.f;
    for (int d = lane; d < CDH; d += 32) s += row[h*CDH + d] * av[d];
#pragma unroll
    for (int o = 16; o; o >>= 1) s += __shfl_xor_sync(0xffffffffu, s, o);
    if (!lane) {
        int b = bn >> 9, n = bn & 511;
        float* dst = part ? g_sj : g_si;
        dst[(b*CH + h)*CN + n] = s;
    }
}

// ---------------- leakyrelu + row softmax -> alpha ----------------
__global__ void k_alpha() {
    int row = blockIdx.x;                     // (b*H + h)*512 + i
    int bh = row >> 9;
    float s_i = g_si[row];
    const float* sjr = g_sj + bh * CN;
    __shared__ float shm[8], shs[8];
    int t = threadIdx.x, lane = t & 31, w = t >> 5;
    float e0 = s_i + sjr[t];       e0 = e0 >= 0.f ? e0 : 0.2f * e0;
    float e1 = s_i + sjr[t + 256]; e1 = e1 >= 0.f ? e1 : 0.2f * e1;
    float m = fmaxf(e0, e1);
#pragma unroll
    for (int o = 16; o; o >>= 1) m = fmaxf(m, __shfl_xor_sync(0xffffffffu, m, o));
    if (!lane) shm[w] = m;
    __syncthreads();
    if (t < 32) {
        float v = (t < 8) ? shm[t] : -INFINITY;
#pragma unroll
        for (int o = 4; o; o >>= 1) v = fmaxf(v, __shfl_xor_sync(0xffffffffu, v, o));
        if (t == 0) shm[0] = v;
    }
    __syncthreads();
    float bm = shm[0];
    float x0 = expf(e0 - bm), x1 = expf(e1 - bm);
    float s = x0 + x1;
#pragma unroll
    for (int o = 16; o; o >>= 1) s += __shfl_xor_sync(0xffffffffu, s, o);
    if (!lane) shs[w] = s;
    __syncthreads();
    if (t < 32) {
        float v = (t < 8) ? shs[t] : 0.f;
#pragma unroll
        for (int o = 4; o; o >>= 1) v += __shfl_xor_sync(0xffffffffu, v, o);
        if (t == 0) shs[0] = v;
    }
    __syncthreads();
    float inv = 1.f / shs[0];
    g_alpha[(size_t)row * CN + t]       = x0 * inv;
    g_alpha[(size_t)row * CN + t + 256] = x1 * inv;
}

// ------- edge scores: sum_a relu(pi+pj+b1)*w2 + b2; 32x32 tile, 2x2 microtile -------
__global__ void __launch_bounds__(256) k_edge(
    const float* __restrict__ b1, const float* __restrict__ w2,
    const float* __restrict__ b2)
{
    int b = blockIdx.z;
    int i0 = blockIdx.y * 32, j0 = blockIdx.x * 32;
    __shared__ __align__(16) float Pi[32][132], Pj[32][132];
    __shared__ float B1s[128], W2s[128];
    const float* pi = g_pij;
    const float* pj = g_pij + (size_t)CB*CN*CAH;
    int t = threadIdx.x;
    int ti = t >> 4, tj = t & 15;
    float acc[2][2] = {};
    for (int a0 = 0; a0 < CAH; a0 += 128) {
        if (t < 128) { B1s[t] = b1[a0 + t]; W2s[t] = w2[a0 + t]; }
        #pragma unroll
        for (int c = 0; c < 4; c++) {
            int q = t + 256 * c;            // 0..1023 over 32 rows x 32 float4
            int r = q >> 5, nc = (q & 31) * 4;
            *(float4*)&Pi[r][nc] = *(const float4*)&pi[(size_t)(b*CN + i0 + r) * CAH + a0 + nc];
            *(float4*)&Pj[r][nc] = *(const float4*)&pj[(size_t)(b*CN + j0 + r) * CAH + a0 + nc];
        }
        __syncthreads();
        #pragma unroll 8
        for (int a = 0; a < 128; a += 4) {
            float4 u0 = *(const float4*)&Pi[2*ti][a];
            float4 u1 = *(const float4*)&Pi[2*ti + 1][a];
            float4 v0 = *(const float4*)&Pj[2*tj][a];
            float4 v1 = *(const float4*)&Pj[2*tj + 1][a];
            float4 bb = *(const float4*)&B1s[a];
            float4 ww = *(const float4*)&W2s[a];
            #define EDGE_E(ue, ve, be, we) { \
                float p00 = ue.x + ve.x + be; float p01 = ue.x + ve.y + be; \
                float p10 = ue.y + ve.x + be; float p11 = ue.y + ve.y + be; \
                acc[0][0] += fmaxf(p00, 0.f) * we; \
                acc[0][1] += fmaxf(p01, 0.f) * we; \
                acc[1][0] += fmaxf(p10, 0.f) * we; \
                acc[1][1] += fmaxf(p11, 0.f) * we; }
            { float2 uu = make_float2(u0.x, u1.x), vv = make_float2(v0.x, v1.x); EDGE_E(uu, vv, bb.x, ww.x); }
            { float2 uu = make_float2(u0.y, u1.y), vv = make_float2(v0.y, v1.y); EDGE_E(uu, vv, bb.y, ww.y); }
            { float2 uu = make_float2(u0.z, u1.z), vv = make_float2(v0.z, v1.z); EDGE_E(uu, vv, bb.z, ww.z); }
            { float2 uu = make_float2(u0.w, u1.w), vv = make_float2(v0.w, v1.w); EDGE_E(uu, vv, bb.w, ww.w); }
            #undef EDGE_E
        }
        __syncthreads();
    }
    float bias = b2[0];
    #pragma unroll
    for (int r = 0; r < 2; r++) {
        float2 o = make_float2(acc[r][0] + bias, acc[r][1] + bias);
        *(float2*)&g_edge[(size_t)b * CNN + (i0 + 2*ti + r) * CN + j0 + 2*tj] = o;
    }
}

// ---------------- radix select pass A: hi-16 histogram + max ----------------
__global__ void k_passA() {
    int b = blockIdx.y;
    const float* e = g_edge + (size_t)b * CNN;
    unsigned lm = 0;
    for (int idx = blockIdx.x * blockDim.x + threadIdx.x; idx < CNN;
         idx += gridDim.x * blockDim.x) {
        unsigned key = key_of(e[idx]);
        atomicAdd(&g_hist[(b << 16) + (key >> 16)], 1u);
        lm = max(lm, key);
    }
    __shared__ unsigned sh[8];
    int t = threadIdx.x, lane = t & 31, w = t >> 5;
#pragma unroll
    for (int o = 16; o; o >>= 1) lm = max(lm, __shfl_xor_sync(0xffffffffu, lm, o));
    if (!lane) sh[w] = lm;
    __syncthreads();
    if (t == 0) {
        unsigned v = sh[0];
        for (int q = 1; q < 8; q++) v = max(v, sh[q]);
        atomicMax(&g_maxkey[b], v);
    }
}

__global__ void k_scan1() {
    int b = blockIdx.x;
    unsigned* h = g_hist + (b << 16);
    __shared__ unsigned part[1024];
    int t = threadIdx.x;
    unsigned s = 0;
    for (int i = 0; i < 64; i++) s += h[t*64 + i];
    part[t] = s;
    __syncthreads();
    for (int off = 1; off < 1024; off <<= 1) {
        unsigned v = (t >= off) ? part[t - off] : 0u;
        __syncthreads();
        if (t >= off) part[t] += v;
        __syncthreads();
    }
    unsigned r = RSEL;
    unsigned pre = t ? part[t-1] : 0u;
    if (pre <= r && r < part[t]) {
        unsigned rem = r - pre;
        for (int i = 0; i < 64; i++) {
            unsigned c = h[t*64 + i];
            if (rem < c) { g_selhi[b] = (unsigned)(t*64 + i); g_rank2[b] = rem; break; }
            rem -= c;
        }
    }
    __syncthreads();
    for (int i = t; i < 65536; i += 1024) h[i] = 0;   // re-zero for pass B
}

__global__ void k_passB() {
    int b = blockIdx.y;
    const float* e = g_edge + (size_t)b * CNN;
    unsigned hi = g_selhi[b];
    for (int idx = blockIdx.x * blockDim.x + threadIdx.x; idx < CNN;
         idx += gridDim.x * blockDim.x) {
        unsigned key = key_of(e[idx]);
        if ((key >> 16) == hi) atomicAdd(&g_hist[(b << 16) + (key & 0xFFFFu)], 1u);
    }
}

__global__ void k_scan2() {
    int b = blockIdx.x;
    unsigned* h = g_hist + (b << 16);
    __shared__ unsigned part[1024];
    int t = threadIdx.x;
    unsigned s = 0;
    for (int i = 0; i < 64; i++) s += h[t*64 + i];
    part[t] = s;
    __syncthreads();
    for (int off = 1; off < 1024; off <<= 1) {
        unsigned v = (t >= off) ? part[t - off] : 0u;
        __syncthreads();
        if (t >= off) part[t] += v;
        __syncthreads();
    }
    unsigned r = g_rank2[b];
    unsigned pre = t ? part[t-1] : 0u;
    if (pre <= r && r < part[t]) {
        unsigned rem = r - pre;
        for (int i = 0; i < 64; i++) {
            unsigned c = h[t*64 + i];
            if (rem < c) {
                unsigned key = (g_selhi[b] << 16) | (unsigned)(t*64 + i);
                g_thr[b] = key_inv(key);
                break;
            }
            rem -= c;
        }
    }
}

// ---------------- masked exp (unnormalized) + partial sums ----------------
__global__ void k_maskexp() {
    int b = blockIdx.y;
    const float* e = g_edge + (size_t)b * CNN;
    float* cm = g_cm + (size_t)b * CNN;
    float zmax = key_inv(g_maxkey[b]);
    float th = g_thr[b];
    float ls = 0.f;
    for (int idx = blockIdx.x * blockDim.x + threadIdx.x; idx < CNN;
         idx += gridDim.x * blockDim.x) {
        float z = e[idx];
        float v = 0.f;
        if (z >= th) v = expf((z - zmax) * 2.0f);   // 1/TEMP = 2
        cm[idx] = v;
        ls += v;
    }
    __shared__ float sh[8];
    int t = threadIdx.x, lane = t & 31, w = t >> 5;
#pragma unroll
    for (int o = 16; o; o >>= 1) ls += __shfl_xor_sync(0xffffffffu, ls, o);
    if (!lane) sh[w] = ls;
    __syncthreads();
    if (t == 0) {
        float v = sh[0];
        for (int q = 1; q < 8; q++) v += sh[q];
        atomicAdd(&g_msum[b], v);
    }
}

// invert sums once -> scale factors consumed by gemm epilogues
__global__ void k_inv() {
    int b = threadIdx.x;
    if (b < CB) g_msum[b] = 1.f / g_msum[b];
}

// ---------------- batch norm ----------------
__global__ void k_bnstats(const float* __restrict__ h, int C, float* sum, float* sq) {
    int row0 = blockIdx.x * 32;
    int c = threadIdx.x;
    float s = 0.f, q = 0.f;
    for (int r = 0; r < 32; r++) {
        float v = h[(size_t)(row0 + r) * C + c];
        s += v; q += v * v;
    }
    atomicAdd(&sum[c], s);
    atomicAdd(&sq[c], q);
}

// sum 4 K-split partials of h4, write h4, accumulate BN2 stats
__global__ void k_bnstats4() {
    int row0 = blockIdx.x * 32;
    int c = threadIdx.x;    // 128
    const long long S = (long long)CB * CN * COUT;
    float s = 0.f, q = 0.f;
    for (int r = 0; r < 32; r++) {
        size_t idx = (size_t)(row0 + r) * COUT + c;
        float v = g_h4p[idx] + g_h4p[idx + S] + g_h4p[idx + 2*S] + g_h4p[idx + 3*S];
        g_h4[idx] = v;
        s += v; q += v * v;
    }
    atomicAdd(&g_bs2[c], s);
    atomicAdd(&g_bq2[c], q);
}

__global__ void k_bnfinal(const float* sum, const float* sq,
                          const float* __restrict__ g, const float* __restrict__ bt,
                          float* scale, float* shift) {
    int c = threadIdx.x;
    const float invn = 1.f / (CB * CN);
    float mean = sum[c] * invn;
    float var = sq[c] * invn - mean * mean;
    float sc = g[c] * rsqrtf(var + 1e-5f);
    scale[c] = sc;
    shift[c] = bt[c] - mean * sc;
}

__global__ void k_bnrelu(float* h, int Cmask, int total, const float* scale, const float* shift) {
    for (int idx = blockIdx.x * blockDim.x + threadIdx.x; idx < total;
         idx += gridDim.x * blockDim.x) {
        int c = idx & Cmask;
        h[idx] = fmaxf(h[idx] * scale[c] + shift[c], 0.f);
    }
}

// ---------------- BN2-apply + relu + mean over N ----------------
__global__ void k_feat() {
    int b = blockIdx.x;
    int c = threadIdx.x;   // 128
    float sc = g_sc2[c], sh = g_sh2[c];
    float s = 0.f;
    for (int n = 0; n < CN; n++) {
        float v = g_h4[(size_t)(b*CN + n) * COUT + c] * sc + sh;
        s += fmaxf(v, 0.f);
    }
    g_feat[b*COUT + c] = s * (1.f / CN);
}

// ---------------- classifier ----------------
__global__ void k_cls(const float* __restrict__ cw, const float* __restrict__ cb,
                      float* __restrict__ out) {
    int w = threadIdx.x >> 5, lane = threadIdx.x & 31;
    if (w < CB * CNCLS) {
        int b = w / CNCLS, c = w % CNCLS;
        float s = 0.f;
        for (int f = lane; f < COUT; f += 32)
            s += g_feat[b*COUT + f] * cw[c*COUT + f];
#pragma unroll
        for (int o = 16; o; o >>= 1) s += __shfl_xor_sync(0xffffffffu, s, o);
        if (!lane) out[b*CNCLS + c] = s + cb[c];
    }
}

// ---------------- host launch ----------------
extern "C" void kernel_launch(void* const* d_in, const int* in_sizes, int n_in,
                              void* d_out, int out_size) {
    (void)in_sizes; (void)n_in; (void)out_size;
    const float* x    = (const float*)d_in[0];
    const float* Wg   = (const float*)d_in[1];
    const float* attn = (const float*)d_in[2];
    const float* W1   = (const float*)d_in[3];
    const float* b1   = (const float*)d_in[4];
    const float* w2   = (const float*)d_in[5];
    const float* b2   = (const float*)d_in[6];
    const float* gc1w = (const float*)d_in[7];
    /* gc1_b (8) cancels in BN */
    const float* bn1g = (const float*)d_in[9];
    const float* bn1b = (const float*)d_in[10];
    const float* gc2w = (const float*)d_in[11];
    /* gc2_b (12) cancels in BN */
    const float* bn2g = (const float*)d_in[13];
    const float* bn2b = (const float*)d_in[14];
    const float* clsw = (const float*)d_in[15];
    const float* clsb = (const float*)d_in[16];
    float* out = (float*)d_out;

    float *hp, *nf, *pij, *cm, *h1, *h2, *h3, *h4p;
    float *bs1, *bq1, *sc1, *sh1, *bs2, *bq2, *sc2, *sh2;
    float *al, *msum;
    cudaGetSymbolAddress((void**)&hp,  g_hp);
    cudaGetSymbolAddress((void**)&al,  g_alpha);
    cudaGetSymbolAddress((void**)&nf,  g_nf);
    cudaGetSymbolAddress((void**)&pij, g_pij);
    cudaGetSymbolAddress((void**)&cm,  g_cm);
    cudaGetSymbolAddress((void**)&h1,  g_h1);
    cudaGetSymbolAddress((void**)&h2,  g_h2);
    cudaGetSymbolAddress((void**)&h3,  g_h3);
    cudaGetSymbolAddress((void**)&h4p, g_h4p);
    cudaGetSymbolAddress((void**)&msum, g_msum);
    cudaGetSymbolAddress((void**)&bs1, g_bs1);
    cudaGetSymbolAddress((void**)&bq1, g_bq1);
    cudaGetSymbolAddress((void**)&sc1, g_sc1);
    cudaGetSymbolAddress((void**)&sh1, g_sh1);
    cudaGetSymbolAddress((void**)&bs2, g_bs2);
    cudaGetSymbolAddress((void**)&bq2, g_bq2);
    cudaGetSymbolAddress((void**)&sc2, g_sc2);
    cudaGetSymbolAddress((void**)&sh2, g_sh2);

    k_zero<<<512, 256>>>();

    // hp = x @ Wg^T     (1024 x 1024 x 1024)
    gemm_t<true><<<dim3(CF/128, (CB*CN)/64, 1), 128>>>(
        x, Wg, hp, CF, CF, CF, CF, 1, 0,0, 0,0, 0,0, (const float*)0);

    k_sij<<<CB*CN, 256>>>(attn);
    k_alpha<<<CB*CH*CN, 256>>>();

    // node_feats: per (b,h)  alpha(512x512) @ hp_bh(512x256, ld 1024) -> nf (ld 1024)
    gemm_t<false><<<dim3(CDH/128, CN/64, CB*CH), 128>>>(
        al, hp, nf, CN, CN, CF, CF,
        CH, (long long)CH*CNN, (long long)CNN,
        (long long)CN*CF, (long long)CDH,
        (long long)CN*CF, (long long)CDH, (const float*)0);

    // pi / pj = nf @ W1i^T / W1j^T   (z selects half of W1 and output block)
    gemm_t<true><<<dim3(CAH/128, (CB*CN)/64, 2), 128>>>(
        nf, W1, pij, CF, CF, 2*CF, CAH,
        1, 0, 0, (long long)CF, 0, (long long)CB*CN*CAH, 0, (const float*)0);

    k_edge<<<dim3(CN/32, CN/32, CB), 256>>>(b1, w2, b2);

    // exact top-k threshold via 2-pass radix select, then masked exp (norm folded into gemms)
    k_passA<<<dim3(128, CB), 256>>>();
    k_scan1<<<CB, 1024>>>();
    k_passB<<<dim3(128, CB), 256>>>();
    k_scan2<<<CB, 1024>>>();
    k_maskexp<<<dim3(128, CB), 256>>>();
    k_inv<<<1, 32>>>();

    // h1 = (cm/Z) @ nf    (per batch 512x1024x512), scale folded in
    gemm_t<false><<<dim3(CF/128, CN/64, CB), 128>>>(
        cm, nf, h1, CN, CN, CF, CF,
        1, (long long)CNN, 0, (long long)CN*CF, 0, (long long)CN*CF, 0, msum);

    // h2 = h1 @ gc1_w^T   (1024 x 512 x 1024)   [gc1_b cancels in BN]
    gemm_t<true><<<dim3(CHID/128, (CB*CN)/64, 1), 128>>>(
        h1, gc1w, h2, CF, CF, CF, CHID, 1, 0,0, 0,0, 0,0, (const float*)0);

    k_bnstats<<<(CB*CN)/32, CHID>>>(h2, CHID, bs1, bq1);
    k_bnfinal<<<1, CHID>>>(bs1, bq1, bn1g, bn1b, sc1, sh1);
    k_bnrelu<<<256, 256>>>(h2, CHID-1, CB*CN*CHID, sc1, sh1);

    // h3 = (cm/Z) @ h2    (per batch 512x512x512), scale folded in
    gemm_t<false><<<dim3(CHID/128, CN/64, CB), 128>>>(
        cm, h2, h3, CN, CN, CHID, CHID,
        1, (long long)CNN, 0, (long long)CN*CHID, 0, (long long)CN*CHID, 0, msum);

    // h4 = h3 @ gc2_w^T   (1024 x 128 x 512), K-split x4 into partials (TN=128)
    gemm_t<true><<<dim3(COUT/128, (CB*CN)/64, 4), 128>>>(
        h3, gc2w, h4p, CHID/4, CHID, CHID, COUT,
        1, 128, 0, 128, 0, (long long)CB*CN*COUT, 0, (const float*)0);

    k_bnstats4<<<(CB*CN)/32, COUT>>>();
    k_bnfinal<<<1, COUT>>>(bs2, bq2, bn2g, bn2b, sc2, sh2);

    k_feat<<<CB, COUT>>>();
    k_cls<<<1, 640>>>(clsw, clsb, out);
}

// round 10
// speedup vs baseline: 1.2655x; 1.2655x over previous
#include <cuda_runtime.h>
#include <cuda_bf16.h>
#include <mma.h>
#include <math.h>

using namespace nvcuda;

#define CB 2
#define CN 512
#define CF 1024
#define CH 4
#define CDH 256
#define CAH 256
#define CHID 512
#define COUT 128
#define CNCLS 10
#define CNN (CN*CN)
#define RSEL 52429u   /* NN - int(0.8*NN) = 262144 - 209715 */

// ---------------- scratch (static device memory; no allocations) ----------------
__device__ float g_hp[CB*CN*CF];
__device__ float g_si[CB*CH*CN];
__device__ float g_sj[CB*CH*CN];
__device__ float g_alpha[CB*CH*CN*CN];
__device__ float g_nf[CB*CN*CF];
__device__ float g_pij[2*CB*CN*CAH];
__device__ float g_edge[CB*CNN];
__device__ float g_cm[CB*CNN];
__device__ float g_h1[CB*CN*CF];
__device__ float g_h2[CB*CN*CHID];
__device__ float g_h3[CB*CN*CHID];
__device__ float g_h4[CB*CN*COUT];
__device__ float g_h4p[4*CB*CN*COUT];
__device__ float g_feat[CB*COUT];
__device__ unsigned g_hist[CB*65536];
__device__ unsigned g_selhi[CB];
__device__ unsigned g_rank2[CB];
__device__ unsigned g_maxkey[CB];
__device__ float g_thr[CB];
__device__ float g_msum[CB];
__device__ float g_bs1[CHID], g_bq1[CHID], g_sc1[CHID], g_sh1[CHID];
__device__ float g_bs2[COUT], g_bq2[COUT], g_sc2[COUT], g_sh2[COUT];

// ---------------- helpers ----------------
__device__ __forceinline__ unsigned key_of(float x) {
    unsigned u = __float_as_uint(x);
    return (u & 0x80000000u) ? ~u : (u | 0x80000000u);
}
__device__ __forceinline__ float key_inv(unsigned key) {
    unsigned u = (key & 0x80000000u) ? (key ^ 0x80000000u) : ~key;
    return __uint_as_float(u);
}
__device__ __forceinline__ void cvt_hl(float v, __nv_bfloat16& h, __nv_bfloat16& l) {
    h = __float2bfloat16(v);
    l = __float2bfloat16(v - __bfloat162float(h));
}

// ---------------- zero scratch (must run every launch; graph replays) ----------------
__global__ void k_zero() {
    int i = blockIdx.x * 256 + threadIdx.x;       // grid = 512 blocks -> 131072 threads
    g_hist[i] = 0;
    if (i < CHID) { g_bs1[i] = 0.f; g_bq1[i] = 0.f; }
    if (i < COUT) { g_bs2[i] = 0.f; g_bq2[i] = 0.f; }
    if (i < CB)   { g_msum[i] = 0.f; g_maxkey[i] = 0u; }
}

// ====== split-bf16 tensor-core GEMM: tile M64 x N128, 256 threads (8 warps 2x4) ======
// C[m,n] = scale * sum_k A[m,k]*B'[k,n], fp32 I/O, internally bf16 hi/lo (3 MMAs).
// BT=true : B given as [n][k] row-major (ld=ldb), i.e. C = A @ B^T
// BT=false: B given as [k][n] row-major (ld=ldb)
// batch z: zo=z/bdiv, zi=z%bdiv; pointers offset by zo*s?o + zi*s?i
// scale = scalep ? scalep[zo] : 1
template<bool BT>
__global__ void __launch_bounds__(256) gemm_w(
    const float* __restrict__ A, const float* __restrict__ Bm, float* __restrict__ C,
    int K, int lda, int ldb, int ldc,
    int bdiv, long long sAo, long long sAi, long long sBo, long long sBi,
    long long sCo, long long sCi, const float* __restrict__ scalep)
{
    int z = blockIdx.z;
    int zo = z / bdiv, zi = z - zo * bdiv;
    A  += zo * sAo + zi * sAi;
    Bm += zo * sBo + zi * sBi;
    C  += zo * sCo + zi * sCi;

    // A: 64 rows x 16 k, ld 40 (80B rows: 16B-aligned, bank-staggered)
    __shared__ __align__(32) __nv_bfloat16 AsH[64][40], AsL[64][40];
    // B: BT -> [n=128][k=16] ld 40 (col_major frags); !BT -> [k=16][n=128] ld 136
    __shared__ __align__(32) __nv_bfloat16 BsH[BT ? 128 : 16][BT ? 40 : 136];
    __shared__ __align__(32) __nv_bfloat16 BsL[BT ? 128 : 16][BT ? 40 : 136];

    int t = threadIdx.x;
    int warp = t >> 5;
    int wm = warp >> 2;            // 0..1 -> 32 rows each
    int wn = warp & 3;             // 0..3 -> 32 cols each
    int m0 = blockIdx.y * 64, n0 = blockIdx.x * 128;

    // staging indices
    int ar = t >> 2, ac = (t & 3) * 4;                 // A: 1 float4 each
    int br, bc;
    if (BT) { br = t >> 1; bc = (t & 1) * 8; }         // B: 2 float4 each
    else    { br = t >> 4; bc = (t & 15) * 8; }

    const float* ApS = A + (size_t)(m0 + ar) * lda + ac;
    const float* BpS = BT ? (Bm + (size_t)(n0 + br) * ldb + bc)
                          : (Bm + (size_t)br * ldb + n0 + bc);

    wmma::fragment<wmma::accumulator, 16, 16, 16, float> acc[2][2];
    #pragma unroll
    for (int i = 0; i < 2; i++)
        #pragma unroll
        for (int j = 0; j < 2; j++) wmma::fill_fragment(acc[i][j], 0.0f);

    for (int k0 = 0; k0 < K; k0 += 16) {
        // ---- stage A (64x16) ----
        {
            float4 v = *(const float4*)(ApS + k0);
            float vv[4] = {v.x, v.y, v.z, v.w};
            #pragma unroll
            for (int e = 0; e < 4; e++)
                cvt_hl(vv[e], AsH[ar][ac + e], AsL[ar][ac + e]);
        }
        // ---- stage B (16x128 or 128x16) ----
        {
            const float* src = BT ? (BpS + k0) : (BpS + (size_t)k0 * ldb);
            float4 v0 = *(const float4*)(src);
            float4 v1 = *(const float4*)(src + 4);
            float vv[8] = {v0.x, v0.y, v0.z, v0.w, v1.x, v1.y, v1.z, v1.w};
            #pragma unroll
            for (int e = 0; e < 8; e++)
                cvt_hl(vv[e], BsH[br][bc + e], BsL[br][bc + e]);
        }
        __syncthreads();

        wmma::fragment<wmma::matrix_a, 16, 16, 16, __nv_bfloat16, wmma::row_major> aH[2], aL[2];
        #pragma unroll
        for (int i = 0; i < 2; i++) {
            wmma::load_matrix_sync(aH[i], &AsH[wm * 32 + i * 16][0], 40);
            wmma::load_matrix_sync(aL[i], &AsL[wm * 32 + i * 16][0], 40);
        }
        #pragma unroll
        for (int j = 0; j < 2; j++) {
            if (BT) {
                wmma::fragment<wmma::matrix_b, 16, 16, 16, __nv_bfloat16, wmma::col_major> bH, bL;
                wmma::load_matrix_sync(bH, &BsH[wn * 32 + j * 16][0], 40);
                wmma::load_matrix_sync(bL, &BsL[wn * 32 + j * 16][0], 40);
                #pragma unroll
                for (int i = 0; i < 2; i++) {
                    wmma::mma_sync(acc[i][j], aH[i], bH, acc[i][j]);
                    wmma::mma_sync(acc[i][j], aH[i], bL, acc[i][j]);
                    wmma::mma_sync(acc[i][j], aL[i], bH, acc[i][j]);
                }
            } else {
                wmma::fragment<wmma::matrix_b, 16, 16, 16, __nv_bfloat16, wmma::row_major> bH, bL;
                wmma::load_matrix_sync(bH, &BsH[0][wn * 32 + j * 16], 136);
                wmma::load_matrix_sync(bL, &BsL[0][wn * 32 + j * 16], 136);
                #pragma unroll
                for (int i = 0; i < 2; i++) {
                    wmma::mma_sync(acc[i][j], aH[i], bH, acc[i][j]);
                    wmma::mma_sync(acc[i][j], aH[i], bL, acc[i][j]);
                    wmma::mma_sync(acc[i][j], aL[i], bH, acc[i][j]);
                }
            }
        }
        __syncthreads();
    }

    float sc = scalep ? scalep[zo] : 1.0f;
    #pragma unroll
    for (int i = 0; i < 2; i++)
        #pragma unroll
        for (int j = 0; j < 2; j++) {
            #pragma unroll
            for (int e = 0; e < acc[i][j].num_elements; e++) acc[i][j].x[e] *= sc;
            wmma::store_matrix_sync(
                &C[(size_t)(m0 + wm * 32 + i * 16) * ldc + n0 + wn * 32 + j * 16],
                acc[i][j], ldc, wmma::mem_row_major);
        }
}

// ---------------- attention scores s_i/s_j ----------------
__global__ void k_sij(const float* __restrict__ attn) {
    int bn = blockIdx.x;                      // b*512 + n
    __shared__ float row[CF];
    for (int i = threadIdx.x; i < CF; i += 256) row[i] = g_hp[(size_t)bn * CF + i];
    __syncthreads();
    int w = threadIdx.x >> 5, lane = threadIdx.x & 31;
    int h = w >> 1, part = w & 1;             // 8 warps: 4 heads x {i,j}
    const float* av = attn + h * (2*CDH) + part * CDH;
    float s = 0.f;
    for (int d = lane; d < CDH; d += 32) s += row[h*CDH + d] * av[d];
#pragma unroll
    for (int o = 16; o; o >>= 1) s += __shfl_xor_sync(0xffffffffu, s, o);
    if (!lane) {
        int b = bn >> 9, n = bn & 511;
        float* dst = part ? g_sj : g_si;
        dst[(b*CH + h)*CN + n] = s;
    }
}

// ---------------- leakyrelu + row softmax -> alpha ----------------
__global__ void k_alpha() {
    int row = blockIdx.x;                     // (b*H + h)*512 + i
    int bh = row >> 9;
    float s_i = g_si[row];
    const float* sjr = g_sj + bh * CN;
    __shared__ float shm[8], shs[8];
    int t = threadIdx.x, lane = t & 31, w = t >> 5;
    float e0 = s_i + sjr[t];       e0 = e0 >= 0.f ? e0 : 0.2f * e0;
    float e1 = s_i + sjr[t + 256]; e1 = e1 >= 0.f ? e1 : 0.2f * e1;
    float m = fmaxf(e0, e1);
#pragma unroll
    for (int o = 16; o; o >>= 1) m = fmaxf(m, __shfl_xor_sync(0xffffffffu, m, o));
    if (!lane) shm[w] = m;
    __syncthreads();
    if (t < 32) {
        float v = (t < 8) ? shm[t] : -INFINITY;
#pragma unroll
        for (int o = 4; o; o >>= 1) v = fmaxf(v, __shfl_xor_sync(0xffffffffu, v, o));
        if (t == 0) shm[0] = v;
    }
    __syncthreads();
    float bm = shm[0];
    float x0 = expf(e0 - bm), x1 = expf(e1 - bm);
    float s = x0 + x1;
#pragma unroll
    for (int o = 16; o; o >>= 1) s += __shfl_xor_sync(0xffffffffu, s, o);
    if (!lane) shs[w] = s;
    __syncthreads();
    if (t < 32) {
        float v = (t < 8) ? shs[t] : 0.f;
#pragma unroll
        for (int o = 4; o; o >>= 1) v += __shfl_xor_sync(0xffffffffu, v, o);
        if (t == 0) shs[0] = v;
    }
    __syncthreads();
    float inv = 1.f / shs[0];
    g_alpha[(size_t)row * CN + t]       = x0 * inv;
    g_alpha[(size_t)row * CN + t + 256] = x1 * inv;
}

// ------- edge scores: sum_a relu(pi+pj+b1)*w2 + b2; 32x32 tile, 2x2 microtile -------
__global__ void __launch_bounds__(256) k_edge(
    const float* __restrict__ b1, const float* __restrict__ w2,
    const float* __restrict__ b2)
{
    int b = blockIdx.z;
    int i0 = blockIdx.y * 32, j0 = blockIdx.x * 32;
    __shared__ __align__(16) float Pi[32][132], Pj[32][132];
    __shared__ float B1s[128], W2s[128];
    const float* pi = g_pij;
    const float* pj = g_pij + (size_t)CB*CN*CAH;
    int t = threadIdx.x;
    int ti = t >> 4, tj = t & 15;
    float acc[2][2] = {};
    for (int a0 = 0; a0 < CAH; a0 += 128) {
        if (t < 128) { B1s[t] = b1[a0 + t]; W2s[t] = w2[a0 + t]; }
        #pragma unroll
        for (int c = 0; c < 4; c++) {
            int q = t + 256 * c;            // 0..1023 over 32 rows x 32 float4
            int r = q >> 5, nc = (q & 31) * 4;
            *(float4*)&Pi[r][nc] = *(const float4*)&pi[(size_t)(b*CN + i0 + r) * CAH + a0 + nc];
            *(float4*)&Pj[r][nc] = *(const float4*)&pj[(size_t)(b*CN + j0 + r) * CAH + a0 + nc];
        }
        __syncthreads();
        #pragma unroll 8
        for (int a = 0; a < 128; a += 4) {
            float4 u0 = *(const float4*)&Pi[2*ti][a];
            float4 u1 = *(const float4*)&Pi[2*ti + 1][a];
            float4 v0 = *(const float4*)&Pj[2*tj][a];
            float4 v1 = *(const float4*)&Pj[2*tj + 1][a];
            float4 bb = *(const float4*)&B1s[a];
            float4 ww = *(const float4*)&W2s[a];
            #define EDGE_E(ue, ve, be, we) { \
                float p00 = ue.x + ve.x + be; float p01 = ue.x + ve.y + be; \
                float p10 = ue.y + ve.x + be; float p11 = ue.y + ve.y + be; \
                acc[0][0] += fmaxf(p00, 0.f) * we; \
                acc[0][1] += fmaxf(p01, 0.f) * we; \
                acc[1][0] += fmaxf(p10, 0.f) * we; \
                acc[1][1] += fmaxf(p11, 0.f) * we; }
            { float2 uu = make_float2(u0.x, u1.x), vv = make_float2(v0.x, v1.x); EDGE_E(uu, vv, bb.x, ww.x); }
            { float2 uu = make_float2(u0.y, u1.y), vv = make_float2(v0.y, v1.y); EDGE_E(uu, vv, bb.y, ww.y); }
            { float2 uu = make_float2(u0.z, u1.z), vv = make_float2(v0.z, v1.z); EDGE_E(uu, vv, bb.z, ww.z); }
            { float2 uu = make_float2(u0.w, u1.w), vv = make_float2(v0.w, v1.w); EDGE_E(uu, vv, bb.w, ww.w); }
            #undef EDGE_E
        }
        __syncthreads();
    }
    float bias = b2[0];
    #pragma unroll
    for (int r = 0; r < 2; r++) {
        float2 o = make_float2(acc[r][0] + bias, acc[r][1] + bias);
        *(float2*)&g_edge[(size_t)b * CNN + (i0 + 2*ti + r) * CN + j0 + 2*tj] = o;
    }
}

// ---------------- radix select pass A: hi-16 histogram + max ----------------
__global__ void k_passA() {
    int b = blockIdx.y;
    const float* e = g_edge + (size_t)b * CNN;
    unsigned lm = 0;
    for (int idx = blockIdx.x * blockDim.x + threadIdx.x; idx < CNN;
         idx += gridDim.x * blockDim.x) {
        unsigned key = key_of(e[idx]);
        atomicAdd(&g_hist[(b << 16) + (key >> 16)], 1u);
        lm = max(lm, key);
    }
    __shared__ unsigned sh[8];
    int t = threadIdx.x, lane = t & 31, w = t >> 5;
#pragma unroll
    for (int o = 16; o; o >>= 1) lm = max(lm, __shfl_xor_sync(0xffffffffu, lm, o));
    if (!lane) sh[w] = lm;
    __syncthreads();
    if (t == 0) {
        unsigned v = sh[0];
        for (int q = 1; q < 8; q++) v = max(v, sh[q]);
        atomicMax(&g_maxkey[b], v);
    }
}

__global__ void k_scan1() {
    int b = blockIdx.x;
    unsigned* h = g_hist + (b << 16);
    __shared__ unsigned part[1024];
    int t = threadIdx.x;
    unsigned s = 0;
    for (int i = 0; i < 64; i++) s += h[t*64 + i];
    part[t] = s;
    __syncthreads();
    for (int off = 1; off < 1024; off <<= 1) {
        unsigned v = (t >= off) ? part[t - off] : 0u;
        __syncthreads();
        if (t >= off) part[t] += v;
        __syncthreads();
    }
    unsigned r = RSEL;
    unsigned pre = t ? part[t-1] : 0u;
    if (pre <= r && r < part[t]) {
        unsigned rem = r - pre;
        for (int i = 0; i < 64; i++) {
            unsigned c = h[t*64 + i];
            if (rem < c) { g_selhi[b] = (unsigned)(t*64 + i); g_rank2[b] = rem; break; }
            rem -= c;
        }
    }
    __syncthreads();
    for (int i = t; i < 65536; i += 1024) h[i] = 0;   // re-zero for pass B
}

__global__ void k_passB() {
    int b = blockIdx.y;
    const float* e = g_edge + (size_t)b * CNN;
    unsigned hi = g_selhi[b];
    for (int idx = blockIdx.x * blockDim.x + threadIdx.x; idx < CNN;
         idx += gridDim.x * blockDim.x) {
        unsigned key = key_of(e[idx]);
        if ((key >> 16) == hi) atomicAdd(&g_hist[(b << 16) + (key & 0xFFFFu)], 1u);
    }
}

__global__ void k_scan2() {
    int b = blockIdx.x;
    unsigned* h = g_hist + (b << 16);
    __shared__ unsigned part[1024];
    int t = threadIdx.x;
    unsigned s = 0;
    for (int i = 0; i < 64; i++) s += h[t*64 + i];
    part[t] = s;
    __syncthreads();
    for (int off = 1; off < 1024; off <<= 1) {
        unsigned v = (t >= off) ? part[t - off] : 0u;
        __syncthreads();
        if (t >= off) part[t] += v;
        __syncthreads();
    }
    unsigned r = g_rank2[b];
    unsigned pre = t ? part[t-1] : 0u;
    if (pre <= r && r < part[t]) {
        unsigned rem = r - pre;
        for (int i = 0; i < 64; i++) {
            unsigned c = h[t*64 + i];
            if (rem < c) {
                unsigned key = (g_selhi[b] << 16) | (unsigned)(t*64 + i);
                g_thr[b] = key_inv(key);
                break;
            }
            rem -= c;
        }
    }
}

// ---------------- masked exp (unnormalized) + partial sums ----------------
__global__ void k_maskexp() {
    int b = blockIdx.y;
    const float* e = g_edge + (size_t)b * CNN;
    float* cm = g_cm + (size_t)b * CNN;
    float zmax = key_inv(g_maxkey[b]);
    float th = g_thr[b];
    float ls = 0.f;
    for (int idx = blockIdx.x * blockDim.x + threadIdx.x; idx < CNN;
         idx += gridDim.x * blockDim.x) {
        float z = e[idx];
        float v = 0.f;
        if (z >= th) v = expf((z - zmax) * 2.0f);   // 1/TEMP = 2
        cm[idx] = v;
        ls += v;
    }
    __shared__ float sh[8];
    int t = threadIdx.x, lane = t & 31, w = t >> 5;
#pragma unroll
    for (int o = 16; o; o >>= 1) ls += __shfl_xor_sync(0xffffffffu, ls, o);
    if (!lane) sh[w] = ls;
    __syncthreads();
    if (t == 0) {
        float v = sh[0];
        for (int q = 1; q < 8; q++) v += sh[q];
        atomicAdd(&g_msum[b], v);
    }
}

// invert sums once -> scale factors consumed by gemm epilogues
__global__ void k_inv() {
    int b = threadIdx.x;
    if (b < CB) g_msum[b] = 1.f / g_msum[b];
}

// ---------------- batch norm ----------------
__global__ void k_bnstats(const float* __restrict__ h, int C, float* sum, float* sq) {
    int row0 = blockIdx.x * 32;
    int c = threadIdx.x;
    float s = 0.f, q = 0.f;
    for (int r = 0; r < 32; r++) {
        float v = h[(size_t)(row0 + r) * C + c];
        s += v; q += v * v;
    }
    atomicAdd(&sum[c], s);
    atomicAdd(&sq[c], q);
}

// sum 4 K-split partials of h4, write h4, accumulate BN2 stats
__global__ void k_bnstats4() {
    int row0 = blockIdx.x * 32;
    int c = threadIdx.x;    // 128
    const long long S = (long long)CB * CN * COUT;
    float s = 0.f, q = 0.f;
    for (int r = 0; r < 32; r++) {
        size_t idx = (size_t)(row0 + r) * COUT + c;
        float v = g_h4p[idx] + g_h4p[idx + S] + g_h4p[idx + 2*S] + g_h4p[idx + 3*S];
        g_h4[idx] = v;
        s += v; q += v * v;
    }
    atomicAdd(&g_bs2[c], s);
    atomicAdd(&g_bq2[c], q);
}

__global__ void k_bnfinal(const float* sum, const float* sq,
                          const float* __restrict__ g, const float* __restrict__ bt,
                          float* scale, float* shift) {
    int c = threadIdx.x;
    const float invn = 1.f / (CB * CN);
    float mean = sum[c] * invn;
    float var = sq[c] * invn - mean * mean;
    float sc = g[c] * rsqrtf(var + 1e-5f);
    scale[c] = sc;
    shift[c] = bt[c] - mean * sc;
}

__global__ void k_bnrelu(float* h, int Cmask, int total, const float* scale, const float* shift) {
    for (int idx = blockIdx.x * blockDim.x + threadIdx.x; idx < total;
         idx += gridDim.x * blockDim.x) {
        int c = idx & Cmask;
        h[idx] = fmaxf(h[idx] * scale[c] + shift[c], 0.f);
    }
}

// ---------------- BN2-apply + relu + mean over N ----------------
__global__ void k_feat() {
    int b = blockIdx.x;
    int c = threadIdx.x;   // 128
    float sc = g_sc2[c], sh = g_sh2[c];
    float s = 0.f;
    for (int n = 0; n < CN; n++) {
        float v = g_h4[(size_t)(b*CN + n) * COUT + c] * sc + sh;
        s += fmaxf(v, 0.f);
    }
    g_feat[b*COUT + c] = s * (1.f / CN);
}

// ---------------- classifier ----------------
__global__ void k_cls(const float* __restrict__ cw, const float* __restrict__ cb,
                      float* __restrict__ out) {
    int w = threadIdx.x >> 5, lane = threadIdx.x & 31;
    if (w < CB * CNCLS) {
        int b = w / CNCLS, c = w % CNCLS;
        float s = 0.f;
        for (int f = lane; f < COUT; f += 32)
            s += g_feat[b*COUT + f] * cw[c*COUT + f];
#pragma unroll
        for (int o = 16; o; o >>= 1) s += __shfl_xor_sync(0xffffffffu, s, o);
        if (!lane) out[b*CNCLS + c] = s + cb[c];
    }
}

// ---------------- host launch ----------------
extern "C" void kernel_launch(void* const* d_in, const int* in_sizes, int n_in,
                              void* d_out, int out_size) {
    (void)in_sizes; (void)n_in; (void)out_size;
    const float* x    = (const float*)d_in[0];
    const float* Wg   = (const float*)d_in[1];
    const float* attn = (const float*)d_in[2];
    const float* W1   = (const float*)d_in[3];
    const float* b1   = (const float*)d_in[4];
    const float* w2   = (const float*)d_in[5];
    const float* b2   = (const float*)d_in[6];
    const float* gc1w = (const float*)d_in[7];
    /* gc1_b (8) cancels in BN */
    const float* bn1g = (const float*)d_in[9];
    const float* bn1b = (const float*)d_in[10];
    const float* gc2w = (const float*)d_in[11];
    /* gc2_b (12) cancels in BN */
    const float* bn2g = (const float*)d_in[13];
    const float* bn2b = (const float*)d_in[14];
    const float* clsw = (const float*)d_in[15];
    const float* clsb = (const float*)d_in[16];
    float* out = (float*)d_out;

    float *hp, *nf, *pij, *cm, *h1, *h2, *h3, *h4p;
    float *bs1, *bq1, *sc1, *sh1, *bs2, *bq2, *sc2, *sh2;
    float *al, *msum;
    cudaGetSymbolAddress((void**)&hp,  g_hp);
    cudaGetSymbolAddress((void**)&al,  g_alpha);
    cudaGetSymbolAddress((void**)&nf,  g_nf);
    cudaGetSymbolAddress((void**)&pij, g_pij);
    cudaGetSymbolAddress((void**)&cm,  g_cm);
    cudaGetSymbolAddress((void**)&h1,  g_h1);
    cudaGetSymbolAddress((void**)&h2,  g_h2);
    cudaGetSymbolAddress((void**)&h3,  g_h3);
    cudaGetSymbolAddress((void**)&h4p, g_h4p);
    cudaGetSymbolAddress((void**)&msum, g_msum);
    cudaGetSymbolAddress((void**)&bs1, g_bs1);
    cudaGetSymbolAddress((void**)&bq1, g_bq1);
    cudaGetSymbolAddress((void**)&sc1, g_sc1);
    cudaGetSymbolAddress((void**)&sh1, g_sh1);
    cudaGetSymbolAddress((void**)&bs2, g_bs2);
    cudaGetSymbolAddress((void**)&bq2, g_bq2);
    cudaGetSymbolAddress((void**)&sc2, g_sc2);
    cudaGetSymbolAddress((void**)&sh2, g_sh2);

    k_zero<<<512, 256>>>();

    // hp = x @ Wg^T     (1024 x 1024 x 1024)
    gemm_w<true><<<dim3(CF/128, (CB*CN)/64, 1), 256>>>(
        x, Wg, hp, CF, CF, CF, CF, 1, 0,0, 0,0, 0,0, (const float*)0);

    k_sij<<<CB*CN, 256>>>(attn);
    k_alpha<<<CB*CH*CN, 256>>>();

    // node_feats: per (b,h)  alpha(512x512) @ hp_bh(512x256, ld 1024) -> nf (ld 1024)
    gemm_w<false><<<dim3(CDH/128, CN/64, CB*CH), 256>>>(
        al, hp, nf, CN, CN, CF, CF,
        CH, (long long)CH*CNN, (long long)CNN,
        (long long)CN*CF, (long long)CDH,
        (long long)CN*CF, (long long)CDH, (const float*)0);

    // pi / pj = nf @ W1i^T / W1j^T   (z selects half of W1 and output block)
    gemm_w<true><<<dim3(CAH/128, (CB*CN)/64, 2), 256>>>(
        nf, W1, pij, CF, CF, 2*CF, CAH,
        1, 0, 0, (long long)CF, 0, (long long)CB*CN*CAH, 0, (const float*)0);

    k_edge<<<dim3(CN/32, CN/32, CB), 256>>>(b1, w2, b2);

    // exact top-k threshold via 2-pass radix select, then masked exp (norm folded into gemms)
    k_passA<<<dim3(128, CB), 256>>>();
    k_scan1<<<CB, 1024>>>();
    k_passB<<<dim3(128, CB), 256>>>();
    k_scan2<<<CB, 1024>>>();
    k_maskexp<<<dim3(128, CB), 256>>>();
    k_inv<<<1, 32>>>();

    // h1 = (cm/Z) @ nf    (per batch 512x1024x512), scale folded in
    gemm_w<false><<<dim3(CF/128, CN/64, CB), 256>>>(
        cm, nf, h1, CN, CN, CF, CF,
        1, (long long)CNN, 0, (long long)CN*CF, 0, (long long)CN*CF, 0, msum);

    // h2 = h1 @ gc1_w^T   (1024 x 512 x 1024)   [gc1_b cancels in BN]
    gemm_w<true><<<dim3(CHID/128, (CB*CN)/64, 1), 256>>>(
        h1, gc1w, h2, CF, CF, CF, CHID, 1, 0,0, 0,0, 0,0, (const float*)0);

    k_bnstats<<<(CB*CN)/32, CHID>>>(h2, CHID, bs1, bq1);
    k_bnfinal<<<1, CHID>>>(bs1, bq1, bn1g, bn1b, sc1, sh1);
    k_bnrelu<<<256, 256>>>(h2, CHID-1, CB*CN*CHID, sc1, sh1);

    // h3 = (cm/Z) @ h2    (per batch 512x512x512), scale folded in
    gemm_w<false><<<dim3(CHID/128, CN/64, CB), 256>>>(
        cm, h2, h3, CN, CN, CHID, CHID,
        1, (long long)CNN, 0, (long long)CN*CHID, 0, (long long)CN*CHID, 0, msum);

    // h4 = h3 @ gc2_w^T   (1024 x 128 x 512), K-split x4 into partials
    gemm_w<true><<<dim3(COUT/128, (CB*CN)/64, 4), 256>>>(
        h3, gc2w, h4p, CHID/4, CHID, CHID, COUT,
        1, 128, 0, 128, 0, (long long)CB*CN*COUT, 0, (const float*)0);

    k_bnstats4<<<(CB*CN)/32, COUT>>>();
    k_bnfinal<<<1, COUT>>>(bs2, bq2, bn2g, bn2b, sc2, sh2);

    k_feat<<<CB, COUT>>>();
    k_cls<<<1, 640>>>(clsw, clsb, out);
}

// round 11
// speedup vs baseline: 1.4424x; 1.1397x over previous
#include <cuda_runtime.h>
#include <cuda_bf16.h>
#include <mma.h>
#include <math.h>

using namespace nvcuda;

#define CB 2
#define CN 512
#define CF 1024
#define CH 4
#define CDH 256
#define CAH 256
#define CHID 512
#define COUT 128
#define CNCLS 10
#define CNN (CN*CN)
#define RSEL 52429u   /* NN - int(0.8*NN) = 262144 - 209715 */

// ---------------- scratch (static device memory; no allocations) ----------------
__device__ float g_hp[CB*CN*CF];
__device__ float g_si[CB*CH*CN];
__device__ float g_sj[CB*CH*CN];
__device__ float g_nf[CB*CN*CF];
__device__ float g_pij[2*CB*CN*CAH];
__device__ float g_edge[CB*CNN];
__device__ float g_h1[CB*CN*CF];
__device__ float g_h2[CB*CN*CHID];
__device__ float g_h3[CB*CN*CHID];
__device__ float g_h4[CB*CN*COUT];
__device__ float g_h4p[4*CB*CN*COUT];
__device__ float g_feat[CB*COUT];
__device__ unsigned g_hist[CB*65536];
__device__ unsigned g_selhi[CB];
__device__ unsigned g_rank2[CB];
__device__ unsigned g_maxkey[CB];
__device__ float g_thr[CB];
__device__ float g_msum[CB];
__device__ float g_bs1[CHID], g_bq1[CHID], g_sc1[CHID], g_sh1[CHID];
__device__ float g_bs2[COUT], g_bq2[COUT], g_sc2[COUT], g_sh2[COUT];

// bf16 hi/lo operand mirrors
__device__ __nv_bfloat16 g_xh[CB*CN*CF],  g_xl[CB*CN*CF];
__device__ __nv_bfloat16 g_Wgh[CF*CF],    g_Wgl[CF*CF];
__device__ __nv_bfloat16 g_hph[CB*CN*CF], g_hpl[CB*CN*CF];
__device__ __nv_bfloat16 g_alh[CB*CH*CNN],g_all[CB*CH*CNN];
__device__ __nv_bfloat16 g_nfh[CB*CN*CF], g_nfl[CB*CN*CF];
__device__ __nv_bfloat16 g_W1h[CAH*2*CF], g_W1l[CAH*2*CF];
__device__ __nv_bfloat16 g_cmh[CB*CNN],   g_cml[CB*CNN];
__device__ __nv_bfloat16 g_h1h[CB*CN*CF], g_h1l[CB*CN*CF];
__device__ __nv_bfloat16 g_gc1h[CHID*CF], g_gc1l[CHID*CF];
__device__ __nv_bfloat16 g_h2h[CB*CN*CHID], g_h2l[CB*CN*CHID];
__device__ __nv_bfloat16 g_h3h[CB*CN*CHID], g_h3l[CB*CN*CHID];
__device__ __nv_bfloat16 g_gc2h[COUT*CHID], g_gc2l[COUT*CHID];

// ---------------- helpers ----------------
__device__ __forceinline__ unsigned key_of(float x) {
    unsigned u = __float_as_uint(x);
    return (u & 0x80000000u) ? ~u : (u | 0x80000000u);
}
__device__ __forceinline__ float key_inv(unsigned key) {
    unsigned u = (key & 0x80000000u) ? (key ^ 0x80000000u) : ~key;
    return __uint_as_float(u);
}
__device__ __forceinline__ void cvt_hl(float v, __nv_bfloat16& h, __nv_bfloat16& l) {
    h = __float2bfloat16(v);
    l = __float2bfloat16(v - __bfloat162float(h));
}

// ---------------- zero scratch (must run every launch; graph replays) ----------------
__global__ void k_zero() {
    int i = blockIdx.x * 256 + threadIdx.x;       // grid = 512 blocks -> 131072 threads
    g_hist[i] = 0;
    if (i < CHID) { g_bs1[i] = 0.f; g_bq1[i] = 0.f; }
    if (i < COUT) { g_bs2[i] = 0.f; g_bq2[i] = 0.f; }
    if (i < CB)   { g_msum[i] = 0.f; g_maxkey[i] = 0u; }
}

// ---------------- fp32 -> bf16 hi/lo conversion ----------------
__global__ void k_cvt(const float* __restrict__ src,
                      __nv_bfloat16* __restrict__ ho,
                      __nv_bfloat16* __restrict__ lo, int n) {
    int i = (blockIdx.x * 256 + threadIdx.x) * 4;
    if (i < n) {
        float4 v = *(const float4*)(src + i);
        __nv_bfloat16 h0,h1,h2,h3, l0,l1,l2,l3;
        cvt_hl(v.x, h0, l0); cvt_hl(v.y, h1, l1);
        cvt_hl(v.z, h2, l2); cvt_hl(v.w, h3, l3);
        union { __nv_bfloat162 b[2]; uint2 u; } uh, ul;
        uh.b[0].x = h0; uh.b[0].y = h1; uh.b[1].x = h2; uh.b[1].y = h3;
        ul.b[0].x = l0; ul.b[0].y = l1; ul.b[1].x = l2; ul.b[1].y = l3;
        *(uint2*)(ho + i) = uh.u;
        *(uint2*)(lo + i) = ul.u;
    }
}

// ====== split-bf16 tensor-core GEMM, bf16 hi/lo operands, K-chunk 32 ======
// TN=128: 256 thr, 8 warps (2x4).  TN=64: 128 thr, 4 warps (2x2).  Tile M64 x TN.
// C[m,n] = scale * sum_k (Ah+Al)[m,k]*(Bh+Bl)'[k,n]  (3 of 4 cross terms)
// BT=true : B given as [n][k] (ld=ldb).  BT=false: B given as [k][n] (ld=ldb)
template<int TN, bool BT>
__global__ void __launch_bounds__(TN == 128 ? 256 : 128) gemm_w(
    const __nv_bfloat16* __restrict__ Ah, const __nv_bfloat16* __restrict__ Al,
    const __nv_bfloat16* __restrict__ Bh, const __nv_bfloat16* __restrict__ Bl,
    float* __restrict__ C,
    int K, int lda, int ldb, int ldc,
    int bdiv, long long sAo, long long sAi, long long sBo, long long sBi,
    long long sCo, long long sCi, const float* __restrict__ scalep)
{
    const int NT = (TN == 128) ? 256 : 128;
    int z = blockIdx.z;
    int zo = z / bdiv, zi = z - zo * bdiv;
    Ah += zo * sAo + zi * sAi;  Al += zo * sAo + zi * sAi;
    Bh += zo * sBo + zi * sBi;  Bl += zo * sBo + zi * sBi;
    C  += zo * sCo + zi * sCi;

    __shared__ __align__(16) __nv_bfloat16 AsH[64][40], AsL[64][40];      // 32k + 8 skew
    __shared__ __align__(16) __nv_bfloat16 BsH[BT ? TN : 32][BT ? 40 : TN + 8];
    __shared__ __align__(16) __nv_bfloat16 BsL[BT ? TN : 32][BT ? 40 : TN + 8];

    int t = threadIdx.x;
    int warp = t >> 5;
    int wm = (TN == 128) ? (warp >> 2) : (warp >> 1);
    int wn = (TN == 128) ? (warp & 3) : (warp & 1);
    int m0 = blockIdx.y * 64, n0 = blockIdx.x * TN;

    wmma::fragment<wmma::accumulator, 16, 16, 16, float> acc[2][2];
    #pragma unroll
    for (int i = 0; i < 2; i++)
        #pragma unroll
        for (int j = 0; j < 2; j++) wmma::fill_fragment(acc[i][j], 0.0f);

    for (int k0 = 0; k0 < K; k0 += 32) {
        // ---- stage A: 64 x 32, groups of 8 bf16 (16B) ----
        #pragma unroll
        for (int g = t; g < 256; g += NT) {
            int r = g >> 2, c = (g & 3) * 8;
            size_t off = (size_t)(m0 + r) * lda + k0 + c;
            *(uint4*)&AsH[r][c] = *(const uint4*)(Ah + off);
            *(uint4*)&AsL[r][c] = *(const uint4*)(Al + off);
        }
        // ---- stage B ----
        if (BT) {
            #pragma unroll
            for (int g = t; g < TN * 4; g += NT) {
                int r = g >> 2, c = (g & 3) * 8;
                size_t off = (size_t)(n0 + r) * ldb + k0 + c;
                *(uint4*)&BsH[r][c] = *(const uint4*)(Bh + off);
                *(uint4*)&BsL[r][c] = *(const uint4*)(Bl + off);
            }
        } else {
            const int TPR = TN / 8;
            #pragma unroll
            for (int g = t; g < TN * 4; g += NT) {
                int r = g / TPR, c = (g % TPR) * 8;
                size_t off = (size_t)(k0 + r) * ldb + n0 + c;
                *(uint4*)&BsH[r][c] = *(const uint4*)(Bh + off);
                *(uint4*)&BsL[r][c] = *(const uint4*)(Bl + off);
            }
        }
        __syncthreads();

        #pragma unroll
        for (int hf = 0; hf < 2; hf++) {
            int ko = hf * 16;
            wmma::fragment<wmma::matrix_a, 16, 16, 16, __nv_bfloat16, wmma::row_major> aH[2], aL[2];
            #pragma unroll
            for (int i = 0; i < 2; i++) {
                wmma::load_matrix_sync(aH[i], &AsH[wm * 32 + i * 16][ko], 40);
                wmma::load_matrix_sync(aL[i], &AsL[wm * 32 + i * 16][ko], 40);
            }
            #pragma unroll
            for (int j = 0; j < 2; j++) {
                if (BT) {
                    wmma::fragment<wmma::matrix_b, 16, 16, 16, __nv_bfloat16, wmma::col_major> bH, bL;
                    wmma::load_matrix_sync(bH, &BsH[wn * 32 + j * 16][ko], 40);
                    wmma::load_matrix_sync(bL, &BsL[wn * 32 + j * 16][ko], 40);
                    #pragma unroll
                    for (int i = 0; i < 2; i++) {
                        wmma::mma_sync(acc[i][j], aH[i], bH, acc[i][j]);
                        wmma::mma_sync(acc[i][j], aH[i], bL, acc[i][j]);
                        wmma::mma_sync(acc[i][j], aL[i], bH, acc[i][j]);
                    }
                } else {
                    wmma::fragment<wmma::matrix_b, 16, 16, 16, __nv_bfloat16, wmma::row_major> bH, bL;
                    wmma::load_matrix_sync(bH, &BsH[ko][wn * 32 + j * 16], TN + 8);
                    wmma::load_matrix_sync(bL, &BsL[ko][wn * 32 + j * 16], TN + 8);
                    #pragma unroll
                    for (int i = 0; i < 2; i++) {
                        wmma::mma_sync(acc[i][j], aH[i], bH, acc[i][j]);
                        wmma::mma_sync(acc[i][j], aH[i], bL, acc[i][j]);
                        wmma::mma_sync(acc[i][j], aL[i], bH, acc[i][j]);
                    }
                }
            }
        }
        __syncthreads();
    }

    float sc = scalep ? scalep[zo] : 1.0f;
    #pragma unroll
    for (int i = 0; i < 2; i++)
        #pragma unroll
        for (int j = 0; j < 2; j++) {
            #pragma unroll
            for (int e = 0; e < acc[i][j].num_elements; e++) acc[i][j].x[e] *= sc;
            wmma::store_matrix_sync(
                &C[(size_t)(m0 + wm * 32 + i * 16) * ldc + n0 + wn * 32 + j * 16],
                acc[i][j], ldc, wmma::mem_row_major);
        }
}

// ---------------- attention scores s_i/s_j ----------------
__global__ void k_sij(const float* __restrict__ attn) {
    int bn = blockIdx.x;                      // b*512 + n
    __shared__ float row[CF];
    for (int i = threadIdx.x; i < CF; i += 256) row[i] = g_hp[(size_t)bn * CF + i];
    __syncthreads();
    int w = threadIdx.x >> 5, lane = threadIdx.x & 31;
    int h = w >> 1, part = w & 1;             // 8 warps: 4 heads x {i,j}
    const float* av = attn + h * (2*CDH) + part * CDH;
    float s = 0.f;
    for (int d = lane; d < CDH; d += 32) s += row[h*CDH + d] * av[d];
#pragma unroll
    for (int o = 16; o; o >>= 1) s += __shfl_xor_sync(0xffffffffu, s, o);
    if (!lane) {
        int b = bn >> 9, n = bn & 511;
        float* dst = part ? g_sj : g_si;
        dst[(b*CH + h)*CN + n] = s;
    }
}

// ---------- leakyrelu + row softmax -> alpha (bf16 hi/lo out) ----------
__global__ void k_alpha() {
    int row = blockIdx.x;                     // (b*H + h)*512 + i
    int bh = row >> 9;
    float s_i = g_si[row];
    const float* sjr = g_sj + bh * CN;
    __shared__ float shm[8], shs[8];
    int t = threadIdx.x, lane = t & 31, w = t >> 5;
    float e0 = s_i + sjr[t];       e0 = e0 >= 0.f ? e0 : 0.2f * e0;
    float e1 = s_i + sjr[t + 256]; e1 = e1 >= 0.f ? e1 : 0.2f * e1;
    float m = fmaxf(e0, e1);
#pragma unroll
    for (int o = 16; o; o >>= 1) m = fmaxf(m, __shfl_xor_sync(0xffffffffu, m, o));
    if (!lane) shm[w] = m;
    __syncthreads();
    if (t < 32) {
        float v = (t < 8) ? shm[t] : -INFINITY;
#pragma unroll
        for (int o = 4; o; o >>= 1) v = fmaxf(v, __shfl_xor_sync(0xffffffffu, v, o));
        if (t == 0) shm[0] = v;
    }
    __syncthreads();
    float bm = shm[0];
    float x0 = expf(e0 - bm), x1 = expf(e1 - bm);
    float s = x0 + x1;
#pragma unroll
    for (int o = 16; o; o >>= 1) s += __shfl_xor_sync(0xffffffffu, s, o);
    if (!lane) shs[w] = s;
    __syncthreads();
    if (t < 32) {
        float v = (t < 8) ? shs[t] : 0.f;
#pragma unroll
        for (int o = 4; o; o >>= 1) v += __shfl_xor_sync(0xffffffffu, v, o);
        if (t == 0) shs[0] = v;
    }
    __syncthreads();
    float inv = 1.f / shs[0];
    __nv_bfloat16 h0, l0, h1, l1;
    cvt_hl(x0 * inv, h0, l0);
    cvt_hl(x1 * inv, h1, l1);
    size_t base = (size_t)row * CN + t;
    g_alh[base] = h0;       g_all[base] = l0;
    g_alh[base + 256] = h1; g_all[base + 256] = l1;
}

// ------- edge scores: sum_a relu(pi+pj+b1)*w2 + b2; 32x32 tile, 2x2 microtile -------
__global__ void __launch_bounds__(256) k_edge(
    const float* __restrict__ b1, const float* __restrict__ w2,
    const float* __restrict__ b2)
{
    int b = blockIdx.z;
    int i0 = blockIdx.y * 32, j0 = blockIdx.x * 32;
    __shared__ __align__(16) float Pi[32][132], Pj[32][132];
    __shared__ float B1s[128], W2s[128];
    const float* pi = g_pij;
    const float* pj = g_pij + (size_t)CB*CN*CAH;
    int t = threadIdx.x;
    int ti = t >> 4, tj = t & 15;
    float acc[2][2] = {};
    for (int a0 = 0; a0 < CAH; a0 += 128) {
        if (t < 128) { B1s[t] = b1[a0 + t]; W2s[t] = w2[a0 + t]; }
        #pragma unroll
        for (int c = 0; c < 4; c++) {
            int q = t + 256 * c;            // 0..1023 over 32 rows x 32 float4
            int r = q >> 5, nc = (q & 31) * 4;
            *(float4*)&Pi[r][nc] = *(const float4*)&pi[(size_t)(b*CN + i0 + r) * CAH + a0 + nc];
            *(float4*)&Pj[r][nc] = *(const float4*)&pj[(size_t)(b*CN + j0 + r) * CAH + a0 + nc];
        }
        __syncthreads();
        #pragma unroll 8
        for (int a = 0; a < 128; a += 4) {
            float4 u0 = *(const float4*)&Pi[2*ti][a];
            float4 u1 = *(const float4*)&Pi[2*ti + 1][a];
            float4 v0 = *(const float4*)&Pj[2*tj][a];
            float4 v1 = *(const float4*)&Pj[2*tj + 1][a];
            float4 bb = *(const float4*)&B1s[a];
            float4 ww = *(const float4*)&W2s[a];
            #define EDGE_E(ue, ve, be, we) { \
                float p00 = ue.x + ve.x + be; float p01 = ue.x + ve.y + be; \
                float p10 = ue.y + ve.x + be; float p11 = ue.y + ve.y + be; \
                acc[0][0] += fmaxf(p00, 0.f) * we; \
                acc[0][1] += fmaxf(p01, 0.f) * we; \
                acc[1][0] += fmaxf(p10, 0.f) * we; \
                acc[1][1] += fmaxf(p11, 0.f) * we; }
            { float2 uu = make_float2(u0.x, u1.x), vv = make_float2(v0.x, v1.x); EDGE_E(uu, vv, bb.x, ww.x); }
            { float2 uu = make_float2(u0.y, u1.y), vv = make_float2(v0.y, v1.y); EDGE_E(uu, vv, bb.y, ww.y); }
            { float2 uu = make_float2(u0.z, u1.z), vv = make_float2(v0.z, v1.z); EDGE_E(uu, vv, bb.z, ww.z); }
            { float2 uu = make_float2(u0.w, u1.w), vv = make_float2(v0.w, v1.w); EDGE_E(uu, vv, bb.w, ww.w); }
            #undef EDGE_E
        }
        __syncthreads();
    }
    float bias = b2[0];
    #pragma unroll
    for (int r = 0; r < 2; r++) {
        float2 o = make_float2(acc[r][0] + bias, acc[r][1] + bias);
        *(float2*)&g_edge[(size_t)b * CNN + (i0 + 2*ti + r) * CN + j0 + 2*tj] = o;
    }
}

// ---------------- radix select pass A: hi-16 histogram + max ----------------
__global__ void k_passA() {
    int b = blockIdx.y;
    const float* e = g_edge + (size_t)b * CNN;
    unsigned lm = 0;
    for (int idx = blockIdx.x * blockDim.x + threadIdx.x; idx < CNN;
         idx += gridDim.x * blockDim.x) {
        unsigned key = key_of(e[idx]);
        atomicAdd(&g_hist[(b << 16) + (key >> 16)], 1u);
        lm = max(lm, key);
    }
    __shared__ unsigned sh[8];
    int t = threadIdx.x, lane = t & 31, w = t >> 5;
#pragma unroll
    for (int o = 16; o; o >>= 1) lm = max(lm, __shfl_xor_sync(0xffffffffu, lm, o));
    if (!lane) sh[w] = lm;
    __syncthreads();
    if (t == 0) {
        unsigned v = sh[0];
        for (int q = 1; q < 8; q++) v = max(v, sh[q]);
        atomicMax(&g_maxkey[b], v);
    }
}

__global__ void k_scan1() {
    int b = blockIdx.x;
    unsigned* h = g_hist + (b << 16);
    __shared__ unsigned part[1024];
    int t = threadIdx.x;
    unsigned s = 0;
    for (int i = 0; i < 64; i++) s += h[t*64 + i];
    part[t] = s;
    __syncthreads();
    for (int off = 1; off < 1024; off <<= 1) {
        unsigned v = (t >= off) ? part[t - off] : 0u;
        __syncthreads();
        if (t >= off) part[t] += v;
        __syncthreads();
    }
    unsigned r = RSEL;
    unsigned pre = t ? part[t-1] : 0u;
    if (pre <= r && r < part[t]) {
        unsigned rem = r - pre;
        for (int i = 0; i < 64; i++) {
            unsigned c = h[t*64 + i];
            if (rem < c) { g_selhi[b] = (unsigned)(t*64 + i); g_rank2[b] = rem; break; }
            rem -= c;
        }
    }
    __syncthreads();
    for (int i = t; i < 65536; i += 1024) h[i] = 0;   // re-zero for pass B
}

__global__ void k_passB() {
    int b = blockIdx.y;
    const float* e = g_edge + (size_t)b * CNN;
    unsigned hi = g_selhi[b];
    for (int idx = blockIdx.x * blockDim.x + threadIdx.x; idx < CNN;
         idx += gridDim.x * blockDim.x) {
        unsigned key = key_of(e[idx]);
        if ((key >> 16) == hi) atomicAdd(&g_hist[(b << 16) + (key & 0xFFFFu)], 1u);
    }
}

__global__ void k_scan2() {
    int b = blockIdx.x;
    unsigned* h = g_hist + (b << 16);
    __shared__ unsigned part[1024];
    int t = threadIdx.x;
    unsigned s = 0;
    for (int i = 0; i < 64; i++) s += h[t*64 + i];
    part[t] = s;
    __syncthreads();
    for (int off = 1; off < 1024; off <<= 1) {
        unsigned v = (t >= off) ? part[t - off] : 0u;
        __syncthreads();
        if (t >= off) part[t] += v;
        __syncthreads();
    }
    unsigned r = g_rank2[b];
    unsigned pre = t ? part[t-1] : 0u;
    if (pre <= r && r < part[t]) {
        unsigned rem = r - pre;
        for (int i = 0; i < 64; i++) {
            unsigned c = h[t*64 + i];
            if (rem < c) {
                unsigned key = (g_selhi[b] << 16) | (unsigned)(t*64 + i);
                g_thr[b] = key_inv(key);
                break;
            }
            rem -= c;
        }
    }
}

// --------- masked exp (unnormalized) -> bf16 hi/lo cm + partial sums ---------
__global__ void k_maskexp() {
    int b = blockIdx.y;
    const float* e = g_edge + (size_t)b * CNN;
    __nv_bfloat16* cmh = g_cmh + (size_t)b * CNN;
    __nv_bfloat16* cml = g_cml + (size_t)b * CNN;
    float zmax = key_inv(g_maxkey[b]);
    float th = g_thr[b];
    float ls = 0.f;
    for (int idx = blockIdx.x * blockDim.x + threadIdx.x; idx < CNN;
         idx += gridDim.x * blockDim.x) {
        float z = e[idx];
        float v = 0.f;
        if (z >= th) v = expf((z - zmax) * 2.0f);   // 1/TEMP = 2
        __nv_bfloat16 h, l;
        cvt_hl(v, h, l);
        cmh[idx] = h; cml[idx] = l;
        ls += v;
    }
    __shared__ float sh[8];
    int t = threadIdx.x, lane = t & 31, w = t >> 5;
#pragma unroll
    for (int o = 16; o; o >>= 1) ls += __shfl_xor_sync(0xffffffffu, ls, o);
    if (!lane) sh[w] = ls;
    __syncthreads();
    if (t == 0) {
        float v = sh[0];
        for (int q = 1; q < 8; q++) v += sh[q];
        atomicAdd(&g_msum[b], v);
    }
}

// invert sums once -> scale factors consumed by gemm epilogues
__global__ void k_inv() {
    int b = threadIdx.x;
    if (b < CB) g_msum[b] = 1.f / g_msum[b];
}

// ---------------- batch norm ----------------
__global__ void k_bnstats(const float* __restrict__ h, int C, float* sum, float* sq) {
    int row0 = blockIdx.x * 32;
    int c = threadIdx.x;
    float s = 0.f, q = 0.f;
    for (int r = 0; r < 32; r++) {
        float v = h[(size_t)(row0 + r) * C + c];
        s += v; q += v * v;
    }
    atomicAdd(&sum[c], s);
    atomicAdd(&sq[c], q);
}

// sum 4 K-split partials of h4, write h4, accumulate BN2 stats
__global__ void k_bnstats4() {
    int row0 = blockIdx.x * 32;
    int c = threadIdx.x;    // 128
    const long long S = (long long)CB * CN * COUT;
    float s = 0.f, q = 0.f;
    for (int r = 0; r < 32; r++) {
        size_t idx = (size_t)(row0 + r) * COUT + c;
        float v = g_h4p[idx] + g_h4p[idx + S] + g_h4p[idx + 2*S] + g_h4p[idx + 3*S];
        g_h4[idx] = v;
        s += v; q += v * v;
    }
    atomicAdd(&g_bs2[c], s);
    atomicAdd(&g_bq2[c], q);
}

__global__ void k_bnfinal(const float* sum, const float* sq,
                          const float* __restrict__ g, const float* __restrict__ bt,
                          float* scale, float* shift) {
    int c = threadIdx.x;
    const float invn = 1.f / (CB * CN);
    float mean = sum[c] * invn;
    float var = sq[c] * invn - mean * mean;
    float sc = g[c] * rsqrtf(var + 1e-5f);
    scale[c] = sc;
    shift[c] = bt[c] - mean * sc;
}

// BN1 apply + relu on h2 -> bf16 hi/lo
__global__ void k_bnrelu2() {
    const int total = CB * CN * CHID;
    for (int idx = blockIdx.x * blockDim.x + threadIdx.x; idx < total;
         idx += gridDim.x * blockDim.x) {
        int c = idx & (CHID - 1);
        float v = fmaxf(g_h2[idx] * g_sc1[c] + g_sh1[c], 0.f);
        __nv_bfloat16 h, l;
        cvt_hl(v, h, l);
        g_h2h[idx] = h; g_h2l[idx] = l;
    }
}

// ---------------- BN2-apply + relu + mean over N ----------------
__global__ void k_feat() {
    int b = blockIdx.x;
    int c = threadIdx.x;   // 128
    float sc = g_sc2[c], sh = g_sh2[c];
    float s = 0.f;
    for (int n = 0; n < CN; n++) {
        float v = g_h4[(size_t)(b*CN + n) * COUT + c] * sc + sh;
        s += fmaxf(v, 0.f);
    }
    g_feat[b*COUT + c] = s * (1.f / CN);
}

// ---------------- classifier ----------------
__global__ void k_cls(const float* __restrict__ cw, const float* __restrict__ cb,
                      float* __restrict__ out) {
    int w = threadIdx.x >> 5, lane = threadIdx.x & 31;
    if (w < CB * CNCLS) {
        int b = w / CNCLS, c = w % CNCLS;
        float s = 0.f;
        for (int f = lane; f < COUT; f += 32)
            s += g_feat[b*COUT + f] * cw[c*COUT + f];
#pragma unroll
        for (int o = 16; o; o >>= 1) s += __shfl_xor_sync(0xffffffffu, s, o);
        if (!lane) out[b*CNCLS + c] = s + cb[c];
    }
}

// ---------------- host launch ----------------
extern "C" void kernel_launch(void* const* d_in, const int* in_sizes, int n_in,
                              void* d_out, int out_size) {
    (void)in_sizes; (void)n_in; (void)out_size;
    const float* x    = (const float*)d_in[0];
    const float* Wg   = (const float*)d_in[1];
    const float* attn = (const float*)d_in[2];
    const float* W1   = (const float*)d_in[3];
    const float* b1   = (const float*)d_in[4];
    const float* w2   = (const float*)d_in[5];
    const float* b2   = (const float*)d_in[6];
    const float* gc1w = (const float*)d_in[7];
    /* gc1_b (8) cancels in BN */
    const float* bn1g = (const float*)d_in[9];
    const float* bn1b = (const float*)d_in[10];
    const float* gc2w = (const float*)d_in[11];
    /* gc2_b (12) cancels in BN */
    const float* bn2g = (const float*)d_in[13];
    const float* bn2b = (const float*)d_in[14];
    const float* clsw = (const float*)d_in[15];
    const float* clsb = (const float*)d_in[16];
    float* out = (float*)d_out;

    float *hp, *nf, *pij, *h1, *h2, *h3, *h4p;
    float *bs1, *bq1, *sc1, *sh1, *bs2, *bq2, *sc2, *sh2, *msum;
    cudaGetSymbolAddress((void**)&hp,  g_hp);
    cudaGetSymbolAddress((void**)&nf,  g_nf);
    cudaGetSymbolAddress((void**)&pij, g_pij);
    cudaGetSymbolAddress((void**)&h1,  g_h1);
    cudaGetSymbolAddress((void**)&h2,  g_h2);
    cudaGetSymbolAddress((void**)&h3,  g_h3);
    cudaGetSymbolAddress((void**)&h4p, g_h4p);
    cudaGetSymbolAddress((void**)&msum, g_msum);
    cudaGetSymbolAddress((void**)&bs1, g_bs1);
    cudaGetSymbolAddress((void**)&bq1, g_bq1);
    cudaGetSymbolAddress((void**)&sc1, g_sc1);
    cudaGetSymbolAddress((void**)&sh1, g_sh1);
    cudaGetSymbolAddress((void**)&bs2, g_bs2);
    cudaGetSymbolAddress((void**)&bq2, g_bq2);
    cudaGetSymbolAddress((void**)&sc2, g_sc2);
    cudaGetSymbolAddress((void**)&sh2, g_sh2);

    __nv_bfloat16 *xh,*xl,*Wgh,*Wgl,*hph,*hpl,*alh,*all,*nfh,*nfl,*W1h,*W1l;
    __nv_bfloat16 *cmh,*cml,*h1h,*h1l,*gc1h,*gc1l,*h2h,*h2l,*h3h,*h3l,*gc2h,*gc2l;
    cudaGetSymbolAddress((void**)&xh,  g_xh);   cudaGetSymbolAddress((void**)&xl,  g_xl);
    cudaGetSymbolAddress((void**)&Wgh, g_Wgh);  cudaGetSymbolAddress((void**)&Wgl, g_Wgl);
    cudaGetSymbolAddress((void**)&hph, g_hph);  cudaGetSymbolAddress((void**)&hpl, g_hpl);
    cudaGetSymbolAddress((void**)&alh, g_alh);  cudaGetSymbolAddress((void**)&all, g_all);
    cudaGetSymbolAddress((void**)&nfh, g_nfh);  cudaGetSymbolAddress((void**)&nfl, g_nfl);
    cudaGetSymbolAddress((void**)&W1h, g_W1h);  cudaGetSymbolAddress((void**)&W1l, g_W1l);
    cudaGetSymbolAddress((void**)&cmh, g_cmh);  cudaGetSymbolAddress((void**)&cml, g_cml);
    cudaGetSymbolAddress((void**)&h1h, g_h1h);  cudaGetSymbolAddress((void**)&h1l, g_h1l);
    cudaGetSymbolAddress((void**)&gc1h,g_gc1h); cudaGetSymbolAddress((void**)&gc1l,g_gc1l);
    cudaGetSymbolAddress((void**)&h2h, g_h2h);  cudaGetSymbolAddress((void**)&h2l, g_h2l);
    cudaGetSymbolAddress((void**)&h3h, g_h3h);  cudaGetSymbolAddress((void**)&h3l, g_h3l);
    cudaGetSymbolAddress((void**)&gc2h,g_gc2h); cudaGetSymbolAddress((void**)&gc2l,g_gc2l);

    k_zero<<<512, 256>>>();

    // one-shot conversions of external inputs
    k_cvt<<<(CB*CN*CF)/1024, 256>>>(x,    xh,   xl,   CB*CN*CF);
    k_cvt<<<(CF*CF)/1024, 256>>>(Wg,      Wgh,  Wgl,  CF*CF);
    k_cvt<<<(CAH*2*CF)/1024, 256>>>(W1,   W1h,  W1l,  CAH*2*CF);
    k_cvt<<<(CHID*CF)/1024, 256>>>(gc1w,  gc1h, gc1l, CHID*CF);
    k_cvt<<<(COUT*CHID)/1024, 256>>>(gc2w, gc2h, gc2l, COUT*CHID);

    // hp = x @ Wg^T     (1024 x 1024 x 1024)
    gemm_w<128, true><<<dim3(CF/128, (CB*CN)/64, 1), 256>>>(
        xh, xl, Wgh, Wgl, hp, CF, CF, CF, CF, 1, 0,0, 0,0, 0,0, (const float*)0);
    k_cvt<<<(CB*CN*CF)/1024, 256>>>(hp, hph, hpl, CB*CN*CF);

    k_sij<<<CB*CN, 256>>>(attn);
    k_alpha<<<CB*CH*CN, 256>>>();

    // node_feats: per (b,h)  alpha(512x512) @ hp_bh(512x256, ld 1024) -> nf (ld 1024)
    gemm_w<128, false><<<dim3(CDH/128, CN/64, CB*CH), 256>>>(
        alh, all, hph, hpl, nf, CN, CN, CF, CF,
        CH, (long long)CH*CNN, (long long)CNN,
        (long long)CN*CF, (long long)CDH,
        (long long)CN*CF, (long long)CDH, (const float*)0);
    k_cvt<<<(CB*CN*CF)/1024, 256>>>(nf, nfh, nfl, CB*CN*CF);

    // pi / pj = nf @ W1i^T / W1j^T   (z selects half of W1 and output block)
    gemm_w<64, true><<<dim3(CAH/64, (CB*CN)/64, 2), 128>>>(
        nfh, nfl, W1h, W1l, pij, CF, CF, 2*CF, CAH,
        1, 0, 0, (long long)CF, 0, (long long)CB*CN*CAH, 0, (const float*)0);

    k_edge<<<dim3(CN/32, CN/32, CB), 256>>>(b1, w2, b2);

    // exact top-k threshold via 2-pass radix select, then masked exp (norm folded into gemms)
    k_passA<<<dim3(128, CB), 256>>>();
    k_scan1<<<CB, 1024>>>();
    k_passB<<<dim3(128, CB), 256>>>();
    k_scan2<<<CB, 1024>>>();
    k_maskexp<<<dim3(128, CB), 256>>>();
    k_inv<<<1, 32>>>();

    // h1 = (cm/Z) @ nf    (per batch 512x1024x512), scale folded in
    gemm_w<128, false><<<dim3(CF/128, CN/64, CB), 256>>>(
        cmh, cml, nfh, nfl, h1, CN, CN, CF, CF,
        1, (long long)CNN, 0, (long long)CN*CF, 0, (long long)CN*CF, 0, msum);
    k_cvt<<<(CB*CN*CF)/1024, 256>>>(h1, h1h, h1l, CB*CN*CF);

    // h2 = h1 @ gc1_w^T   (1024 x 512 x 1024)   [gc1_b cancels in BN]
    gemm_w<64, true><<<dim3(CHID/64, (CB*CN)/64, 1), 128>>>(
        h1h, h1l, gc1h, gc1l, h2, CF, CF, CF, CHID, 1, 0,0, 0,0, 0,0, (const float*)0);

    k_bnstats<<<(CB*CN)/32, CHID>>>(h2, CHID, bs1, bq1);
    k_bnfinal<<<1, CHID>>>(bs1, bq1, bn1g, bn1b, sc1, sh1);
    k_bnrelu2<<<256, 256>>>();

    // h3 = (cm/Z) @ h2    (per batch 512x512x512), scale folded in
    gemm_w<64, false><<<dim3(CHID/64, CN/64, CB), 128>>>(
        cmh, cml, h2h, h2l, h3, CN, CN, CHID, CHID,
        1, (long long)CNN, 0, (long long)CN*CHID, 0, (long long)CN*CHID, 0, msum);
    k_cvt<<<(CB*CN*CHID)/1024, 256>>>(h3, h3h, h3l, CB*CN*CHID);

    // h4 = h3 @ gc2_w^T   (1024 x 128 x 512), K-split x4 into partials
    gemm_w<64, true><<<dim3(COUT/64, (CB*CN)/64, 4), 128>>>(
        h3h, h3l, gc2h, gc2l, h4p, CHID/4, CHID, CHID, COUT,
        1, 128, 0, 128, 0, (long long)CB*CN*COUT, 0, (const float*)0);

    k_bnstats4<<<(CB*CN)/32, COUT>>>();
    k_bnfinal<<<1, COUT>>>(bs2, bq2, bn2g, bn2b, sc2, sh2);

    k_feat<<<CB, COUT>>>();
    k_cls<<<1, 640>>>(clsw, clsb, out);
}

// round 12
// speedup vs baseline: 1.4717x; 1.0204x over previous
#include <cuda_runtime.h>
#include <cuda_bf16.h>
#include <mma.h>
#include <math.h>

using namespace nvcuda;

#define CB 2
#define CN 512
#define CF 1024
#define CH 4
#define CDH 256
#define CAH 256
#define CHID 512
#define COUT 128
#define CNCLS 10
#define CNN (CN*CN)
#define RSEL 52429u   /* NN - int(0.8*NN) = 262144 - 209715 */

// ---------------- scratch (static device memory; no allocations) ----------------
__device__ float g_hp[CB*CN*CF];
__device__ float g_si[CB*CH*CN];
__device__ float g_sj[CB*CH*CN];
__device__ float g_pij[2*CB*CN*CAH];
__device__ float g_edge[CB*CNN];
__device__ float g_h2[CB*CN*CHID];
__device__ float g_h4[CB*CN*COUT];
__device__ float g_h4p[4*CB*CN*COUT];
__device__ float g_feat[CB*COUT];
__device__ unsigned g_hist[CB*65536];
__device__ unsigned g_selhi[CB];
__device__ unsigned g_rank2[CB];
__device__ unsigned g_maxkey[CB];
__device__ float g_thr[CB];
__device__ float g_msum[CB];
__device__ float g_bs1[CHID], g_bq1[CHID], g_sc1[CHID], g_sh1[CHID];
__device__ float g_bs2[COUT], g_bq2[COUT], g_sc2[COUT], g_sh2[COUT];

// bf16 hi/lo operand mirrors
__device__ __nv_bfloat16 g_xh[CB*CN*CF],  g_xl[CB*CN*CF];
__device__ __nv_bfloat16 g_Wgh[CF*CF],    g_Wgl[CF*CF];
__device__ __nv_bfloat16 g_hph[CB*CN*CF], g_hpl[CB*CN*CF];
__device__ __nv_bfloat16 g_alh[CB*CH*CNN],g_all[CB*CH*CNN];
__device__ __nv_bfloat16 g_nfh[CB*CN*CF], g_nfl[CB*CN*CF];
__device__ __nv_bfloat16 g_W1h[CAH*2*CF], g_W1l[CAH*2*CF];
__device__ __nv_bfloat16 g_cmh[CB*CNN],   g_cml[CB*CNN];
__device__ __nv_bfloat16 g_h1h[CB*CN*CF], g_h1l[CB*CN*CF];
__device__ __nv_bfloat16 g_gc1h[CHID*CF], g_gc1l[CHID*CF];
__device__ __nv_bfloat16 g_h2h[CB*CN*CHID], g_h2l[CB*CN*CHID];
__device__ __nv_bfloat16 g_h3h[CB*CN*CHID], g_h3l[CB*CN*CHID];
__device__ __nv_bfloat16 g_gc2h[COUT*CHID], g_gc2l[COUT*CHID];

// ---------------- helpers ----------------
__device__ __forceinline__ unsigned key_of(float x) {
    unsigned u = __float_as_uint(x);
    return (u & 0x80000000u) ? ~u : (u | 0x80000000u);
}
__device__ __forceinline__ float key_inv(unsigned key) {
    unsigned u = (key & 0x80000000u) ? (key ^ 0x80000000u) : ~key;
    return __uint_as_float(u);
}
__device__ __forceinline__ void cvt_hl(float v, __nv_bfloat16& h, __nv_bfloat16& l) {
    h = __float2bfloat16(v);
    l = __float2bfloat16(v - __bfloat162float(h));
}

// ---------------- zero scratch (must run every launch; graph replays) ----------------
__global__ void k_zero() {
    int i = blockIdx.x * 256 + threadIdx.x;       // grid = 512 blocks -> 131072 threads
    g_hist[i] = 0;
    if (i < CHID) { g_bs1[i] = 0.f; g_bq1[i] = 0.f; }
    if (i < COUT) { g_bs2[i] = 0.f; g_bq2[i] = 0.f; }
    if (i < CB)   { g_msum[i] = 0.f; g_maxkey[i] = 0u; }
}

// ------------ fp32 -> bf16 hi/lo conversion, 16 floats per thread (ILP 4) ------------
__global__ void k_cvt(const float* __restrict__ src,
                      __nv_bfloat16* __restrict__ ho,
                      __nv_bfloat16* __restrict__ lo, int n) {
    int base = (blockIdx.x * 256 + threadIdx.x) * 16;
    if (base < n) {
        float4 v[4];
        #pragma unroll
        for (int q = 0; q < 4; q++) v[q] = *(const float4*)(src + base + q * 4);
        #pragma unroll
        for (int q = 0; q < 4; q++) {
            float vv[4] = {v[q].x, v[q].y, v[q].z, v[q].w};
            union { __nv_bfloat16 b[4]; uint2 u; } uh, ul;
            #pragma unroll
            for (int e = 0; e < 4; e++) cvt_hl(vv[e], uh.b[e], ul.b[e]);
            *(uint2*)(ho + base + q * 4) = uh.u;
            *(uint2*)(lo + base + q * 4) = ul.u;
        }
    }
}

// ====== split-bf16 tensor-core GEMM, bf16 hi/lo operands, K-chunk 32 ======
// TN=128: 256 thr, 8 warps (2x4).  TN=64: 128 thr, 4 warps (2x2).  Tile M64 x TN.
// C = scale * (Ah+Al) @ (Bh+Bl)'   (3 of 4 cross terms, fp32 accumulate)
// EPI: 0 = fp32 C only; 1 = fp32 C + bf16 hi/lo Ch/Cl; 2 = bf16 hi/lo only
template<int TN, bool BT, int EPI>
__global__ void __launch_bounds__(TN == 128 ? 256 : 128) gemm_w(
    const __nv_bfloat16* __restrict__ Ah, const __nv_bfloat16* __restrict__ Al,
    const __nv_bfloat16* __restrict__ Bh, const __nv_bfloat16* __restrict__ Bl,
    float* __restrict__ C, __nv_bfloat16* __restrict__ Ch, __nv_bfloat16* __restrict__ Cl,
    int K, int lda, int ldb, int ldc,
    int bdiv, long long sAo, long long sAi, long long sBo, long long sBi,
    long long sCo, long long sCi, const float* __restrict__ scalep)
{
    const int NT = (TN == 128) ? 256 : 128;
    const int NW = NT / 32;
    int z = blockIdx.z;
    int zo = z / bdiv, zi = z - zo * bdiv;
    long long aoff = zo * sAo + zi * sAi;
    long long boff = zo * sBo + zi * sBi;
    long long coff = zo * sCo + zi * sCi;
    Ah += aoff;  Al += aoff;
    Bh += boff;  Bl += boff;
    C  += coff;
    if (EPI) { Ch += coff; Cl += coff; }

    constexpr int BROWS = BT ? TN : 32;
    constexpr int BLD   = BT ? 40 : TN + 8;
    constexpr int STAGE = (64*40*2 + BROWS*BLD*2) * 2;          // bytes
    constexpr int CBY   = NW * 32 * 36 * 4;
    constexpr int SB    = (EPI && CBY > STAGE) ? CBY : STAGE;
    __shared__ __align__(16) char sraw[SB];
    __nv_bfloat16* AsH = (__nv_bfloat16*)sraw;
    __nv_bfloat16* AsL = AsH + 64 * 40;
    __nv_bfloat16* BsH = AsL + 64 * 40;
    __nv_bfloat16* BsL = BsH + BROWS * BLD;

    int t = threadIdx.x;
    int warp = t >> 5, lane = t & 31;
    int wm = (TN == 128) ? (warp >> 2) : (warp >> 1);
    int wn = (TN == 128) ? (warp & 3) : (warp & 1);
    int m0 = blockIdx.y * 64, n0 = blockIdx.x * TN;

    wmma::fragment<wmma::accumulator, 16, 16, 16, float> acc[2][2];
    #pragma unroll
    for (int i = 0; i < 2; i++)
        #pragma unroll
        for (int j = 0; j < 2; j++) wmma::fill_fragment(acc[i][j], 0.0f);

    for (int k0 = 0; k0 < K; k0 += 32) {
        // ---- stage A: 64 x 32, 16B groups ----
        #pragma unroll
        for (int g = t; g < 256; g += NT) {
            int r = g >> 2, c = (g & 3) * 8;
            size_t off = (size_t)(m0 + r) * lda + k0 + c;
            *(uint4*)&AsH[r * 40 + c] = *(const uint4*)(Ah + off);
            *(uint4*)&AsL[r * 40 + c] = *(const uint4*)(Al + off);
        }
        // ---- stage B ----
        if (BT) {
            #pragma unroll
            for (int g = t; g < TN * 4; g += NT) {
                int r = g >> 2, c = (g & 3) * 8;
                size_t off = (size_t)(n0 + r) * ldb + k0 + c;
                *(uint4*)&BsH[r * 40 + c] = *(const uint4*)(Bh + off);
                *(uint4*)&BsL[r * 40 + c] = *(const uint4*)(Bl + off);
            }
        } else {
            const int TPR = TN / 8;
            #pragma unroll
            for (int g = t; g < TN * 4; g += NT) {
                int r = g / TPR, c = (g % TPR) * 8;
                size_t off = (size_t)(k0 + r) * ldb + n0 + c;
                *(uint4*)&BsH[r * BLD + c] = *(const uint4*)(Bh + off);
                *(uint4*)&BsL[r * BLD + c] = *(const uint4*)(Bl + off);
            }
        }
        __syncthreads();

        #pragma unroll
        for (int hf = 0; hf < 2; hf++) {
            int ko = hf * 16;
            wmma::fragment<wmma::matrix_a, 16, 16, 16, __nv_bfloat16, wmma::row_major> aH[2], aL[2];
            #pragma unroll
            for (int i = 0; i < 2; i++) {
                wmma::load_matrix_sync(aH[i], &AsH[(wm * 32 + i * 16) * 40 + ko], 40);
                wmma::load_matrix_sync(aL[i], &AsL[(wm * 32 + i * 16) * 40 + ko], 40);
            }
            #pragma unroll
            for (int j = 0; j < 2; j++) {
                if (BT) {
                    wmma::fragment<wmma::matrix_b, 16, 16, 16, __nv_bfloat16, wmma::col_major> bH, bL;
                    wmma::load_matrix_sync(bH, &BsH[(wn * 32 + j * 16) * 40 + ko], 40);
                    wmma::load_matrix_sync(bL, &BsL[(wn * 32 + j * 16) * 40 + ko], 40);
                    #pragma unroll
                    for (int i = 0; i < 2; i++) {
                        wmma::mma_sync(acc[i][j], aH[i], bH, acc[i][j]);
                        wmma::mma_sync(acc[i][j], aH[i], bL, acc[i][j]);
                        wmma::mma_sync(acc[i][j], aL[i], bH, acc[i][j]);
                    }
                } else {
                    wmma::fragment<wmma::matrix_b, 16, 16, 16, __nv_bfloat16, wmma::row_major> bH, bL;
                    wmma::load_matrix_sync(bH, &BsH[ko * BLD + wn * 32 + j * 16], BLD);
                    wmma::load_matrix_sync(bL, &BsL[ko * BLD + wn * 32 + j * 16], BLD);
                    #pragma unroll
                    for (int i = 0; i < 2; i++) {
                        wmma::mma_sync(acc[i][j], aH[i], bH, acc[i][j]);
                        wmma::mma_sync(acc[i][j], aH[i], bL, acc[i][j]);
                        wmma::mma_sync(acc[i][j], aL[i], bH, acc[i][j]);
                    }
                }
            }
        }
        __syncthreads();
    }

    float sc = scalep ? scalep[zo] : 1.0f;
    if (EPI == 0) {
        #pragma unroll
        for (int i = 0; i < 2; i++)
            #pragma unroll
            for (int j = 0; j < 2; j++) {
                #pragma unroll
                for (int e = 0; e < acc[i][j].num_elements; e++) acc[i][j].x[e] *= sc;
                wmma::store_matrix_sync(
                    &C[(size_t)(m0 + wm * 32 + i * 16) * ldc + n0 + wn * 32 + j * 16],
                    acc[i][j], ldc, wmma::mem_row_major);
            }
    } else {
        // park fp32 tile in smem (aliases staging; last chunk already synced), repack
        float* Cs = (float*)sraw + warp * (32 * 36);
        #pragma unroll
        for (int i = 0; i < 2; i++)
            #pragma unroll
            for (int j = 0; j < 2; j++)
                wmma::store_matrix_sync(Cs + (i * 16) * 36 + j * 16, acc[i][j], 36,
                                        wmma::mem_row_major);
        __syncwarp();
        int grow = m0 + wm * 32 + lane;
        int gcol = n0 + wn * 32;
        const float* src = Cs + lane * 36;
        float v[32];
        #pragma unroll
        for (int c = 0; c < 32; c++) v[c] = src[c] * sc;
        if (EPI == 1) {
            #pragma unroll
            for (int q = 0; q < 8; q++)
                *(float4*)&C[(size_t)grow * ldc + gcol + q * 4] =
                    make_float4(v[q*4], v[q*4+1], v[q*4+2], v[q*4+3]);
        }
        #pragma unroll
        for (int q = 0; q < 4; q++) {
            union { __nv_bfloat16 b[8]; uint4 u; } ph, pl;
            #pragma unroll
            for (int e = 0; e < 8; e++) cvt_hl(v[q*8 + e], ph.b[e], pl.b[e]);
            *(uint4*)&Ch[(size_t)grow * ldc + gcol + q * 8] = ph.u;
            *(uint4*)&Cl[(size_t)grow * ldc + gcol + q * 8] = pl.u;
        }
    }
}

// ---------------- attention scores s_i/s_j ----------------
__global__ void k_sij(const float* __restrict__ attn) {
    int bn = blockIdx.x;                      // b*512 + n
    __shared__ float row[CF];
    for (int i = threadIdx.x; i < CF; i += 256) row[i] = g_hp[(size_t)bn * CF + i];
    __syncthreads();
    int w = threadIdx.x >> 5, lane = threadIdx.x & 31;
    int h = w >> 1, part = w & 1;             // 8 warps: 4 heads x {i,j}
    const float* av = attn + h * (2*CDH) + part * CDH;
    float s = 0.f;
    for (int d = lane; d < CDH; d += 32) s += row[h*CDH + d] * av[d];
#pragma unroll
    for (int o = 16; o; o >>= 1) s += __shfl_xor_sync(0xffffffffu, s, o);
    if (!lane) {
        int b = bn >> 9, n = bn & 511;
        float* dst = part ? g_sj : g_si;
        dst[(b*CH + h)*CN + n] = s;
    }
}

// ---------- leakyrelu + row softmax -> alpha (bf16 hi/lo out) ----------
__global__ void k_alpha() {
    int row = blockIdx.x;                     // (b*H + h)*512 + i
    int bh = row >> 9;
    float s_i = g_si[row];
    const float* sjr = g_sj + bh * CN;
    __shared__ float shm[8], shs[8];
    int t = threadIdx.x, lane = t & 31, w = t >> 5;
    float e0 = s_i + sjr[t];       e0 = e0 >= 0.f ? e0 : 0.2f * e0;
    float e1 = s_i + sjr[t + 256]; e1 = e1 >= 0.f ? e1 : 0.2f * e1;
    float m = fmaxf(e0, e1);
#pragma unroll
    for (int o = 16; o; o >>= 1) m = fmaxf(m, __shfl_xor_sync(0xffffffffu, m, o));
    if (!lane) shm[w] = m;
    __syncthreads();
    if (t < 32) {
        float v = (t < 8) ? shm[t] : -INFINITY;
#pragma unroll
        for (int o = 4; o; o >>= 1) v = fmaxf(v, __shfl_xor_sync(0xffffffffu, v, o));
        if (t == 0) shm[0] = v;
    }
    __syncthreads();
    float bm = shm[0];
    float x0 = expf(e0 - bm), x1 = expf(e1 - bm);
    float s = x0 + x1;
#pragma unroll
    for (int o = 16; o; o >>= 1) s += __shfl_xor_sync(0xffffffffu, s, o);
    if (!lane) shs[w] = s;
    __syncthreads();
    if (t < 32) {
        float v = (t < 8) ? shs[t] : 0.f;
#pragma unroll
        for (int o = 4; o; o >>= 1) v += __shfl_xor_sync(0xffffffffu, v, o);
        if (t == 0) shs[0] = v;
    }
    __syncthreads();
    float inv = 1.f / shs[0];
    __nv_bfloat16 h0, l0, h1, l1;
    cvt_hl(x0 * inv, h0, l0);
    cvt_hl(x1 * inv, h1, l1);
    size_t base = (size_t)row * CN + t;
    g_alh[base] = h0;       g_all[base] = l0;
    g_alh[base + 256] = h1; g_all[base + 256] = l1;
}

// ------- edge scores: sum_a relu(pi+pj+b1)*w2 + b2; 32x32 tile, 2x2 microtile -------
__global__ void __launch_bounds__(256) k_edge(
    const float* __restrict__ b1, const float* __restrict__ w2,
    const float* __restrict__ b2)
{
    int b = blockIdx.z;
    int i0 = blockIdx.y * 32, j0 = blockIdx.x * 32;
    __shared__ __align__(16) float Pi[32][132], Pj[32][132];
    __shared__ float B1s[128], W2s[128];
    const float* pi = g_pij;
    const float* pj = g_pij + (size_t)CB*CN*CAH;
    int t = threadIdx.x;
    int ti = t >> 4, tj = t & 15;
    float acc[2][2] = {};
    for (int a0 = 0; a0 < CAH; a0 += 128) {
        if (t < 128) { B1s[t] = b1[a0 + t]; W2s[t] = w2[a0 + t]; }
        #pragma unroll
        for (int c = 0; c < 4; c++) {
            int q = t + 256 * c;            // 0..1023 over 32 rows x 32 float4
            int r = q >> 5, nc = (q & 31) * 4;
            *(float4*)&Pi[r][nc] = *(const float4*)&pi[(size_t)(b*CN + i0 + r) * CAH + a0 + nc];
            *(float4*)&Pj[r][nc] = *(const float4*)&pj[(size_t)(b*CN + j0 + r) * CAH + a0 + nc];
        }
        __syncthreads();
        #pragma unroll 8
        for (int a = 0; a < 128; a += 4) {
            float4 u0 = *(const float4*)&Pi[2*ti][a];
            float4 u1 = *(const float4*)&Pi[2*ti + 1][a];
            float4 v0 = *(const float4*)&Pj[2*tj][a];
            float4 v1 = *(const float4*)&Pj[2*tj + 1][a];
            float4 bb = *(const float4*)&B1s[a];
            float4 ww = *(const float4*)&W2s[a];
            #define EDGE_E(ue, ve, be, we) { \
                float p00 = ue.x + ve.x + be; float p01 = ue.x + ve.y + be; \
                float p10 = ue.y + ve.x + be; float p11 = ue.y + ve.y + be; \
                acc[0][0] += fmaxf(p00, 0.f) * we; \
                acc[0][1] += fmaxf(p01, 0.f) * we; \
                acc[1][0] += fmaxf(p10, 0.f) * we; \
                acc[1][1] += fmaxf(p11, 0.f) * we; }
            { float2 uu = make_float2(u0.x, u1.x), vv = make_float2(v0.x, v1.x); EDGE_E(uu, vv, bb.x, ww.x); }
            { float2 uu = make_float2(u0.y, u1.y), vv = make_float2(v0.y, v1.y); EDGE_E(uu, vv, bb.y, ww.y); }
            { float2 uu = make_float2(u0.z, u1.z), vv = make_float2(v0.z, v1.z); EDGE_E(uu, vv, bb.z, ww.z); }
            { float2 uu = make_float2(u0.w, u1.w), vv = make_float2(v0.w, v1.w); EDGE_E(uu, vv, bb.w, ww.w); }
            #undef EDGE_E
        }
        __syncthreads();
    }
    float bias = b2[0];
    #pragma unroll
    for (int r = 0; r < 2; r++) {
        float2 o = make_float2(acc[r][0] + bias, acc[r][1] + bias);
        *(float2*)&g_edge[(size_t)b * CNN + (i0 + 2*ti + r) * CN + j0 + 2*tj] = o;
    }
}

// ---------------- radix select pass A: hi-16 histogram + max ----------------
__global__ void k_passA() {
    int b = blockIdx.y;
    const float* e = g_edge + (size_t)b * CNN;
    unsigned lm = 0;
    for (int idx = blockIdx.x * blockDim.x + threadIdx.x; idx < CNN;
         idx += gridDim.x * blockDim.x) {
        unsigned key = key_of(e[idx]);
        atomicAdd(&g_hist[(b << 16) + (key >> 16)], 1u);
        lm = max(lm, key);
    }
    __shared__ unsigned sh[8];
    int t = threadIdx.x, lane = t & 31, w = t >> 5;
#pragma unroll
    for (int o = 16; o; o >>= 1) lm = max(lm, __shfl_xor_sync(0xffffffffu, lm, o));
    if (!lane) sh[w] = lm;
    __syncthreads();
    if (t == 0) {
        unsigned v = sh[0];
        for (int q = 1; q < 8; q++) v = max(v, sh[q]);
        atomicMax(&g_maxkey[b], v);
    }
}

__global__ void k_scan1() {
    int b = blockIdx.x;
    unsigned* h = g_hist + (b << 16);
    __shared__ unsigned part[1024];
    int t = threadIdx.x;
    unsigned s = 0;
    for (int i = 0; i < 64; i++) s += h[t*64 + i];
    part[t] = s;
    __syncthreads();
    for (int off = 1; off < 1024; off <<= 1) {
        unsigned v = (t >= off) ? part[t - off] : 0u;
        __syncthreads();
        if (t >= off) part[t] += v;
        __syncthreads();
    }
    unsigned r = RSEL;
    unsigned pre = t ? part[t-1] : 0u;
    if (pre <= r && r < part[t]) {
        unsigned rem = r - pre;
        for (int i = 0; i < 64; i++) {
            unsigned c = h[t*64 + i];
            if (rem < c) { g_selhi[b] = (unsigned)(t*64 + i); g_rank2[b] = rem; break; }
            rem -= c;
        }
    }
    __syncthreads();
    for (int i = t; i < 65536; i += 1024) h[i] = 0;   // re-zero for pass B
}

__global__ void k_passB() {
    int b = blockIdx.y;
    const float* e = g_edge + (size_t)b * CNN;
    unsigned hi = g_selhi[b];
    for (int idx = blockIdx.x * blockDim.x + threadIdx.x; idx < CNN;
         idx += gridDim.x * blockDim.x) {
        unsigned key = key_of(e[idx]);
        if ((key >> 16) == hi) atomicAdd(&g_hist[(b << 16) + (key & 0xFFFFu)], 1u);
    }
}

__global__ void k_scan2() {
    int b = blockIdx.x;
    unsigned* h = g_hist + (b << 16);
    __shared__ unsigned part[1024];
    int t = threadIdx.x;
    unsigned s = 0;
    for (int i = 0; i < 64; i++) s += h[t*64 + i];
    part[t] = s;
    __syncthreads();
    for (int off = 1; off < 1024; off <<= 1) {
        unsigned v = (t >= off) ? part[t - off] : 0u;
        __syncthreads();
        if (t >= off) part[t] += v;
        __syncthreads();
    }
    unsigned r = g_rank2[b];
    unsigned pre = t ? part[t-1] : 0u;
    if (pre <= r && r < part[t]) {
        unsigned rem = r - pre;
        for (int i = 0; i < 64; i++) {
            unsigned c = h[t*64 + i];
            if (rem < c) {
                unsigned key = (g_selhi[b] << 16) | (unsigned)(t*64 + i);
                g_thr[b] = key_inv(key);
                break;
            }
            rem -= c;
        }
    }
}

// --------- masked exp (unnormalized) -> bf16 hi/lo cm + partial sums ---------
__global__ void k_maskexp() {
    int b = blockIdx.y;
    const float* e = g_edge + (size_t)b * CNN;
    __nv_bfloat16* cmh = g_cmh + (size_t)b * CNN;
    __nv_bfloat16* cml = g_cml + (size_t)b * CNN;
    float zmax = key_inv(g_maxkey[b]);
    float th = g_thr[b];
    float ls = 0.f;
    for (int idx = blockIdx.x * blockDim.x + threadIdx.x; idx < CNN;
         idx += gridDim.x * blockDim.x) {
        float z = e[idx];
        float v = 0.f;
        if (z >= th) v = expf((z - zmax) * 2.0f);   // 1/TEMP = 2
        __nv_bfloat16 h, l;
        cvt_hl(v, h, l);
        cmh[idx] = h; cml[idx] = l;
        ls += v;
    }
    __shared__ float sh[8];
    int t = threadIdx.x, lane = t & 31, w = t >> 5;
#pragma unroll
    for (int o = 16; o; o >>= 1) ls += __shfl_xor_sync(0xffffffffu, ls, o);
    if (!lane) sh[w] = ls;
    __syncthreads();
    if (t == 0) {
        float v = sh[0];
        for (int q = 1; q < 8; q++) v += sh[q];
        atomicAdd(&g_msum[b], v);
    }
}

// invert sums once -> scale factors consumed by gemm epilogues
__global__ void k_inv() {
    int b = threadIdx.x;
    if (b < CB) g_msum[b] = 1.f / g_msum[b];
}

// ---------------- batch norm ----------------
__global__ void k_bnstats(const float* __restrict__ h, int C, float* sum, float* sq) {
    int row0 = blockIdx.x * 32;
    int c = threadIdx.x;
    float s = 0.f, q = 0.f;
    for (int r = 0; r < 32; r++) {
        float v = h[(size_t)(row0 + r) * C + c];
        s += v; q += v * v;
    }
    atomicAdd(&sum[c], s);
    atomicAdd(&sq[c], q);
}

// sum 4 K-split partials of h4, write h4, accumulate BN2 stats
__global__ void k_bnstats4() {
    int row0 = blockIdx.x * 32;
    int c = threadIdx.x;    // 128
    const long long S = (long long)CB * CN * COUT;
    float s = 0.f, q = 0.f;
    for (int r = 0; r < 32; r++) {
        size_t idx = (size_t)(row0 + r) * COUT + c;
        float v = g_h4p[idx] + g_h4p[idx + S] + g_h4p[idx + 2*S] + g_h4p[idx + 3*S];
        g_h4[idx] = v;
        s += v; q += v * v;
    }
    atomicAdd(&g_bs2[c], s);
    atomicAdd(&g_bq2[c], q);
}

__global__ void k_bnfinal(const float* sum, const float* sq,
                          const float* __restrict__ g, const float* __restrict__ bt,
                          float* scale, float* shift) {
    int c = threadIdx.x;
    const float invn = 1.f / (CB * CN);
    float mean = sum[c] * invn;
    float var = sq[c] * invn - mean * mean;
    float sc = g[c] * rsqrtf(var + 1e-5f);
    scale[c] = sc;
    shift[c] = bt[c] - mean * sc;
}

// BN1 apply + relu on h2 -> bf16 hi/lo
__global__ void k_bnrelu2() {
    const int total = CB * CN * CHID;
    for (int idx = blockIdx.x * blockDim.x + threadIdx.x; idx < total;
         idx += gridDim.x * blockDim.x) {
        int c = idx & (CHID - 1);
        float v = fmaxf(g_h2[idx] * g_sc1[c] + g_sh1[c], 0.f);
        __nv_bfloat16 h, l;
        cvt_hl(v, h, l);
        g_h2h[idx] = h; g_h2l[idx] = l;
    }
}

// ---------------- BN2-apply + relu + mean over N ----------------
__global__ void k_feat() {
    int b = blockIdx.x;
    int c = threadIdx.x;   // 128
    float sc = g_sc2[c], sh = g_sh2[c];
    float s = 0.f;
    for (int n = 0; n < CN; n++) {
        float v = g_h4[(size_t)(b*CN + n) * COUT + c] * sc + sh;
        s += fmaxf(v, 0.f);
    }
    g_feat[b*COUT + c] = s * (1.f / CN);
}

// ---------------- classifier ----------------
__global__ void k_cls(const float* __restrict__ cw, const float* __restrict__ cb,
                      float* __restrict__ out) {
    int w = threadIdx.x >> 5, lane = threadIdx.x & 31;
    if (w < CB * CNCLS) {
        int b = w / CNCLS, c = w % CNCLS;
        float s = 0.f;
        for (int f = lane; f < COUT; f += 32)
            s += g_feat[b*COUT + f] * cw[c*COUT + f];
#pragma unroll
        for (int o = 16; o; o >>= 1) s += __shfl_xor_sync(0xffffffffu, s, o);
        if (!lane) out[b*CNCLS + c] = s + cb[c];
    }
}

// ---------------- host launch ----------------
extern "C" void kernel_launch(void* const* d_in, const int* in_sizes, int n_in,
                              void* d_out, int out_size) {
    (void)in_sizes; (void)n_in; (void)out_size;
    const float* x    = (const float*)d_in[0];
    const float* Wg   = (const float*)d_in[1];
    const float* attn = (const float*)d_in[2];
    const float* W1   = (const float*)d_in[3];
    const float* b1   = (const float*)d_in[4];
    const float* w2   = (const float*)d_in[5];
    const float* b2   = (const float*)d_in[6];
    const float* gc1w = (const float*)d_in[7];
    /* gc1_b (8) cancels in BN */
    const float* bn1g = (const float*)d_in[9];
    const float* bn1b = (const float*)d_in[10];
    const float* gc2w = (const float*)d_in[11];
    /* gc2_b (12) cancels in BN */
    const float* bn2g = (const float*)d_in[13];
    const float* bn2b = (const float*)d_in[14];
    const float* clsw = (const float*)d_in[15];
    const float* clsb = (const float*)d_in[16];
    float* out = (float*)d_out;

    float *hp, *pij, *h2, *h4p;
    float *bs1, *bq1, *sc1, *sh1, *bs2, *bq2, *sc2, *sh2, *msum;
    cudaGetSymbolAddress((void**)&hp,  g_hp);
    cudaGetSymbolAddress((void**)&pij, g_pij);
    cudaGetSymbolAddress((void**)&h2,  g_h2);
    cudaGetSymbolAddress((void**)&h4p, g_h4p);
    cudaGetSymbolAddress((void**)&msum, g_msum);
    cudaGetSymbolAddress((void**)&bs1, g_bs1);
    cudaGetSymbolAddress((void**)&bq1, g_bq1);
    cudaGetSymbolAddress((void**)&sc1, g_sc1);
    cudaGetSymbolAddress((void**)&sh1, g_sh1);
    cudaGetSymbolAddress((void**)&bs2, g_bs2);
    cudaGetSymbolAddress((void**)&bq2, g_bq2);
    cudaGetSymbolAddress((void**)&sc2, g_sc2);
    cudaGetSymbolAddress((void**)&sh2, g_sh2);

    __nv_bfloat16 *xh,*xl,*Wgh,*Wgl,*hph,*hpl,*alh,*all,*nfh,*nfl,*W1h,*W1l;
    __nv_bfloat16 *cmh,*cml,*h1h,*h1l,*gc1h,*gc1l,*h2h,*h2l,*h3h,*h3l,*gc2h,*gc2l;
    cudaGetSymbolAddress((void**)&xh,  g_xh);   cudaGetSymbolAddress((void**)&xl,  g_xl);
    cudaGetSymbolAddress((void**)&Wgh, g_Wgh);  cudaGetSymbolAddress((void**)&Wgl, g_Wgl);
    cudaGetSymbolAddress((void**)&hph, g_hph);  cudaGetSymbolAddress((void**)&hpl, g_hpl);
    cudaGetSymbolAddress((void**)&alh, g_alh);  cudaGetSymbolAddress((void**)&all, g_all);
    cudaGetSymbolAddress((void**)&nfh, g_nfh);  cudaGetSymbolAddress((void**)&nfl, g_nfl);
    cudaGetSymbolAddress((void**)&W1h, g_W1h);  cudaGetSymbolAddress((void**)&W1l, g_W1l);
    cudaGetSymbolAddress((void**)&cmh, g_cmh);  cudaGetSymbolAddress((void**)&cml, g_cml);
    cudaGetSymbolAddress((void**)&h1h, g_h1h);  cudaGetSymbolAddress((void**)&h1l, g_h1l);
    cudaGetSymbolAddress((void**)&gc1h,g_gc1h); cudaGetSymbolAddress((void**)&gc1l,g_gc1l);
    cudaGetSymbolAddress((void**)&h2h, g_h2h);  cudaGetSymbolAddress((void**)&h2l, g_h2l);
    cudaGetSymbolAddress((void**)&h3h, g_h3h);  cudaGetSymbolAddress((void**)&h3l, g_h3l);
    cudaGetSymbolAddress((void**)&gc2h,g_gc2h); cudaGetSymbolAddress((void**)&gc2l,g_gc2l);

    k_zero<<<512, 256>>>();

    // one-shot conversions of external inputs (16 floats/thread)
    k_cvt<<<(CB*CN*CF)/4096, 256>>>(x,    xh,   xl,   CB*CN*CF);
    k_cvt<<<(CF*CF)/4096, 256>>>(Wg,      Wgh,  Wgl,  CF*CF);
    k_cvt<<<(CAH*2*CF)/4096, 256>>>(W1,   W1h,  W1l,  CAH*2*CF);
    k_cvt<<<(CHID*CF)/4096, 256>>>(gc1w,  gc1h, gc1l, CHID*CF);
    k_cvt<<<(COUT*CHID)/4096, 256>>>(gc2w, gc2h, gc2l, COUT*CHID);

    // hp = x @ Wg^T  (fp32 out for k_sij + bf16 hi/lo for nf gemm)
    gemm_w<128, true, 1><<<dim3(CF/128, (CB*CN)/64, 1), 256>>>(
        xh, xl, Wgh, Wgl, hp, hph, hpl, CF, CF, CF, CF, 1, 0,0, 0,0, 0,0, (const float*)0);

    k_sij<<<CB*CN, 256>>>(attn);
    k_alpha<<<CB*CH*CN, 256>>>();

    // node_feats: per (b,h)  alpha(512x512) @ hp_bh -> nf (bf16 hi/lo only)
    gemm_w<128, false, 2><<<dim3(CDH/128, CN/64, CB*CH), 256>>>(
        alh, all, hph, hpl, (float*)0, nfh, nfl, CN, CN, CF, CF,
        CH, (long long)CH*CNN, (long long)CNN,
        (long long)CN*CF, (long long)CDH,
        (long long)CN*CF, (long long)CDH, (const float*)0);

    // pi / pj = nf @ W1i^T / W1j^T   (fp32 only)
    gemm_w<64, true, 0><<<dim3(CAH/64, (CB*CN)/64, 2), 128>>>(
        nfh, nfl, W1h, W1l, pij, (__nv_bfloat16*)0, (__nv_bfloat16*)0, CF, CF, 2*CF, CAH,
        1, 0, 0, (long long)CF, 0, (long long)CB*CN*CAH, 0, (const float*)0);

    k_edge<<<dim3(CN/32, CN/32, CB), 256>>>(b1, w2, b2);

    // exact top-k threshold via 2-pass radix select, then masked exp (norm folded into gemms)
    k_passA<<<dim3(128, CB), 256>>>();
    k_scan1<<<CB, 1024>>>();
    k_passB<<<dim3(128, CB), 256>>>();
    k_scan2<<<CB, 1024>>>();
    k_maskexp<<<dim3(128, CB), 256>>>();
    k_inv<<<1, 32>>>();

    // h1 = (cm/Z) @ nf  (bf16 hi/lo only), scale folded in
    gemm_w<128, false, 2><<<dim3(CF/128, CN/64, CB), 256>>>(
        cmh, cml, nfh, nfl, (float*)0, h1h, h1l, CN, CN, CF, CF,
        1, (long long)CNN, 0, (long long)CN*CF, 0, (long long)CN*CF, 0, msum);

    // h2 = h1 @ gc1_w^T  (fp32 for bnstats)   [gc1_b cancels in BN]
    gemm_w<64, true, 0><<<dim3(CHID/64, (CB*CN)/64, 1), 128>>>(
        h1h, h1l, gc1h, gc1l, h2, (__nv_bfloat16*)0, (__nv_bfloat16*)0, CF, CF, CF, CHID,
        1, 0,0, 0,0, 0,0, (const float*)0);

    k_bnstats<<<(CB*CN)/32, CHID>>>(h2, CHID, bs1, bq1);
    k_bnfinal<<<1, CHID>>>(bs1, bq1, bn1g, bn1b, sc1, sh1);
    k_bnrelu2<<<256, 256>>>();

    // h3 = (cm/Z) @ h2  (bf16 hi/lo only), scale folded in
    gemm_w<64, false, 2><<<dim3(CHID/64, CN/64, CB), 128>>>(
        cmh, cml, h2h, h2l, (float*)0, h3h, h3l, CN, CN, CHID, CHID,
        1, (long long)CNN, 0, (long long)CN*CHID, 0, (long long)CN*CHID, 0, msum);

    // h4 = h3 @ gc2_w^T  (K-split x4 partials, fp32)
    gemm_w<64, true, 0><<<dim3(COUT/64, (CB*CN)/64, 4), 128>>>(
        h3h, h3l, gc2h, gc2l, h4p, (__nv_bfloat16*)0, (__nv_bfloat16*)0, CHID/4, CHID, CHID, COUT,
        1, 128, 0, 128, 0, (long long)CB*CN*COUT, 0, (const float*)0);

    k_bnstats4<<<(CB*CN)/32, COUT>>>();
    k_bnfinal<<<1, COUT>>>(bs2, bq2, bn2g, bn2b, sc2, sh2);

    k_feat<<<CB, COUT>>>();
    k_cls<<<1, 640>>>(clsw, clsb, out);
}

// round 14
// speedup vs baseline: 1.6544x; 1.1241x over previous
#include <cuda_runtime.h>
#include <cuda_bf16.h>
#include <mma.h>
#include <math.h>

using namespace nvcuda;

#define CB 2
#define CN 512
#define CF 1024
#define CH 4
#define CDH 256
#define CAH 256
#define CHID 512
#define COUT 128
#define CNCLS 10
#define CNN (CN*CN)
#define RSEL 52429u   /* NN - int(0.8*NN) = 262144 - 209715 */

// ---------------- scratch (static device memory; no allocations) ----------------
__device__ float g_hp[CB*CN*CF];
__device__ float g_si[CB*CH*CN];
__device__ float g_sj[CB*CH*CN];
__device__ float g_pij[2*CB*CN*CAH];
__device__ float g_edge[CB*CNN];
__device__ float g_h2[CB*CN*CHID];
__device__ float g_h4[CB*CN*COUT];
__device__ float g_h4p[4*CB*CN*COUT];
__device__ float g_feat[CB*COUT];
__device__ unsigned g_hist[CB*65536];
__device__ unsigned g_selhi[CB];
__device__ unsigned g_rank2[CB];
__device__ unsigned g_maxkey[CB];
__device__ float g_thr[CB];
__device__ float g_msum[CB];
__device__ float g_bs1[CHID], g_bq1[CHID], g_sc1[CHID], g_sh1[CHID];
__device__ float g_bs2[COUT], g_bq2[COUT], g_sc2[COUT], g_sh2[COUT];

// bf16 hi/lo operand mirrors
__device__ __nv_bfloat16 g_xh[CB*CN*CF],  g_xl[CB*CN*CF];
__device__ __nv_bfloat16 g_Wgh[CF*CF],    g_Wgl[CF*CF];
__device__ __nv_bfloat16 g_hph[CB*CN*CF], g_hpl[CB*CN*CF];
__device__ __nv_bfloat16 g_alh[CB*CH*CNN],g_all[CB*CH*CNN];
__device__ __nv_bfloat16 g_nfh[CB*CN*CF], g_nfl[CB*CN*CF];
__device__ __nv_bfloat16 g_W1h[CAH*2*CF], g_W1l[CAH*2*CF];
__device__ __nv_bfloat16 g_cmh[CB*CNN],   g_cml[CB*CNN];
__device__ __nv_bfloat16 g_h1h[CB*CN*CF], g_h1l[CB*CN*CF];
__device__ __nv_bfloat16 g_gc1h[CHID*CF], g_gc1l[CHID*CF];
__device__ __nv_bfloat16 g_h2h[CB*CN*CHID], g_h2l[CB*CN*CHID];
__device__ __nv_bfloat16 g_h3h[CB*CN*CHID], g_h3l[CB*CN*CHID];
__device__ __nv_bfloat16 g_gc2h[COUT*CHID], g_gc2l[COUT*CHID];

// ---------------- helpers ----------------
__device__ __forceinline__ unsigned key_of(float x) {
    unsigned u = __float_as_uint(x);
    return (u & 0x80000000u) ? ~u : (u | 0x80000000u);
}
__device__ __forceinline__ float key_inv(unsigned key) {
    unsigned u = (key & 0x80000000u) ? (key ^ 0x80000000u) : ~key;
    return __uint_as_float(u);
}
__device__ __forceinline__ void cvt_hl(float v, __nv_bfloat16& h, __nv_bfloat16& l) {
    h = __float2bfloat16(v);
    l = __float2bfloat16(v - __bfloat162float(h));
}
__device__ __forceinline__ void cpa16(void* smem, const void* gmem) {
    unsigned saddr = (unsigned)__cvta_generic_to_shared(smem);
    asm volatile("cp.async.ca.shared.global [%0], [%1], 16;\n" :: "r"(saddr), "l"(gmem));
}
#define CPA_COMMIT() asm volatile("cp.async.commit_group;\n" ::: "memory")
#define CPA_WAIT0()  asm volatile("cp.async.wait_group 0;\n" ::: "memory")

// ---------------- zero scratch (must run every launch; graph replays) ----------------
__global__ void k_zero() {
    int i = blockIdx.x * 256 + threadIdx.x;       // grid = 512 blocks -> 131072 threads
    g_hist[i] = 0;
    if (i < CHID) { g_bs1[i] = 0.f; g_bq1[i] = 0.f; }
    if (i < COUT) { g_bs2[i] = 0.f; g_bq2[i] = 0.f; }
    if (i < CB)   { g_msum[i] = 0.f; g_maxkey[i] = 0u; }
}

// ------ fused one-shot input conversions: 5 tensors, block-range dispatch ------
// elements/block = 4096. x:256 | Wg:256 | W1:128 | gc1:128 | gc2:16  -> 784 blocks
__global__ void k_cvt5(const float* __restrict__ x,   const float* __restrict__ Wg,
                       const float* __restrict__ W1,  const float* __restrict__ gc1,
                       const float* __restrict__ gc2) {
    int b = blockIdx.x;
    const float* src; __nv_bfloat16 *ho, *lo; int blk;
    if (b < 256)       { src = x;   ho = g_xh;   lo = g_xl;   blk = b; }
    else if (b < 512)  { src = Wg;  ho = g_Wgh;  lo = g_Wgl;  blk = b - 256; }
    else if (b < 640)  { src = W1;  ho = g_W1h;  lo = g_W1l;  blk = b - 512; }
    else if (b < 768)  { src = gc1; ho = g_gc1h; lo = g_gc1l; blk = b - 640; }
    else               { src = gc2; ho = g_gc2h; lo = g_gc2l; blk = b - 768; }
    int base = blk * 4096 + threadIdx.x * 16;
    float4 v[4];
    #pragma unroll
    for (int q = 0; q < 4; q++) v[q] = *(const float4*)(src + base + q * 4);
    #pragma unroll
    for (int q = 0; q < 4; q++) {
        float vv[4] = {v[q].x, v[q].y, v[q].z, v[q].w};
        union { __nv_bfloat16 bb[4]; uint2 u; } uh, ul;
        #pragma unroll
        for (int e = 0; e < 4; e++) cvt_hl(vv[e], uh.bb[e], ul.bb[e]);
        *(uint2*)(ho + base + q * 4) = uh.u;
        *(uint2*)(lo + base + q * 4) = ul.u;
    }
}

// ====== split-bf16 tensor-core GEMM, cp.async double-buffered, K-chunk 32 ======
// TN=128: 256 thr, 8 warps (2x4).  TN=64: 128 thr, 4 warps (2x2).  Tile M64 x TN.
// C = scale * (Ah+Al) @ (Bh+Bl)'   (3 of 4 cross terms, fp32 accumulate)
// EPI: 0 = fp32 C only; 1 = fp32 C + bf16 hi/lo Ch/Cl; 2 = bf16 hi/lo only
template<int TN, bool BT, int EPI>
__global__ void __launch_bounds__(TN == 128 ? 256 : 128) gemm_w(
    const __nv_bfloat16* __restrict__ Ah, const __nv_bfloat16* __restrict__ Al,
    const __nv_bfloat16* __restrict__ Bh, const __nv_bfloat16* __restrict__ Bl,
    float* __restrict__ C, __nv_bfloat16* __restrict__ Ch, __nv_bfloat16* __restrict__ Cl,
    int K, int lda, int ldb, int ldc,
    int bdiv, long long sAo, long long sAi, long long sBo, long long sBi,
    long long sCo, long long sCi, const float* __restrict__ scalep)
{
    const int NT = (TN == 128) ? 256 : 128;
    extern __shared__ __align__(16) char sraw[];
    constexpr int BROWS = BT ? TN : 32;
    constexpr int BLD   = BT ? 40 : TN + 8;
    constexpr int AELE  = 64 * 40;                 // elements per A plane
    constexpr int BELE  = BROWS * BLD;
    constexpr int BUFE  = 2 * AELE + 2 * BELE;     // elements per buffer (H+L planes)

    int z = blockIdx.z;
    int zo = z / bdiv, zi = z - zo * bdiv;
    long long aoff = zo * sAo + zi * sAi;
    long long boff = zo * sBo + zi * sBi;
    long long coff = zo * sCo + zi * sCi;
    Ah += aoff;  Al += aoff;
    Bh += boff;  Bl += boff;
    C  += coff;
    if (EPI) { Ch += coff; Cl += coff; }

    int t = threadIdx.x;
    int warp = t >> 5, lane = t & 31;
    int wm = (TN == 128) ? (warp >> 2) : (warp >> 1);
    int wn = (TN == 128) ? (warp & 3) : (warp & 1);
    int m0 = blockIdx.y * 64, n0 = blockIdx.x * TN;

    // issue cp.async stage of chunk at k0 into buffer b
    auto stage = [&](int b, int k0) {
        __nv_bfloat16* AsH = (__nv_bfloat16*)sraw + b * BUFE;
        __nv_bfloat16* AsL = AsH + AELE;
        __nv_bfloat16* BsH = AsL + AELE;
        __nv_bfloat16* BsL = BsH + BELE;
        #pragma unroll
        for (int g = t; g < 256; g += NT) {
            int r = g >> 2, c = (g & 3) * 8;
            size_t off = (size_t)(m0 + r) * lda + k0 + c;
            cpa16(&AsH[r * 40 + c], Ah + off);
            cpa16(&AsL[r * 40 + c], Al + off);
        }
        if (BT) {
            #pragma unroll
            for (int g = t; g < TN * 4; g += NT) {
                int r = g >> 2, c = (g & 3) * 8;
                size_t off = (size_t)(n0 + r) * ldb + k0 + c;
                cpa16(&BsH[r * 40 + c], Bh + off);
                cpa16(&BsL[r * 40 + c], Bl + off);
            }
        } else {
            const int TPR = TN / 8;
            #pragma unroll
            for (int g = t; g < TN * 4; g += NT) {
                int r = g / TPR, c = (g % TPR) * 8;
                size_t off = (size_t)(k0 + r) * ldb + n0 + c;
                cpa16(&BsH[r * BLD + c], Bh + off);
                cpa16(&BsL[r * BLD + c], Bl + off);
            }
        }
    };

    wmma::fragment<wmma::accumulator, 16, 16, 16, float> acc[2][2];
    #pragma unroll
    for (int i = 0; i < 2; i++)
        #pragma unroll
        for (int j = 0; j < 2; j++) wmma::fill_fragment(acc[i][j], 0.0f);

    int nch = K >> 5;
    stage(0, 0);
    CPA_COMMIT();
    CPA_WAIT0();
    __syncthreads();

    int buf = 0;
    for (int c = 0; c < nch; c++) {
        if (c + 1 < nch) { stage(buf ^ 1, (c + 1) * 32); CPA_COMMIT(); }

        __nv_bfloat16* AsH = (__nv_bfloat16*)sraw + buf * BUFE;
        __nv_bfloat16* AsL = AsH + AELE;
        __nv_bfloat16* BsH = AsL + AELE;
        __nv_bfloat16* BsL = BsH + BELE;
        #pragma unroll
        for (int hf = 0; hf < 2; hf++) {
            int ko = hf * 16;
            wmma::fragment<wmma::matrix_a, 16, 16, 16, __nv_bfloat16, wmma::row_major> aH[2], aL[2];
            #pragma unroll
            for (int i = 0; i < 2; i++) {
                wmma::load_matrix_sync(aH[i], &AsH[(wm * 32 + i * 16) * 40 + ko], 40);
                wmma::load_matrix_sync(aL[i], &AsL[(wm * 32 + i * 16) * 40 + ko], 40);
            }
            #pragma unroll
            for (int j = 0; j < 2; j++) {
                if (BT) {
                    wmma::fragment<wmma::matrix_b, 16, 16, 16, __nv_bfloat16, wmma::col_major> bH, bL;
                    wmma::load_matrix_sync(bH, &BsH[(wn * 32 + j * 16) * 40 + ko], 40);
                    wmma::load_matrix_sync(bL, &BsL[(wn * 32 + j * 16) * 40 + ko], 40);
                    #pragma unroll
                    for (int i = 0; i < 2; i++) {
                        wmma::mma_sync(acc[i][j], aH[i], bH, acc[i][j]);
                        wmma::mma_sync(acc[i][j], aH[i], bL, acc[i][j]);
                        wmma::mma_sync(acc[i][j], aL[i], bH, acc[i][j]);
                    }
                } else {
                    wmma::fragment<wmma::matrix_b, 16, 16, 16, __nv_bfloat16, wmma::row_major> bH, bL;
                    wmma::load_matrix_sync(bH, &BsH[ko * BLD + wn * 32 + j * 16], BLD);
                    wmma::load_matrix_sync(bL, &BsL[ko * BLD + wn * 32 + j * 16], BLD);
                    #pragma unroll
                    for (int i = 0; i < 2; i++) {
                        wmma::mma_sync(acc[i][j], aH[i], bH, acc[i][j]);
                        wmma::mma_sync(acc[i][j], aH[i], bL, acc[i][j]);
                        wmma::mma_sync(acc[i][j], aL[i], bH, acc[i][j]);
                    }
                }
            }
        }
        if (c + 1 < nch) {
            CPA_WAIT0();
            __syncthreads();
            buf ^= 1;
        }
    }

    float sc = scalep ? scalep[zo] : 1.0f;
    if (EPI == 0) {
        #pragma unroll
        for (int i = 0; i < 2; i++)
            #pragma unroll
            for (int j = 0; j < 2; j++) {
                #pragma unroll
                for (int e = 0; e < acc[i][j].num_elements; e++) acc[i][j].x[e] *= sc;
                wmma::store_matrix_sync(
                    &C[(size_t)(m0 + wm * 32 + i * 16) * ldc + n0 + wn * 32 + j * 16],
                    acc[i][j], ldc, wmma::mem_row_major);
            }
    } else {
        __syncthreads();    // all compute done before aliasing smem as fp32 scratch
        float* Cs = (float*)sraw + warp * (32 * 36);
        #pragma unroll
        for (int i = 0; i < 2; i++)
            #pragma unroll
            for (int j = 0; j < 2; j++)
                wmma::store_matrix_sync(Cs + (i * 16) * 36 + j * 16, acc[i][j], 36,
                                        wmma::mem_row_major);
        __syncwarp();
        int grow = m0 + wm * 32 + lane;
        int gcol = n0 + wn * 32;
        const float* src = Cs + lane * 36;
        float v[32];
        #pragma unroll
        for (int c2 = 0; c2 < 32; c2++) v[c2] = src[c2] * sc;
        if (EPI == 1) {
            #pragma unroll
            for (int q = 0; q < 8; q++)
                *(float4*)&C[(size_t)grow * ldc + gcol + q * 4] =
                    make_float4(v[q*4], v[q*4+1], v[q*4+2], v[q*4+3]);
        }
        #pragma unroll
        for (int q = 0; q < 4; q++) {
            union { __nv_bfloat16 b[8]; uint4 u; } ph, pl;
            #pragma unroll
            for (int e = 0; e < 8; e++) cvt_hl(v[q*8 + e], ph.b[e], pl.b[e]);
            *(uint4*)&Ch[(size_t)grow * ldc + gcol + q * 8] = ph.u;
            *(uint4*)&Cl[(size_t)grow * ldc + gcol + q * 8] = pl.u;
        }
    }
}

// ---------------- attention scores s_i/s_j ----------------
__global__ void k_sij(const float* __restrict__ attn) {
    int bn = blockIdx.x;                      // b*512 + n
    __shared__ float row[CF];
    for (int i = threadIdx.x; i < CF; i += 256) row[i] = g_hp[(size_t)bn * CF + i];
    __syncthreads();
    int w = threadIdx.x >> 5, lane = threadIdx.x & 31;
    int h = w >> 1, part = w & 1;             // 8 warps: 4 heads x {i,j}
    const float* av = attn + h * (2*CDH) + part * CDH;
    float s = 0.f;
    for (int d = lane; d < CDH; d += 32) s += row[h*CDH + d] * av[d];
#pragma unroll
    for (int o = 16; o; o >>= 1) s += __shfl_xor_sync(0xffffffffu, s, o);
    if (!lane) {
        int b = bn >> 9, n = bn & 511;
        float* dst = part ? g_sj : g_si;
        dst[(b*CH + h)*CN + n] = s;
    }
}

// ---------- leakyrelu + row softmax -> alpha (bf16 hi/lo out) ----------
__global__ void k_alpha() {
    int row = blockIdx.x;                     // (b*H + h)*512 + i
    int bh = row >> 9;
    float s_i = g_si[row];
    const float* sjr = g_sj + bh * CN;
    __shared__ float shm[8], shs[8];
    int t = threadIdx.x, lane = t & 31, w = t >> 5;
    float e0 = s_i + sjr[t];       e0 = e0 >= 0.f ? e0 : 0.2f * e0;
    float e1 = s_i + sjr[t + 256]; e1 = e1 >= 0.f ? e1 : 0.2f * e1;
    float m = fmaxf(e0, e1);
#pragma unroll
    for (int o = 16; o; o >>= 1) m = fmaxf(m, __shfl_xor_sync(0xffffffffu, m, o));
    if (!lane) shm[w] = m;
    __syncthreads();
    if (t < 32) {
        float v = (t < 8) ? shm[t] : -INFINITY;
#pragma unroll
        for (int o = 4; o; o >>= 1) v = fmaxf(v, __shfl_xor_sync(0xffffffffu, v, o));
        if (t == 0) shm[0] = v;
    }
    __syncthreads();
    float bm = shm[0];
    float x0 = expf(e0 - bm), x1 = expf(e1 - bm);
    float s = x0 + x1;
#pragma unroll
    for (int o = 16; o; o >>= 1) s += __shfl_xor_sync(0xffffffffu, s, o);
    if (!lane) shs[w] = s;
    __syncthreads();
    if (t < 32) {
        float v = (t < 8) ? shs[t] : 0.f;
#pragma unroll
        for (int o = 4; o; o >>= 1) v += __shfl_xor_sync(0xffffffffu, v, o);
        if (t == 0) shs[0] = v;
    }
    __syncthreads();
    float inv = 1.f / shs[0];
    __nv_bfloat16 h0, l0, h1, l1;
    cvt_hl(x0 * inv, h0, l0);
    cvt_hl(x1 * inv, h1, l1);
    size_t base = (size_t)row * CN + t;
    g_alh[base] = h0;       g_all[base] = l0;
    g_alh[base + 256] = h1; g_all[base + 256] = l1;
}

// ------- edge scores: sum_a relu(pi+pj+b1)*w2 + b2; 32x32 tile, 2x2 microtile -------
__global__ void __launch_bounds__(256) k_edge(
    const float* __restrict__ b1, const float* __restrict__ w2,
    const float* __restrict__ b2)
{
    int b = blockIdx.z;
    int i0 = blockIdx.y * 32, j0 = blockIdx.x * 32;
    __shared__ __align__(16) float Pi[32][132], Pj[32][132];
    __shared__ float B1s[128], W2s[128];
    const float* pi = g_pij;
    const float* pj = g_pij + (size_t)CB*CN*CAH;
    int t = threadIdx.x;
    int ti = t >> 4, tj = t & 15;
    float acc[2][2] = {};
    for (int a0 = 0; a0 < CAH; a0 += 128) {
        if (t < 128) { B1s[t] = b1[a0 + t]; W2s[t] = w2[a0 + t]; }
        #pragma unroll
        for (int c = 0; c < 4; c++) {
            int q = t + 256 * c;            // 0..1023 over 32 rows x 32 float4
            int r = q >> 5, nc = (q & 31) * 4;
            *(float4*)&Pi[r][nc] = *(const float4*)&pi[(size_t)(b*CN + i0 + r) * CAH + a0 + nc];
            *(float4*)&Pj[r][nc] = *(const float4*)&pj[(size_t)(b*CN + j0 + r) * CAH + a0 + nc];
        }
        __syncthreads();
        #pragma unroll 8
        for (int a = 0; a < 128; a += 4) {
            float4 u0 = *(const float4*)&Pi[2*ti][a];
            float4 u1 = *(const float4*)&Pi[2*ti + 1][a];
            float4 v0 = *(const float4*)&Pj[2*tj][a];
            float4 v1 = *(const float4*)&Pj[2*tj + 1][a];
            float4 bb = *(const float4*)&B1s[a];
            float4 ww = *(const float4*)&W2s[a];
            #define EDGE_E(ue, ve, be, we) { \
                float p00 = ue.x + ve.x + be; float p01 = ue.x + ve.y + be; \
                float p10 = ue.y + ve.x + be; float p11 = ue.y + ve.y + be; \
                acc[0][0] += fmaxf(p00, 0.f) * we; \
                acc[0][1] += fmaxf(p01, 0.f) * we; \
                acc[1][0] += fmaxf(p10, 0.f) * we; \
                acc[1][1] += fmaxf(p11, 0.f) * we; }
            { float2 uu = make_float2(u0.x, u1.x), vv = make_float2(v0.x, v1.x); EDGE_E(uu, vv, bb.x, ww.x); }
            { float2 uu = make_float2(u0.y, u1.y), vv = make_float2(v0.y, v1.y); EDGE_E(uu, vv, bb.y, ww.y); }
            { float2 uu = make_float2(u0.z, u1.z), vv = make_float2(v0.z, v1.z); EDGE_E(uu, vv, bb.z, ww.z); }
            { float2 uu = make_float2(u0.w, u1.w), vv = make_float2(v0.w, v1.w); EDGE_E(uu, vv, bb.w, ww.w); }
            #undef EDGE_E
        }
        __syncthreads();
    }
    float bias = b2[0];
    #pragma unroll
    for (int r = 0; r < 2; r++) {
        float2 o = make_float2(acc[r][0] + bias, acc[r][1] + bias);
        *(float2*)&g_edge[(size_t)b * CNN + (i0 + 2*ti + r) * CN + j0 + 2*tj] = o;
    }
}

// ---------------- radix select pass A: hi-16 histogram + max ----------------
__global__ void k_passA() {
    int b = blockIdx.y;
    const float* e = g_edge + (size_t)b * CNN;
    unsigned lm = 0;
    for (int idx = blockIdx.x * blockDim.x + threadIdx.x; idx < CNN;
         idx += gridDim.x * blockDim.x) {
        unsigned key = key_of(e[idx]);
        atomicAdd(&g_hist[(b << 16) + (key >> 16)], 1u);
        lm = max(lm, key);
    }
    __shared__ unsigned sh[8];
    int t = threadIdx.x, lane = t & 31, w = t >> 5;
#pragma unroll
    for (int o = 16; o; o >>= 1) lm = max(lm, __shfl_xor_sync(0xffffffffu, lm, o));
    if (!lane) sh[w] = lm;
    __syncthreads();
    if (t == 0) {
        unsigned v = sh[0];
        for (int q = 1; q < 8; q++) v = max(v, sh[q]);
        atomicMax(&g_maxkey[b], v);
    }
}

__global__ void k_scan1() {
    int b = blockIdx.x;
    unsigned* h = g_hist + (b << 16);
    __shared__ unsigned part[1024];
    int t = threadIdx.x;
    unsigned s = 0;
    for (int i = 0; i < 64; i++) s += h[t*64 + i];
    part[t] = s;
    __syncthreads();
    for (int off = 1; off < 1024; off <<= 1) {
        unsigned v = (t >= off) ? part[t - off] : 0u;
        __syncthreads();
        if (t >= off) part[t] += v;
        __syncthreads();
    }
    unsigned r = RSEL;
    unsigned pre = t ? part[t-1] : 0u;
    if (pre <= r && r < part[t]) {
        unsigned rem = r - pre;
        for (int i = 0; i < 64; i++) {
            unsigned c = h[t*64 + i];
            if (rem < c) { g_selhi[b] = (unsigned)(t*64 + i); g_rank2[b] = rem; break; }
            rem -= c;
        }
    }
    __syncthreads();
    for (int i = t; i < 65536; i += 1024) h[i] = 0;   // re-zero for pass B
}

__global__ void k_passB() {
    int b = blockIdx.y;
    const float* e = g_edge + (size_t)b * CNN;
    unsigned hi = g_selhi[b];
    for (int idx = blockIdx.x * blockDim.x + threadIdx.x; idx < CNN;
         idx += gridDim.x * blockDim.x) {
        unsigned key = key_of(e[idx]);
        if ((key >> 16) == hi) atomicAdd(&g_hist[(b << 16) + (key & 0xFFFFu)], 1u);
    }
}

__global__ void k_scan2() {
    int b = blockIdx.x;
    unsigned* h = g_hist + (b << 16);
    __shared__ unsigned part[1024];
    int t = threadIdx.x;
    unsigned s = 0;
    for (int i = 0; i < 64; i++) s += h[t*64 + i];
    part[t] = s;
    __syncthreads();
    for (int off = 1; off < 1024; off <<= 1) {
        unsigned v = (t >= off) ? part[t - off] : 0u;
        __syncthreads();
        if (t >= off) part[t] += v;
        __syncthreads();
    }
    unsigned r = g_rank2[b];
    unsigned pre = t ? part[t-1] : 0u;
    if (pre <= r && r < part[t]) {
        unsigned rem = r - pre;
        for (int i = 0; i < 64; i++) {
            unsigned c = h[t*64 + i];
            if (rem < c) {
                unsigned key = (g_selhi[b] << 16) | (unsigned)(t*64 + i);
                g_thr[b] = key_inv(key);
                break;
            }
            rem -= c;
        }
    }
}

// --------- masked exp (unnormalized) -> bf16 hi/lo cm + partial sums ---------
__global__ void k_maskexp() {
    int b = blockIdx.y;
    const float* e = g_edge + (size_t)b * CNN;
    __nv_bfloat16* cmh = g_cmh + (size_t)b * CNN;
    __nv_bfloat16* cml = g_cml + (size_t)b * CNN;
    float zmax = key_inv(g_maxkey[b]);
    float th = g_thr[b];
    float ls = 0.f;
    for (int idx = blockIdx.x * blockDim.x + threadIdx.x; idx < CNN;
         idx += gridDim.x * blockDim.x) {
        float z = e[idx];
        float v = 0.f;
        if (z >= th) v = expf((z - zmax) * 2.0f);   // 1/TEMP = 2
        __nv_bfloat16 h, l;
        cvt_hl(v, h, l);
        cmh[idx] = h; cml[idx] = l;
        ls += v;
    }
    __shared__ float sh[8];
    int t = threadIdx.x, lane = t & 31, w = t >> 5;
#pragma unroll
    for (int o = 16; o; o >>= 1) ls += __shfl_xor_sync(0xffffffffu, ls, o);
    if (!lane) sh[w] = ls;
    __syncthreads();
    if (t == 0) {
        float v = sh[0];
        for (int q = 1; q < 8; q++) v += sh[q];
        atomicAdd(&g_msum[b], v);
    }
}

// invert sums once -> scale factors consumed by gemm epilogues
__global__ void k_inv() {
    int b = threadIdx.x;
    if (b < CB) g_msum[b] = 1.f / g_msum[b];
}

// ---------------- batch norm ----------------
__global__ void k_bnstats(const float* __restrict__ h, int C, float* sum, float* sq) {
    int row0 = blockIdx.x * 32;
    int c = threadIdx.x;
    float s = 0.f, q = 0.f;
    for (int r = 0; r < 32; r++) {
        float v = h[(size_t)(row0 + r) * C + c];
        s += v; q += v * v;
    }
    atomicAdd(&sum[c], s);
    atomicAdd(&sq[c], q);
}

// sum 4 K-split partials of h4, write h4, accumulate BN2 stats
__global__ void k_bnstats4() {
    int row0 = blockIdx.x * 32;
    int c = threadIdx.x;    // 128
    const long long S = (long long)CB * CN * COUT;
    float s = 0.f, q = 0.f;
    for (int r = 0; r < 32; r++) {
        size_t idx = (size_t)(row0 + r) * COUT + c;
        float v = g_h4p[idx] + g_h4p[idx + S] + g_h4p[idx + 2*S] + g_h4p[idx + 3*S];
        g_h4[idx] = v;
        s += v; q += v * v;
    }
    atomicAdd(&g_bs2[c], s);
    atomicAdd(&g_bq2[c], q);
}

__global__ void k_bnfinal(const float* sum, const float* sq,
                          const float* __restrict__ g, const float* __restrict__ bt,
                          float* scale, float* shift) {
    int c = threadIdx.x;
    const float invn = 1.f / (CB * CN);
    float mean = sum[c] * invn;
    float var = sq[c] * invn - mean * mean;
    float sc = g[c] * rsqrtf(var + 1e-5f);
    scale[c] = sc;
    shift[c] = bt[c] - mean * sc;
}

// BN1 apply + relu on h2 -> bf16 hi/lo
__global__ void k_bnrelu2() {
    const int total = CB * CN * CHID;
    for (int idx = blockIdx.x * blockDim.x + threadIdx.x; idx < total;
         idx += gridDim.x * blockDim.x) {
        int c = idx & (CHID - 1);
        float v = fmaxf(g_h2[idx] * g_sc1[c] + g_sh1[c], 0.f);
        __nv_bfloat16 h, l;
        cvt_hl(v, h, l);
        g_h2h[idx] = h; g_h2l[idx] = l;
    }
}

// ---------------- BN2-apply + relu + mean over N ----------------
__global__ void k_feat() {
    int b = blockIdx.x;
    int c = threadIdx.x;   // 128
    float sc = g_sc2[c], sh = g_sh2[c];
    float s = 0.f;
    for (int n = 0; n < CN; n++) {
        float v = g_h4[(size_t)(b*CN + n) * COUT + c] * sc + sh;
        s += fmaxf(v, 0.f);
    }
    g_feat[b*COUT + c] = s * (1.f / CN);
}

// ---------------- classifier ----------------
__global__ void k_cls(const float* __restrict__ cw, const float* __restrict__ cb,
                      float* __restrict__ out) {
    int w = threadIdx.x >> 5, lane = threadIdx.x & 31;
    if (w < CB * CNCLS) {
        int b = w / CNCLS, c = w % CNCLS;
        float s = 0.f;
        for (int f = lane; f < COUT; f += 32)
            s += g_feat[b*COUT + f] * cw[c*COUT + f];
#pragma unroll
        for (int o = 16; o; o >>= 1) s += __shfl_xor_sync(0xffffffffu, s, o);
        if (!lane) out[b*CNCLS + c] = s + cb[c];
    }
}

// ---------------- host launch ----------------
extern "C" void kernel_launch(void* const* d_in, const int* in_sizes, int n_in,
                              void* d_out, int out_size) {
    (void)in_sizes; (void)n_in; (void)out_size;
    const float* x    = (const float*)d_in[0];
    const float* Wg   = (const float*)d_in[1];
    const float* attn = (const float*)d_in[2];
    const float* W1   = (const float*)d_in[3];
    const float* b1   = (const float*)d_in[4];
    const float* w2   = (const float*)d_in[5];
    const float* b2   = (const float*)d_in[6];
    const float* gc1w = (const float*)d_in[7];
    /* gc1_b (8) cancels in BN */
    const float* bn1g = (const float*)d_in[9];
    const float* bn1b = (const float*)d_in[10];
    const float* gc2w = (const float*)d_in[11];
    /* gc2_b (12) cancels in BN */
    const float* bn2g = (const float*)d_in[13];
    const float* bn2b = (const float*)d_in[14];
    const float* clsw = (const float*)d_in[15];
    const float* clsb = (const float*)d_in[16];
    float* out = (float*)d_out;

    float *hp, *pij, *h2, *h4p;
    float *bs1, *bq1, *sc1, *sh1, *bs2, *bq2, *sc2, *sh2, *msum;
    cudaGetSymbolAddress((void**)&hp,  g_hp);
    cudaGetSymbolAddress((void**)&pij, g_pij);
    cudaGetSymbolAddress((void**)&h2,  g_h2);
    cudaGetSymbolAddress((void**)&h4p, g_h4p);
    cudaGetSymbolAddress((void**)&msum, g_msum);
    cudaGetSymbolAddress((void**)&bs1, g_bs1);
    cudaGetSymbolAddress((void**)&bq1, g_bq1);
    cudaGetSymbolAddress((void**)&sc1, g_sc1);
    cudaGetSymbolAddress((void**)&sh1, g_sh1);
    cudaGetSymbolAddress((void**)&bs2, g_bs2);
    cudaGetSymbolAddress((void**)&bq2, g_bq2);
    cudaGetSymbolAddress((void**)&sc2, g_sc2);
    cudaGetSymbolAddress((void**)&sh2, g_sh2);

    __nv_bfloat16 *xh,*xl,*Wgh,*Wgl,*hph,*hpl,*alh,*all,*nfh,*nfl,*W1h,*W1l;
    __nv_bfloat16 *cmh,*cml,*h1h,*h1l,*gc1h,*gc1l,*h2h,*h2l,*h3h,*h3l,*gc2h,*gc2l;
    cudaGetSymbolAddress((void**)&xh,  g_xh);   cudaGetSymbolAddress((void**)&xl,  g_xl);
    cudaGetSymbolAddress((void**)&Wgh, g_Wgh);  cudaGetSymbolAddress((void**)&Wgl, g_Wgl);
    cudaGetSymbolAddress((void**)&hph, g_hph);  cudaGetSymbolAddress((void**)&hpl, g_hpl);
    cudaGetSymbolAddress((void**)&alh, g_alh);  cudaGetSymbolAddress((void**)&all, g_all);
    cudaGetSymbolAddress((void**)&nfh, g_nfh);  cudaGetSymbolAddress((void**)&nfl, g_nfl);
    cudaGetSymbolAddress((void**)&W1h, g_W1h);  cudaGetSymbolAddress((void**)&W1l, g_W1l);
    cudaGetSymbolAddress((void**)&cmh, g_cmh);  cudaGetSymbolAddress((void**)&cml, g_cml);
    cudaGetSymbolAddress((void**)&h1h, g_h1h);  cudaGetSymbolAddress((void**)&h1l, g_h1l);
    cudaGetSymbolAddress((void**)&gc1h,g_gc1h); cudaGetSymbolAddress((void**)&gc1l,g_gc1l);
    cudaGetSymbolAddress((void**)&h2h, g_h2h);  cudaGetSymbolAddress((void**)&h2l, g_h2l);
    cudaGetSymbolAddress((void**)&h3h, g_h3h);  cudaGetSymbolAddress((void**)&h3l, g_h3l);
    cudaGetSymbolAddress((void**)&gc2h,g_gc2h); cudaGetSymbolAddress((void**)&gc2l,g_gc2l);

    // dynamic smem sizes (double-buffered staging; epilogue scratch is smaller)
    const int SM128T = 2 * (2*64*40 + 2*128*40) * 2;     // 61440
    const int SM128F = 2 * (2*64*40 + 2*32*136) * 2;     // 55296
    const int SM64T  = 2 * (2*64*40 + 2*64*40) * 2;      // 40960
    const int SM64F  = 2 * (2*64*40 + 2*32*72) * 2;      // 38912
    cudaFuncSetAttribute(gemm_w<128, true, 1>,  cudaFuncAttributeMaxDynamicSharedMemorySize, SM128T);
    cudaFuncSetAttribute(gemm_w<128, false, 2>, cudaFuncAttributeMaxDynamicSharedMemorySize, SM128F);
    cudaFuncSetAttribute(gemm_w<64, true, 0>,   cudaFuncAttributeMaxDynamicSharedMemorySize, SM64T);
    cudaFuncSetAttribute(gemm_w<64, false, 2>,  cudaFuncAttributeMaxDynamicSharedMemorySize, SM64F);

    k_zero<<<512, 256>>>();

    // fused one-shot conversions of all 5 external inputs
    k_cvt5<<<784, 256>>>(x, Wg, W1, gc1w, gc2w);

    // hp = x @ Wg^T  (fp32 out for k_sij + bf16 hi/lo for nf gemm)
    gemm_w<128, true, 1><<<dim3(CF/128, (CB*CN)/64, 1), 256, SM128T>>>(
        xh, xl, Wgh, Wgl, hp, hph, hpl, CF, CF, CF, CF, 1, 0,0, 0,0, 0,0, (const float*)0);

    k_sij<<<CB*CN, 256>>>(attn);
    k_alpha<<<CB*CH*CN, 256>>>();

    // node_feats: per (b,h)  alpha(512x512) @ hp_bh -> nf (bf16 hi/lo only)
    gemm_w<128, false, 2><<<dim3(CDH/128, CN/64, CB*CH), 256, SM128F>>>(
        alh, all, hph, hpl, (float*)0, nfh, nfl, CN, CN, CF, CF,
        CH, (long long)CH*CNN, (long long)CNN,
        (long long)CN*CF, (long long)CDH,
        (long long)CN*CF, (long long)CDH, (const float*)0);

    // pi / pj = nf @ W1i^T / W1j^T   (fp32 only)
    gemm_w<64, true, 0><<<dim3(CAH/64, (CB*CN)/64, 2), 128, SM64T>>>(
        nfh, nfl, W1h, W1l, pij, (__nv_bfloat16*)0, (__nv_bfloat16*)0, CF, CF, 2*CF, CAH,
        1, 0, 0, (long long)CF, 0, (long long)CB*CN*CAH, 0, (const float*)0);

    k_edge<<<dim3(CN/32, CN/32, CB), 256>>>(b1, w2, b2);

    // exact top-k threshold via 2-pass radix select, then masked exp (norm folded into gemms)
    k_passA<<<dim3(128, CB), 256>>>();
    k_scan1<<<CB, 1024>>>();
    k_passB<<<dim3(128, CB), 256>>>();
    k_scan2<<<CB, 1024>>>();
    k_maskexp<<<dim3(128, CB), 256>>>();
    k_inv<<<1, 32>>>();

    // h1 = (cm/Z) @ nf  (bf16 hi/lo only), scale folded in
    gemm_w<128, false, 2><<<dim3(CF/128, CN/64, CB), 256, SM128F>>>(
        cmh, cml, nfh, nfl, (float*)0, h1h, h1l, CN, CN, CF, CF,
        1, (long long)CNN, 0, (long long)CN*CF, 0, (long long)CN*CF, 0, msum);

    // h2 = h1 @ gc1_w^T  (fp32 for bnstats)   [gc1_b cancels in BN]
    gemm_w<64, true, 0><<<dim3(CHID/64, (CB*CN)/64, 1), 128, SM64T>>>(
        h1h, h1l, gc1h, gc1l, h2, (__nv_bfloat16*)0, (__nv_bfloat16*)0, CF, CF, CF, CHID,
        1, 0,0, 0,0, 0,0, (const float*)0);

    k_bnstats<<<(CB*CN)/32, CHID>>>(h2, CHID, bs1, bq1);
    k_bnfinal<<<1, CHID>>>(bs1, bq1, bn1g, bn1b, sc1, sh1);
    k_bnrelu2<<<256, 256>>>();

    // h3 = (cm/Z) @ h2  (bf16 hi/lo only), scale folded in
    gemm_w<64, false, 2><<<dim3(CHID/64, CN/64, CB), 128, SM64F>>>(
        cmh, cml, h2h, h2l, (float*)0, h3h, h3l, CN, CN, CHID, CHID,
        1, (long long)CNN, 0, (long long)CN*CHID, 0, (long long)CN*CHID, 0, msum);

    // h4 = h3 @ gc2_w^T  (K-split x4 partials, fp32)
    gemm_w<64, true, 0><<<dim3(COUT/64, (CB*CN)/64, 4), 128, SM64T>>>(
        h3h, h3l, gc2h, gc2l, h4p, (__nv_bfloat16*)0, (__nv_bfloat16*)0, CHID/4, CHID, CHID, COUT,
        1, 128, 0, 128, 0, (long long)CB*CN*COUT, 0, (const float*)0);

    k_bnstats4<<<(CB*CN)/32, COUT>>>();
    k_bnfinal<<<1, COUT>>>(bs2, bq2, bn2g, bn2b, sc2, sh2);

    k_feat<<<CB, COUT>>>();
    k_cls<<<1, 640>>>(clsw, clsb, out);
}

// round 15
// speedup vs baseline: 1.6630x; 1.0052x over previous
#include <cuda_runtime.h>
#include <cuda_bf16.h>
#include <mma.h>
#include <math.h>

using namespace nvcuda;

#define CB 2
#define CN 512
#define CF 1024
#define CH 4
#define CDH 256
#define CAH 256
#define CHID 512
#define COUT 128
#define CNCLS 10
#define CNN (CN*CN)
#define RSEL 52429u   /* NN - int(0.8*NN) = 262144 - 209715 */

// ---------------- scratch (static device memory; no allocations) ----------------
__device__ float g_si[CB*CH*CN];
__device__ float g_sj[CB*CH*CN];
__device__ float g_pij[2*CB*CN*CAH];
__device__ float g_edge[CB*CNN];
__device__ float g_h2[CB*CN*CHID];
__device__ float g_h4[CB*CN*COUT];
__device__ float g_h4p[4*CB*CN*COUT];
__device__ float g_feat[CB*COUT];
__device__ unsigned g_hist[CB*65536];
__device__ unsigned g_selhi[CB];
__device__ unsigned g_rank2[CB];
__device__ unsigned g_maxkey[CB];
__device__ float g_thr[CB];
__device__ float g_msum[CB];
__device__ float g_bs1[CHID], g_bq1[CHID], g_sc1[CHID], g_sh1[CHID];
__device__ float g_bs2[COUT], g_bq2[COUT], g_sc2[COUT], g_sh2[COUT];

// bf16 hi/lo operand mirrors
__device__ __nv_bfloat16 g_xh[CB*CN*CF],  g_xl[CB*CN*CF];
__device__ __nv_bfloat16 g_Wgh[CF*CF],    g_Wgl[CF*CF];
__device__ __nv_bfloat16 g_hph[CB*CN*CF], g_hpl[CB*CN*CF];
__device__ __nv_bfloat16 g_alh[CB*CH*CNN],g_all[CB*CH*CNN];
__device__ __nv_bfloat16 g_nfh[CB*CN*CF], g_nfl[CB*CN*CF];
__device__ __nv_bfloat16 g_W1h[CAH*2*CF], g_W1l[CAH*2*CF];
__device__ __nv_bfloat16 g_cmh[CB*CNN],   g_cml[CB*CNN];
__device__ __nv_bfloat16 g_h1h[CB*CN*CF], g_h1l[CB*CN*CF];
__device__ __nv_bfloat16 g_gc1h[CHID*CF], g_gc1l[CHID*CF];
__device__ __nv_bfloat16 g_h2h[CB*CN*CHID], g_h2l[CB*CN*CHID];
__device__ __nv_bfloat16 g_h3h[CB*CN*CHID], g_h3l[CB*CN*CHID];
__device__ __nv_bfloat16 g_gc2h[COUT*CHID], g_gc2l[COUT*CHID];

// ---------------- helpers ----------------
__device__ __forceinline__ unsigned key_of(float x) {
    unsigned u = __float_as_uint(x);
    return (u & 0x80000000u) ? ~u : (u | 0x80000000u);
}
__device__ __forceinline__ float key_inv(unsigned key) {
    unsigned u = (key & 0x80000000u) ? (key ^ 0x80000000u) : ~key;
    return __uint_as_float(u);
}
__device__ __forceinline__ void cvt_hl(float v, __nv_bfloat16& h, __nv_bfloat16& l) {
    h = __float2bfloat16(v);
    l = __float2bfloat16(v - __bfloat162float(h));
}
__device__ __forceinline__ void cpa16(void* smem, const void* gmem) {
    unsigned saddr = (unsigned)__cvta_generic_to_shared(smem);
    asm volatile("cp.async.ca.shared.global [%0], [%1], 16;\n" :: "r"(saddr), "l"(gmem));
}
#define CPA_COMMIT() asm volatile("cp.async.commit_group;\n" ::: "memory")
#define CPA_WAIT0()  asm volatile("cp.async.wait_group 0;\n" ::: "memory")

// ---------------- zero scratch (must run every launch; graph replays) ----------------
__global__ void k_zero() {
    int i = blockIdx.x * 256 + threadIdx.x;       // grid = 512 blocks -> 131072 threads
    g_hist[i] = 0;
    if (i < CHID) { g_bs1[i] = 0.f; g_bq1[i] = 0.f; }
    if (i < COUT) { g_bs2[i] = 0.f; g_bq2[i] = 0.f; }
    if (i < CB*CH*CN) { g_si[i] = 0.f; g_sj[i] = 0.f; }
    if (i < CB)   { g_msum[i] = 0.f; g_maxkey[i] = 0u; }
}

// ------ fused one-shot input conversions: 5 tensors, block-range dispatch ------
// elements/block = 4096. x:256 | Wg:256 | W1:128 | gc1:128 | gc2:16  -> 784 blocks
__global__ void k_cvt5(const float* __restrict__ x,   const float* __restrict__ Wg,
                       const float* __restrict__ W1,  const float* __restrict__ gc1,
                       const float* __restrict__ gc2) {
    int b = blockIdx.x;
    const float* src; __nv_bfloat16 *ho, *lo; int blk;
    if (b < 256)       { src = x;   ho = g_xh;   lo = g_xl;   blk = b; }
    else if (b < 512)  { src = Wg;  ho = g_Wgh;  lo = g_Wgl;  blk = b - 256; }
    else if (b < 640)  { src = W1;  ho = g_W1h;  lo = g_W1l;  blk = b - 512; }
    else if (b < 768)  { src = gc1; ho = g_gc1h; lo = g_gc1l; blk = b - 640; }
    else               { src = gc2; ho = g_gc2h; lo = g_gc2l; blk = b - 768; }
    int base = blk * 4096 + threadIdx.x * 16;
    float4 v[4];
    #pragma unroll
    for (int q = 0; q < 4; q++) v[q] = *(const float4*)(src + base + q * 4);
    #pragma unroll
    for (int q = 0; q < 4; q++) {
        float vv[4] = {v[q].x, v[q].y, v[q].z, v[q].w};
        union { __nv_bfloat16 bb[4]; uint2 u; } uh, ul;
        #pragma unroll
        for (int e = 0; e < 4; e++) cvt_hl(vv[e], uh.bb[e], ul.bb[e]);
        *(uint2*)(ho + base + q * 4) = uh.u;
        *(uint2*)(lo + base + q * 4) = ul.u;
    }
}

// ====== split-bf16 tensor-core GEMM, cp.async double-buffered, K-chunk 32 ======
// TN=128: 256 thr, 8 warps (2x4).  TN=64: 128 thr, 4 warps (2x2).  Tile M64 x TN.
// C = scale * (Ah+Al) @ (Bh+Bl)'   (3 of 4 cross terms, fp32 accumulate)
// EPI: 0 = fp32 C (direct frag store)
//      1 = fp32 C + bf16 hi/lo Ch/Cl
//      2 = bf16 hi/lo only (+optional fused s_i/s_j via attnp: rows=b*512+n, cols=head dims)
//      3 = fp32 C + per-column stats atomics into bsum/bsq
// scalep: if non-null, sc = 1/scalep[zo]  (raw sums; reciprocal folded here)
template<int TN, bool BT, int EPI>
__global__ void __launch_bounds__(TN == 128 ? 256 : 128) gemm_w(
    const __nv_bfloat16* __restrict__ Ah, const __nv_bfloat16* __restrict__ Al,
    const __nv_bfloat16* __restrict__ Bh, const __nv_bfloat16* __restrict__ Bl,
    float* __restrict__ C, __nv_bfloat16* __restrict__ Ch, __nv_bfloat16* __restrict__ Cl,
    int K, int lda, int ldb, int ldc,
    int bdiv, long long sAo, long long sAi, long long sBo, long long sBi,
    long long sCo, long long sCi, const float* __restrict__ scalep,
    const float* __restrict__ attnp, float* __restrict__ bsum, float* __restrict__ bsq)
{
    const int NT = (TN == 128) ? 256 : 128;
    extern __shared__ __align__(16) char sraw[];
    constexpr int BROWS = BT ? TN : 32;
    constexpr int BLD   = BT ? 40 : TN + 8;
    constexpr int AELE  = 64 * 40;                 // elements per A plane
    constexpr int BELE  = BROWS * BLD;
    constexpr int BUFE  = 2 * AELE + 2 * BELE;     // elements per buffer (H+L planes)

    int z = blockIdx.z;
    int zo = z / bdiv, zi = z - zo * bdiv;
    long long aoff = zo * sAo + zi * sAi;
    long long boff = zo * sBo + zi * sBi;
    long long coff = zo * sCo + zi * sCi;
    Ah += aoff;  Al += aoff;
    Bh += boff;  Bl += boff;
    C  += coff;
    if (EPI == 1 || EPI == 2) { Ch += coff; Cl += coff; }

    int t = threadIdx.x;
    int warp = t >> 5, lane = t & 31;
    int wm = (TN == 128) ? (warp >> 2) : (warp >> 1);
    int wn = (TN == 128) ? (warp & 3) : (warp & 1);
    int m0 = blockIdx.y * 64, n0 = blockIdx.x * TN;

    // issue cp.async stage of chunk at k0 into buffer b
    auto stage = [&](int b, int k0) {
        __nv_bfloat16* AsH = (__nv_bfloat16*)sraw + b * BUFE;
        __nv_bfloat16* AsL = AsH + AELE;
        __nv_bfloat16* BsH = AsL + AELE;
        __nv_bfloat16* BsL = BsH + BELE;
        #pragma unroll
        for (int g = t; g < 256; g += NT) {
            int r = g >> 2, c = (g & 3) * 8;
            size_t off = (size_t)(m0 + r) * lda + k0 + c;
            cpa16(&AsH[r * 40 + c], Ah + off);
            cpa16(&AsL[r * 40 + c], Al + off);
        }
        if (BT) {
            #pragma unroll
            for (int g = t; g < TN * 4; g += NT) {
                int r = g >> 2, c = (g & 3) * 8;
                size_t off = (size_t)(n0 + r) * ldb + k0 + c;
                cpa16(&BsH[r * 40 + c], Bh + off);
                cpa16(&BsL[r * 40 + c], Bl + off);
            }
        } else {
            const int TPR = TN / 8;
            #pragma unroll
            for (int g = t; g < TN * 4; g += NT) {
                int r = g / TPR, c = (g % TPR) * 8;
                size_t off = (size_t)(k0 + r) * ldb + n0 + c;
                cpa16(&BsH[r * BLD + c], Bh + off);
                cpa16(&BsL[r * BLD + c], Bl + off);
            }
        }
    };

    wmma::fragment<wmma::accumulator, 16, 16, 16, float> acc[2][2];
    #pragma unroll
    for (int i = 0; i < 2; i++)
        #pragma unroll
        for (int j = 0; j < 2; j++) wmma::fill_fragment(acc[i][j], 0.0f);

    int nch = K >> 5;
    stage(0, 0);
    CPA_COMMIT();
    CPA_WAIT0();
    __syncthreads();

    int buf = 0;
    for (int c = 0; c < nch; c++) {
        if (c + 1 < nch) { stage(buf ^ 1, (c + 1) * 32); CPA_COMMIT(); }

        __nv_bfloat16* AsH = (__nv_bfloat16*)sraw + buf * BUFE;
        __nv_bfloat16* AsL = AsH + AELE;
        __nv_bfloat16* BsH = AsL + AELE;
        __nv_bfloat16* BsL = BsH + BELE;
        #pragma unroll
        for (int hf = 0; hf < 2; hf++) {
            int ko = hf * 16;
            wmma::fragment<wmma::matrix_a, 16, 16, 16, __nv_bfloat16, wmma::row_major> aH[2], aL[2];
            #pragma unroll
            for (int i = 0; i < 2; i++) {
                wmma::load_matrix_sync(aH[i], &AsH[(wm * 32 + i * 16) * 40 + ko], 40);
                wmma::load_matrix_sync(aL[i], &AsL[(wm * 32 + i * 16) * 40 + ko], 40);
            }
            #pragma unroll
            for (int j = 0; j < 2; j++) {
                if (BT) {
                    wmma::fragment<wmma::matrix_b, 16, 16, 16, __nv_bfloat16, wmma::col_major> bH, bL;
                    wmma::load_matrix_sync(bH, &BsH[(wn * 32 + j * 16) * 40 + ko], 40);
                    wmma::load_matrix_sync(bL, &BsL[(wn * 32 + j * 16) * 40 + ko], 40);
                    #pragma unroll
                    for (int i = 0; i < 2; i++) {
                        wmma::mma_sync(acc[i][j], aH[i], bH, acc[i][j]);
                        wmma::mma_sync(acc[i][j], aH[i], bL, acc[i][j]);
                        wmma::mma_sync(acc[i][j], aL[i], bH, acc[i][j]);
                    }
                } else {
                    wmma::fragment<wmma::matrix_b, 16, 16, 16, __nv_bfloat16, wmma::row_major> bH, bL;
                    wmma::load_matrix_sync(bH, &BsH[ko * BLD + wn * 32 + j * 16], BLD);
                    wmma::load_matrix_sync(bL, &BsL[ko * BLD + wn * 32 + j * 16], BLD);
                    #pragma unroll
                    for (int i = 0; i < 2; i++) {
                        wmma::mma_sync(acc[i][j], aH[i], bH, acc[i][j]);
                        wmma::mma_sync(acc[i][j], aH[i], bL, acc[i][j]);
                        wmma::mma_sync(acc[i][j], aL[i], bH, acc[i][j]);
                    }
                }
            }
        }
        if (c + 1 < nch) {
            CPA_WAIT0();
            __syncthreads();
            buf ^= 1;
        }
    }

    float sc = scalep ? (1.0f / scalep[zo]) : 1.0f;
    if (EPI == 0) {
        #pragma unroll
        for (int i = 0; i < 2; i++)
            #pragma unroll
            for (int j = 0; j < 2; j++) {
                #pragma unroll
                for (int e = 0; e < acc[i][j].num_elements; e++) acc[i][j].x[e] *= sc;
                wmma::store_matrix_sync(
                    &C[(size_t)(m0 + wm * 32 + i * 16) * ldc + n0 + wn * 32 + j * 16],
                    acc[i][j], ldc, wmma::mem_row_major);
            }
    } else {
        __syncthreads();    // all compute done before aliasing smem as fp32 scratch
        float* Cs = (float*)sraw + warp * (32 * 36);
        #pragma unroll
        for (int i = 0; i < 2; i++)
            #pragma unroll
            for (int j = 0; j < 2; j++)
                wmma::store_matrix_sync(Cs + (i * 16) * 36 + j * 16, acc[i][j], 36,
                                        wmma::mem_row_major);
        __syncwarp();
        int grow = m0 + wm * 32 + lane;
        int gcol = n0 + wn * 32;
        const float* src = Cs + lane * 36;
        float v[32];
        #pragma unroll
        for (int c2 = 0; c2 < 32; c2++) v[c2] = src[c2] * sc;
        if (EPI == 1 || EPI == 3) {
            #pragma unroll
            for (int q = 0; q < 8; q++)
                *(float4*)&C[(size_t)grow * ldc + gcol + q * 4] =
                    make_float4(v[q*4], v[q*4+1], v[q*4+2], v[q*4+3]);
        }
        if (EPI == 1 || EPI == 2) {
            #pragma unroll
            for (int q = 0; q < 4; q++) {
                union { __nv_bfloat16 b[8]; uint4 u; } ph, pl;
                #pragma unroll
                for (int e = 0; e < 8; e++) cvt_hl(v[q*8 + e], ph.b[e], pl.b[e]);
                *(uint4*)&Ch[(size_t)grow * ldc + gcol + q * 8] = ph.u;
                *(uint4*)&Cl[(size_t)grow * ldc + gcol + q * 8] = pl.u;
            }
        }
        if (EPI == 2 && attnp) {
            // fused s_i/s_j partials: rows = b*512+n, cols = head dims (head = gcol>>8)
            int b = grow >> 9, n = grow & 511;
            int h = gcol >> 8, cb = gcol & 255;
            const float* ai = attnp + h * (2*CDH) + cb;
            const float* aj = ai + CDH;
            float si = 0.f, sj = 0.f;
            #pragma unroll
            for (int c2 = 0; c2 < 32; c2++) { si += v[c2] * ai[c2]; sj += v[c2] * aj[c2]; }
            atomicAdd(&g_si[(b*CH + h)*CN + n], si);
            atomicAdd(&g_sj[(b*CH + h)*CN + n], sj);
        }
        if (EPI == 3) {
            // per-column BN stats over this warp's 32 rows
            float s = 0.f, q = 0.f;
            const float* col = Cs + lane;
            #pragma unroll
            for (int r = 0; r < 32; r++) {
                float vv = col[r * 36] * sc;
                s += vv; q += vv * vv;
            }
            atomicAdd(&bsum[gcol + lane], s);
            atomicAdd(&bsq[gcol + lane], q);
        }
    }
}

// ---------- leakyrelu + row softmax -> alpha (bf16 hi/lo out) ----------
__global__ void k_alpha() {
    int row = blockIdx.x;                     // (b*H + h)*512 + i
    int bh = row >> 9;
    float s_i = g_si[row];
    const float* sjr = g_sj + bh * CN;
    __shared__ float shm[8], shs[8];
    int t = threadIdx.x, lane = t & 31, w = t >> 5;
    float e0 = s_i + sjr[t];       e0 = e0 >= 0.f ? e0 : 0.2f * e0;
    float e1 = s_i + sjr[t + 256]; e1 = e1 >= 0.f ? e1 : 0.2f * e1;
    float m = fmaxf(e0, e1);
#pragma unroll
    for (int o = 16; o; o >>= 1) m = fmaxf(m, __shfl_xor_sync(0xffffffffu, m, o));
    if (!lane) shm[w] = m;
    __syncthreads();
    if (t < 32) {
        float v = (t < 8) ? shm[t] : -INFINITY;
#pragma unroll
        for (int o = 4; o; o >>= 1) v = fmaxf(v, __shfl_xor_sync(0xffffffffu, v, o));
        if (t == 0) shm[0] = v;
    }
    __syncthreads();
    float bm = shm[0];
    float x0 = expf(e0 - bm), x1 = expf(e1 - bm);
    float s = x0 + x1;
#pragma unroll
    for (int o = 16; o; o >>= 1) s += __shfl_xor_sync(0xffffffffu, s, o);
    if (!lane) shs[w] = s;
    __syncthreads();
    if (t < 32) {
        float v = (t < 8) ? shs[t] : 0.f;
#pragma unroll
        for (int o = 4; o; o >>= 1) v += __shfl_xor_sync(0xffffffffu, v, o);
        if (t == 0) shs[0] = v;
    }
    __syncthreads();
    float inv = 1.f / shs[0];
    __nv_bfloat16 h0, l0, h1, l1;
    cvt_hl(x0 * inv, h0, l0);
    cvt_hl(x1 * inv, h1, l1);
    size_t base = (size_t)row * CN + t;
    g_alh[base] = h0;       g_all[base] = l0;
    g_alh[base + 256] = h1; g_all[base + 256] = l1;
}

// --- edge scores + fused radix pass A (hist + max); 32x32 tile, 2x2 microtile ---
__global__ void __launch_bounds__(256) k_edge(
    const float* __restrict__ b1, const float* __restrict__ w2,
    const float* __restrict__ b2)
{
    int b = blockIdx.z;
    int i0 = blockIdx.y * 32, j0 = blockIdx.x * 32;
    __shared__ __align__(16) float Pi[32][132], Pj[32][132];
    __shared__ float B1s[128], W2s[128];
    __shared__ unsigned shk[8];
    const float* pi = g_pij;
    const float* pj = g_pij + (size_t)CB*CN*CAH;
    int t = threadIdx.x;
    int ti = t >> 4, tj = t & 15;
    float acc[2][2] = {};
    for (int a0 = 0; a0 < CAH; a0 += 128) {
        if (t < 128) { B1s[t] = b1[a0 + t]; W2s[t] = w2[a0 + t]; }
        #pragma unroll
        for (int c = 0; c < 4; c++) {
            int q = t + 256 * c;            // 0..1023 over 32 rows x 32 float4
            int r = q >> 5, nc = (q & 31) * 4;
            *(float4*)&Pi[r][nc] = *(const float4*)&pi[(size_t)(b*CN + i0 + r) * CAH + a0 + nc];
            *(float4*)&Pj[r][nc] = *(const float4*)&pj[(size_t)(b*CN + j0 + r) * CAH + a0 + nc];
        }
        __syncthreads();
        #pragma unroll 8
        for (int a = 0; a < 128; a += 4) {
            float4 u0 = *(const float4*)&Pi[2*ti][a];
            float4 u1 = *(const float4*)&Pi[2*ti + 1][a];
            float4 v0 = *(const float4*)&Pj[2*tj][a];
            float4 v1 = *(const float4*)&Pj[2*tj + 1][a];
            float4 bb = *(const float4*)&B1s[a];
            float4 ww = *(const float4*)&W2s[a];
            #define EDGE_E(ue, ve, be, we) { \
                float p00 = ue.x + ve.x + be; float p01 = ue.x + ve.y + be; \
                float p10 = ue.y + ve.x + be; float p11 = ue.y + ve.y + be; \
                acc[0][0] += fmaxf(p00, 0.f) * we; \
                acc[0][1] += fmaxf(p01, 0.f) * we; \
                acc[1][0] += fmaxf(p10, 0.f) * we; \
                acc[1][1] += fmaxf(p11, 0.f) * we; }
            { float2 uu = make_float2(u0.x, u1.x), vv = make_float2(v0.x, v1.x); EDGE_E(uu, vv, bb.x, ww.x); }
            { float2 uu = make_float2(u0.y, u1.y), vv = make_float2(v0.y, v1.y); EDGE_E(uu, vv, bb.y, ww.y); }
            { float2 uu = make_float2(u0.z, u1.z), vv = make_float2(v0.z, v1.z); EDGE_E(uu, vv, bb.z, ww.z); }
            { float2 uu = make_float2(u0.w, u1.w), vv = make_float2(v0.w, v1.w); EDGE_E(uu, vv, bb.w, ww.w); }
            #undef EDGE_E
        }
        __syncthreads();
    }
    float bias = b2[0];
    unsigned lm = 0;
    #pragma unroll
    for (int r = 0; r < 2; r++) {
        float o0 = acc[r][0] + bias, o1 = acc[r][1] + bias;
        unsigned k0 = key_of(o0), k1 = key_of(o1);
        atomicAdd(&g_hist[(b << 16) + (k0 >> 16)], 1u);
        atomicAdd(&g_hist[(b << 16) + (k1 >> 16)], 1u);
        lm = max(lm, max(k0, k1));
        *(float2*)&g_edge[(size_t)b * CNN + (i0 + 2*ti + r) * CN + j0 + 2*tj] =
            make_float2(o0, o1);
    }
    int lane = t & 31, w = t >> 5;
#pragma unroll
    for (int o = 16; o; o >>= 1) lm = max(lm, __shfl_xor_sync(0xffffffffu, lm, o));
    if (!lane) shk[w] = lm;
    __syncthreads();
    if (t == 0) {
        unsigned v = shk[0];
        for (int q = 1; q < 8; q++) v = max(v, shk[q]);
        atomicMax(&g_maxkey[b], v);
    }
}

__global__ void k_scan1() {
    int b = blockIdx.x;
    unsigned* h = g_hist + (b << 16);
    __shared__ unsigned part[1024];
    int t = threadIdx.x;
    unsigned s = 0;
    for (int i = 0; i < 64; i++) s += h[t*64 + i];
    part[t] = s;
    __syncthreads();
    for (int off = 1; off < 1024; off <<= 1) {
        unsigned v = (t >= off) ? part[t - off] : 0u;
        __syncthreads();
        if (t >= off) part[t] += v;
        __syncthreads();
    }
    unsigned r = RSEL;
    unsigned pre = t ? part[t-1] : 0u;
    if (pre <= r && r < part[t]) {
        unsigned rem = r - pre;
        for (int i = 0; i < 64; i++) {
            unsigned c = h[t*64 + i];
            if (rem < c) { g_selhi[b] = (unsigned)(t*64 + i); g_rank2[b] = rem; break; }
            rem -= c;
        }
    }
    __syncthreads();
    for (int i = t; i < 65536; i += 1024) h[i] = 0;   // re-zero for pass B
}

__global__ void k_passB() {
    int b = blockIdx.y;
    const float* e = g_edge + (size_t)b * CNN;
    unsigned hi = g_selhi[b];
    for (int idx = blockIdx.x * blockDim.x + threadIdx.x; idx < CNN;
         idx += gridDim.x * blockDim.x) {
        unsigned key = key_of(e[idx]);
        if ((key >> 16) == hi) atomicAdd(&g_hist[(b << 16) + (key & 0xFFFFu)], 1u);
    }
}

__global__ void k_scan2() {
    int b = blockIdx.x;
    unsigned* h = g_hist + (b << 16);
    __shared__ unsigned part[1024];
    int t = threadIdx.x;
    unsigned s = 0;
    for (int i = 0; i < 64; i++) s += h[t*64 + i];
    part[t] = s;
    __syncthreads();
    for (int off = 1; off < 1024; off <<= 1) {
        unsigned v = (t >= off) ? part[t - off] : 0u;
        __syncthreads();
        if (t >= off) part[t] += v;
        __syncthreads();
    }
    unsigned r = g_rank2[b];
    unsigned pre = t ? part[t-1] : 0u;
    if (pre <= r && r < part[t]) {
        unsigned rem = r - pre;
        for (int i = 0; i < 64; i++) {
            unsigned c = h[t*64 + i];
            if (rem < c) {
                unsigned key = (g_selhi[b] << 16) | (unsigned)(t*64 + i);
                g_thr[b] = key_inv(key);
                break;
            }
            rem -= c;
        }
    }
}

// --------- masked exp (unnormalized) -> bf16 hi/lo cm + partial sums ---------
__global__ void k_maskexp() {
    int b = blockIdx.y;
    const float* e = g_edge + (size_t)b * CNN;
    __nv_bfloat16* cmh = g_cmh + (size_t)b * CNN;
    __nv_bfloat16* cml = g_cml + (size_t)b * CNN;
    float zmax = key_inv(g_maxkey[b]);
    float th = g_thr[b];
    float ls = 0.f;
    for (int idx = blockIdx.x * blockDim.x + threadIdx.x; idx < CNN;
         idx += gridDim.x * blockDim.x) {
        float z = e[idx];
        float v = 0.f;
        if (z >= th) v = expf((z - zmax) * 2.0f);   // 1/TEMP = 2
        __nv_bfloat16 h, l;
        cvt_hl(v, h, l);
        cmh[idx] = h; cml[idx] = l;
        ls += v;
    }
    __shared__ float sh[8];
    int t = threadIdx.x, lane = t & 31, w = t >> 5;
#pragma unroll
    for (int o = 16; o; o >>= 1) ls += __shfl_xor_sync(0xffffffffu, ls, o);
    if (!lane) sh[w] = ls;
    __syncthreads();
    if (t == 0) {
        float v = sh[0];
        for (int q = 1; q < 8; q++) v += sh[q];
        atomicAdd(&g_msum[b], v);
    }
}

// sum 4 K-split partials of h4, write h4, accumulate BN2 stats
__global__ void k_bnstats4() {
    int row0 = blockIdx.x * 32;
    int c = threadIdx.x;    // 128
    const long long S = (long long)CB * CN * COUT;
    float s = 0.f, q = 0.f;
    for (int r = 0; r < 32; r++) {
        size_t idx = (size_t)(row0 + r) * COUT + c;
        float v = g_h4p[idx] + g_h4p[idx + S] + g_h4p[idx + 2*S] + g_h4p[idx + 3*S];
        g_h4[idx] = v;
        s += v; q += v * v;
    }
    atomicAdd(&g_bs2[c], s);
    atomicAdd(&g_bq2[c], q);
}

__global__ void k_bnfinal(const float* sum, const float* sq,
                          const float* __restrict__ g, const float* __restrict__ bt,
                          float* scale, float* shift) {
    int c = threadIdx.x;
    const float invn = 1.f / (CB * CN);
    float mean = sum[c] * invn;
    float var = sq[c] * invn - mean * mean;
    float sc = g[c] * rsqrtf(var + 1e-5f);
    scale[c] = sc;
    shift[c] = bt[c] - mean * sc;
}

// BN1 apply + relu on h2 -> bf16 hi/lo
__global__ void k_bnrelu2() {
    const int total = CB * CN * CHID;
    for (int idx = blockIdx.x * blockDim.x + threadIdx.x; idx < total;
         idx += gridDim.x * blockDim.x) {
        int c = idx & (CHID - 1);
        float v = fmaxf(g_h2[idx] * g_sc1[c] + g_sh1[c], 0.f);
        __nv_bfloat16 h, l;
        cvt_hl(v, h, l);
        g_h2h[idx] = h; g_h2l[idx] = l;
    }
}

// ---------------- BN2-apply + relu + mean over N ----------------
__global__ void k_feat() {
    int b = blockIdx.x;
    int c = threadIdx.x;   // 128
    float sc = g_sc2[c], sh = g_sh2[c];
    float s = 0.f;
    for (int n = 0; n < CN; n++) {
        float v = g_h4[(size_t)(b*CN + n) * COUT + c] * sc + sh;
        s += fmaxf(v, 0.f);
    }
    g_feat[b*COUT + c] = s * (1.f / CN);
}

// ---------------- classifier ----------------
__global__ void k_cls(const float* __restrict__ cw, const float* __restrict__ cb,
                      float* __restrict__ out) {
    int w = threadIdx.x >> 5, lane = threadIdx.x & 31;
    if (w < CB * CNCLS) {
        int b = w / CNCLS, c = w % CNCLS;
        float s = 0.f;
        for (int f = lane; f < COUT; f += 32)
            s += g_feat[b*COUT + f] * cw[c*COUT + f];
#pragma unroll
        for (int o = 16; o; o >>= 1) s += __shfl_xor_sync(0xffffffffu, s, o);
        if (!lane) out[b*CNCLS + c] = s + cb[c];
    }
}

// ---------------- host launch ----------------
extern "C" void kernel_launch(void* const* d_in, const int* in_sizes, int n_in,
                              void* d_out, int out_size) {
    (void)in_sizes; (void)n_in; (void)out_size;
    const float* x    = (const float*)d_in[0];
    const float* Wg   = (const float*)d_in[1];
    const float* attn = (const float*)d_in[2];
    const float* W1   = (const float*)d_in[3];
    const float* b1   = (const float*)d_in[4];
    const float* w2   = (const float*)d_in[5];
    const float* b2   = (const float*)d_in[6];
    const float* gc1w = (const float*)d_in[7];
    /* gc1_b (8) cancels in BN */
    const float* bn1g = (const float*)d_in[9];
    const float* bn1b = (const float*)d_in[10];
    const float* gc2w = (const float*)d_in[11];
    /* gc2_b (12) cancels in BN */
    const float* bn2g = (const float*)d_in[13];
    const float* bn2b = (const float*)d_in[14];
    const float* clsw = (const float*)d_in[15];
    const float* clsb = (const float*)d_in[16];
    float* out = (float*)d_out;

    float *pij, *h2, *h4p;
    float *bs1, *bq1, *sc1, *sh1, *bs2, *bq2, *sc2, *sh2, *msum;
    cudaGetSymbolAddress((void**)&pij, g_pij);
    cudaGetSymbolAddress((void**)&h2,  g_h2);
    cudaGetSymbolAddress((void**)&h4p, g_h4p);
    cudaGetSymbolAddress((void**)&msum, g_msum);
    cudaGetSymbolAddress((void**)&bs1, g_bs1);
    cudaGetSymbolAddress((void**)&bq1, g_bq1);
    cudaGetSymbolAddress((void**)&sc1, g_sc1);
    cudaGetSymbolAddress((void**)&sh1, g_sh1);
    cudaGetSymbolAddress((void**)&bs2, g_bs2);
    cudaGetSymbolAddress((void**)&bq2, g_bq2);
    cudaGetSymbolAddress((void**)&sc2, g_sc2);
    cudaGetSymbolAddress((void**)&sh2, g_sh2);

    __nv_bfloat16 *xh,*xl,*Wgh,*Wgl,*hph,*hpl,*alh,*all,*nfh,*nfl,*W1h,*W1l;
    __nv_bfloat16 *cmh,*cml,*h1h,*h1l,*gc1h,*gc1l,*h2h,*h2l,*h3h,*h3l,*gc2h,*gc2l;
    cudaGetSymbolAddress((void**)&xh,  g_xh);   cudaGetSymbolAddress((void**)&xl,  g_xl);
    cudaGetSymbolAddress((void**)&Wgh, g_Wgh);  cudaGetSymbolAddress((void**)&Wgl, g_Wgl);
    cudaGetSymbolAddress((void**)&hph, g_hph);  cudaGetSymbolAddress((void**)&hpl, g_hpl);
    cudaGetSymbolAddress((void**)&alh, g_alh);  cudaGetSymbolAddress((void**)&all, g_all);
    cudaGetSymbolAddress((void**)&nfh, g_nfh);  cudaGetSymbolAddress((void**)&nfl, g_nfl);
    cudaGetSymbolAddress((void**)&W1h, g_W1h);  cudaGetSymbolAddress((void**)&W1l, g_W1l);
    cudaGetSymbolAddress((void**)&cmh, g_cmh);  cudaGetSymbolAddress((void**)&cml, g_cml);
    cudaGetSymbolAddress((void**)&h1h, g_h1h);  cudaGetSymbolAddress((void**)&h1l, g_h1l);
    cudaGetSymbolAddress((void**)&gc1h,g_gc1h); cudaGetSymbolAddress((void**)&gc1l,g_gc1l);
    cudaGetSymbolAddress((void**)&h2h, g_h2h);  cudaGetSymbolAddress((void**)&h2l, g_h2l);
    cudaGetSymbolAddress((void**)&h3h, g_h3h);  cudaGetSymbolAddress((void**)&h3l, g_h3l);
    cudaGetSymbolAddress((void**)&gc2h,g_gc2h); cudaGetSymbolAddress((void**)&gc2l,g_gc2l);

    // dynamic smem sizes (double-buffered staging; epilogue scratch is smaller)
    const int SM128T = 2 * (2*64*40 + 2*128*40) * 2;     // 61440
    const int SM128F = 2 * (2*64*40 + 2*32*136) * 2;     // 55296
    const int SM64T  = 2 * (2*64*40 + 2*64*40) * 2;      // 40960
    const int SM64F  = 2 * (2*64*40 + 2*32*72) * 2;      // 38912
    cudaFuncSetAttribute(gemm_w<128, true, 2>,  cudaFuncAttributeMaxDynamicSharedMemorySize, SM128T);
    cudaFuncSetAttribute(gemm_w<128, false, 2>, cudaFuncAttributeMaxDynamicSharedMemorySize, SM128F);
    cudaFuncSetAttribute(gemm_w<64, true, 0>,   cudaFuncAttributeMaxDynamicSharedMemorySize, SM64T);
    cudaFuncSetAttribute(gemm_w<64, true, 3>,   cudaFuncAttributeMaxDynamicSharedMemorySize, SM64T);
    cudaFuncSetAttribute(gemm_w<64, false, 2>,  cudaFuncAttributeMaxDynamicSharedMemorySize, SM64F);

    k_zero<<<512, 256>>>();

    // fused one-shot conversions of all 5 external inputs
    k_cvt5<<<784, 256>>>(x, Wg, W1, gc1w, gc2w);

    // hp = x @ Wg^T  (bf16 hi/lo only; s_i/s_j fused via attn)
    gemm_w<128, true, 2><<<dim3(CF/128, (CB*CN)/64, 1), 256, SM128T>>>(
        xh, xl, Wgh, Wgl, (float*)0, hph, hpl, CF, CF, CF, CF,
        1, 0,0, 0,0, 0,0, (const float*)0, attn, (float*)0, (float*)0);

    k_alpha<<<CB*CH*CN, 256>>>();

    // node_feats: per (b,h)  alpha(512x512) @ hp_bh -> nf (bf16 hi/lo only)
    gemm_w<128, false, 2><<<dim3(CDH/128, CN/64, CB*CH), 256, SM128F>>>(
        alh, all, hph, hpl, (float*)0, nfh, nfl, CN, CN, CF, CF,
        CH, (long long)CH*CNN, (long long)CNN,
        (long long)CN*CF, (long long)CDH,
        (long long)CN*CF, (long long)CDH, (const float*)0,
        (const float*)0, (float*)0, (float*)0);

    // pi / pj = nf @ W1i^T / W1j^T   (fp32 only)
    gemm_w<64, true, 0><<<dim3(CAH/64, (CB*CN)/64, 2), 128, SM64T>>>(
        nfh, nfl, W1h, W1l, pij, (__nv_bfloat16*)0, (__nv_bfloat16*)0, CF, CF, 2*CF, CAH,
        1, 0, 0, (long long)CF, 0, (long long)CB*CN*CAH, 0, (const float*)0,
        (const float*)0, (float*)0, (float*)0);

    // edge scores + fused radix pass A
    k_edge<<<dim3(CN/32, CN/32, CB), 256>>>(b1, w2, b2);

    // exact top-k threshold, then masked exp (norm reciprocal folded into gemms)
    k_scan1<<<CB, 1024>>>();
    k_passB<<<dim3(128, CB), 256>>>();
    k_scan2<<<CB, 1024>>>();
    k_maskexp<<<dim3(128, CB), 256>>>();

    // h1 = (cm/Z) @ nf  (bf16 hi/lo only), 1/Z folded in
    gemm_w<128, false, 2><<<dim3(CF/128, CN/64, CB), 256, SM128F>>>(
        cmh, cml, nfh, nfl, (float*)0, h1h, h1l, CN, CN, CF, CF,
        1, (long long)CNN, 0, (long long)CN*CF, 0, (long long)CN*CF, 0, msum,
        (const float*)0, (float*)0, (float*)0);

    // h2 = h1 @ gc1_w^T  (fp32 + fused BN1 stats)   [gc1_b cancels in BN]
    gemm_w<64, true, 3><<<dim3(CHID/64, (CB*CN)/64, 1), 128, SM64T>>>(
        h1h, h1l, gc1h, gc1l, h2, (__nv_bfloat16*)0, (__nv_bfloat16*)0, CF, CF, CF, CHID,
        1, 0,0, 0,0, 0,0, (const float*)0, (const float*)0, bs1, bq1);

    k_bnfinal<<<1, CHID>>>(bs1, bq1, bn1g, bn1b, sc1, sh1);
    k_bnrelu2<<<256, 256>>>();

    // h3 = (cm/Z) @ h2  (bf16 hi/lo only), 1/Z folded in
    gemm_w<64, false, 2><<<dim3(CHID/64, CN/64, CB), 128, SM64F>>>(
        cmh, cml, h2h, h2l, (float*)0, h3h, h3l, CN, CN, CHID, CHID,
        1, (long long)CNN, 0, (long long)CN*CHID, 0, (long long)CN*CHID, 0, msum,
        (const float*)0, (float*)0, (float*)0);

    // h4 = h3 @ gc2_w^T  (K-split x4 partials, fp32)
    gemm_w<64, true, 0><<<dim3(COUT/64, (CB*CN)/64, 4), 128, SM64T>>>(
        h3h, h3l, gc2h, gc2l, h4p, (__nv_bfloat16*)0, (__nv_bfloat16*)0, CHID/4, CHID, CHID, COUT,
        1, 128, 0, 128, 0, (long long)CB*CN*COUT, 0, (const float*)0,
        (const float*)0, (float*)0, (float*)0);

    k_bnstats4<<<(CB*CN)/32, COUT>>>();
    k_bnfinal<<<1, COUT>>>(bs2, bq2, bn2g, bn2b, sc2, sh2);

    k_feat<<<CB, COUT>>>();
    k_cls<<<1, 640>>>(clsw, clsb, out);
}

// round 16
// speedup vs baseline: 1.7381x; 1.0452x over previous
#include <cuda_runtime.h>
#include <cuda_bf16.h>
#include <mma.h>
#include <math.h>

using namespace nvcuda;

#define CB 2
#define CN 512
#define CF 1024
#define CH 4
#define CDH 256
#define CAH 256
#define CHID 512
#define COUT 128
#define CNCLS 10
#define CNN (CN*CN)
#define RSEL 52429u   /* NN - int(0.8*NN) = 262144 - 209715 */

// ---------------- scratch (static device memory; no allocations) ----------------
__device__ float g_si[CB*CH*CN];
__device__ float g_sj[CB*CH*CN];
__device__ float g_pij[2*CB*CN*CAH];
__device__ float g_edge[CB*CNN];
__device__ float g_h2[CB*CN*CHID];
__device__ float g_h4[CB*CN*COUT];
__device__ float g_h4p[4*CB*CN*COUT];
__device__ float g_feat[CB*COUT];
__device__ unsigned g_hist[CB*65536];
__device__ unsigned g_selhi[CB];
__device__ unsigned g_rank2[CB];
__device__ unsigned g_maxkey[CB];
__device__ float g_thr[CB];
__device__ float g_msum[CB];
__device__ float g_bs1[CHID], g_bq1[CHID];
__device__ float g_bs2[COUT], g_bq2[COUT];

// bf16 hi/lo operand mirrors
__device__ __nv_bfloat16 g_xh[CB*CN*CF],  g_xl[CB*CN*CF];
__device__ __nv_bfloat16 g_Wgh[CF*CF],    g_Wgl[CF*CF];
__device__ __nv_bfloat16 g_hph[CB*CN*CF], g_hpl[CB*CN*CF];
__device__ __nv_bfloat16 g_alh[CB*CH*CNN],g_all[CB*CH*CNN];
__device__ __nv_bfloat16 g_nfh[CB*CN*CF], g_nfl[CB*CN*CF];
__device__ __nv_bfloat16 g_W1h[CAH*2*CF], g_W1l[CAH*2*CF];
__device__ __nv_bfloat16 g_cmh[CB*CNN],   g_cml[CB*CNN];
__device__ __nv_bfloat16 g_h1h[CB*CN*CF], g_h1l[CB*CN*CF];
__device__ __nv_bfloat16 g_gc1h[CHID*CF], g_gc1l[CHID*CF];
__device__ __nv_bfloat16 g_h2h[CB*CN*CHID], g_h2l[CB*CN*CHID];
__device__ __nv_bfloat16 g_h3h[CB*CN*CHID], g_h3l[CB*CN*CHID];
__device__ __nv_bfloat16 g_gc2h[COUT*CHID], g_gc2l[COUT*CHID];

// ---------------- helpers ----------------
__device__ __forceinline__ unsigned key_of(float x) {
    unsigned u = __float_as_uint(x);
    return (u & 0x80000000u) ? ~u : (u | 0x80000000u);
}
__device__ __forceinline__ float key_inv(unsigned key) {
    unsigned u = (key & 0x80000000u) ? (key ^ 0x80000000u) : ~key;
    return __uint_as_float(u);
}
__device__ __forceinline__ void cvt_hl(float v, __nv_bfloat16& h, __nv_bfloat16& l) {
    h = __float2bfloat16(v);
    l = __float2bfloat16(v - __bfloat162float(h));
}
__device__ __forceinline__ void cpa16(void* smem, const void* gmem) {
    unsigned saddr = (unsigned)__cvta_generic_to_shared(smem);
    asm volatile("cp.async.ca.shared.global [%0], [%1], 16;\n" :: "r"(saddr), "l"(gmem));
}
#define CPA_COMMIT() asm volatile("cp.async.commit_group;\n" ::: "memory")
#define CPA_WAIT0()  asm volatile("cp.async.wait_group 0;\n" ::: "memory")

// ---------------- zero scratch (must run every launch; graph replays) ----------------
__global__ void k_zero() {
    int i = blockIdx.x * 256 + threadIdx.x;       // grid = 512 blocks -> 131072 threads
    g_hist[i] = 0;
    if (i < CHID) { g_bs1[i] = 0.f; g_bq1[i] = 0.f; }
    if (i < COUT) { g_bs2[i] = 0.f; g_bq2[i] = 0.f; }
    if (i < CB*COUT) g_feat[i] = 0.f;
    if (i < CB*CH*CN) { g_si[i] = 0.f; g_sj[i] = 0.f; }
    if (i < CB)   { g_msum[i] = 0.f; g_maxkey[i] = 0u; }
}

// ------ fused one-shot input conversions: 5 tensors, block-range dispatch ------
// elements/block = 4096. x:256 | Wg:256 | W1:128 | gc1:128 | gc2:16  -> 784 blocks
__global__ void k_cvt5(const float* __restrict__ x,   const float* __restrict__ Wg,
                       const float* __restrict__ W1,  const float* __restrict__ gc1,
                       const float* __restrict__ gc2) {
    int b = blockIdx.x;
    const float* src; __nv_bfloat16 *ho, *lo; int blk;
    if (b < 256)       { src = x;   ho = g_xh;   lo = g_xl;   blk = b; }
    else if (b < 512)  { src = Wg;  ho = g_Wgh;  lo = g_Wgl;  blk = b - 256; }
    else if (b < 640)  { src = W1;  ho = g_W1h;  lo = g_W1l;  blk = b - 512; }
    else if (b < 768)  { src = gc1; ho = g_gc1h; lo = g_gc1l; blk = b - 640; }
    else               { src = gc2; ho = g_gc2h; lo = g_gc2l; blk = b - 768; }
    int base = blk * 4096 + threadIdx.x * 16;
    float4 v[4];
    #pragma unroll
    for (int q = 0; q < 4; q++) v[q] = *(const float4*)(src + base + q * 4);
    #pragma unroll
    for (int q = 0; q < 4; q++) {
        float vv[4] = {v[q].x, v[q].y, v[q].z, v[q].w};
        union { __nv_bfloat16 bb[4]; uint2 u; } uh, ul;
        #pragma unroll
        for (int e = 0; e < 4; e++) cvt_hl(vv[e], uh.bb[e], ul.bb[e]);
        *(uint2*)(ho + base + q * 4) = uh.u;
        *(uint2*)(lo + base + q * 4) = ul.u;
    }
}

// ====== split-bf16 tensor-core GEMM, cp.async double-buffered, K-chunk 32 ======
// TN=128: 256 thr, 8 warps (2x4).  TN=64: 128 thr, 4 warps (2x2).  Tile M64 x TN.
// C = scale * (Ah+Al) @ (Bh+Bl)'   (3 of 4 cross terms, fp32 accumulate)
// EPI: 0 = fp32 C (direct frag store)
//      1 = fp32 C + bf16 hi/lo Ch/Cl
//      2 = bf16 hi/lo only (+optional fused s_i/s_j via attnp)
//      3 = fp32 C + per-column stats atomics into bsum/bsq
// scalep: if non-null, sc = 1/scalep[zo]  (raw sums; reciprocal folded here)
template<int TN, bool BT, int EPI>
__global__ void __launch_bounds__(TN == 128 ? 256 : 128) gemm_w(
    const __nv_bfloat16* __restrict__ Ah, const __nv_bfloat16* __restrict__ Al,
    const __nv_bfloat16* __restrict__ Bh, const __nv_bfloat16* __restrict__ Bl,
    float* __restrict__ C, __nv_bfloat16* __restrict__ Ch, __nv_bfloat16* __restrict__ Cl,
    int K, int lda, int ldb, int ldc,
    int bdiv, long long sAo, long long sAi, long long sBo, long long sBi,
    long long sCo, long long sCi, const float* __restrict__ scalep,
    const float* __restrict__ attnp, float* __restrict__ bsum, float* __restrict__ bsq)
{
    const int NT = (TN == 128) ? 256 : 128;
    extern __shared__ __align__(16) char sraw[];
    constexpr int BROWS = BT ? TN : 32;
    constexpr int BLD   = BT ? 40 : TN + 8;
    constexpr int AELE  = 64 * 40;                 // elements per A plane
    constexpr int BELE  = BROWS * BLD;
    constexpr int BUFE  = 2 * AELE + 2 * BELE;     // elements per buffer (H+L planes)

    int z = blockIdx.z;
    int zo = z / bdiv, zi = z - zo * bdiv;
    long long aoff = zo * sAo + zi * sAi;
    long long boff = zo * sBo + zi * sBi;
    long long coff = zo * sCo + zi * sCi;
    Ah += aoff;  Al += aoff;
    Bh += boff;  Bl += boff;
    C  += coff;
    if (EPI == 1 || EPI == 2) { Ch += coff; Cl += coff; }

    int t = threadIdx.x;
    int warp = t >> 5, lane = t & 31;
    int wm = (TN == 128) ? (warp >> 2) : (warp >> 1);
    int wn = (TN == 128) ? (warp & 3) : (warp & 1);
    int m0 = blockIdx.y * 64, n0 = blockIdx.x * TN;

    // issue cp.async stage of chunk at k0 into buffer b
    auto stage = [&](int b, int k0) {
        __nv_bfloat16* AsH = (__nv_bfloat16*)sraw + b * BUFE;
        __nv_bfloat16* AsL = AsH + AELE;
        __nv_bfloat16* BsH = AsL + AELE;
        __nv_bfloat16* BsL = BsH + BELE;
        #pragma unroll
        for (int g = t; g < 256; g += NT) {
            int r = g >> 2, c = (g & 3) * 8;
            size_t off = (size_t)(m0 + r) * lda + k0 + c;
            cpa16(&AsH[r * 40 + c], Ah + off);
            cpa16(&AsL[r * 40 + c], Al + off);
        }
        if (BT) {
            #pragma unroll
            for (int g = t; g < TN * 4; g += NT) {
                int r = g >> 2, c = (g & 3) * 8;
                size_t off = (size_t)(n0 + r) * ldb + k0 + c;
                cpa16(&BsH[r * 40 + c], Bh + off);
                cpa16(&BsL[r * 40 + c], Bl + off);
            }
        } else {
            const int TPR = TN / 8;
            #pragma unroll
            for (int g = t; g < TN * 4; g += NT) {
                int r = g / TPR, c = (g % TPR) * 8;
                size_t off = (size_t)(k0 + r) * ldb + n0 + c;
                cpa16(&BsH[r * BLD + c], Bh + off);
                cpa16(&BsL[r * BLD + c], Bl + off);
            }
        }
    };

    wmma::fragment<wmma::accumulator, 16, 16, 16, float> acc[2][2];
    #pragma unroll
    for (int i = 0; i < 2; i++)
        #pragma unroll
        for (int j = 0; j < 2; j++) wmma::fill_fragment(acc[i][j], 0.0f);

    int nch = K >> 5;
    stage(0, 0);
    CPA_COMMIT();
    CPA_WAIT0();
    __syncthreads();

    int buf = 0;
    for (int c = 0; c < nch; c++) {
        if (c + 1 < nch) { stage(buf ^ 1, (c + 1) * 32); CPA_COMMIT(); }

        __nv_bfloat16* AsH = (__nv_bfloat16*)sraw + buf * BUFE;
        __nv_bfloat16* AsL = AsH + AELE;
        __nv_bfloat16* BsH = AsL + AELE;
        __nv_bfloat16* BsL = BsH + BELE;
        #pragma unroll
        for (int hf = 0; hf < 2; hf++) {
            int ko = hf * 16;
            wmma::fragment<wmma::matrix_a, 16, 16, 16, __nv_bfloat16, wmma::row_major> aH[2], aL[2];
            #pragma unroll
            for (int i = 0; i < 2; i++) {
                wmma::load_matrix_sync(aH[i], &AsH[(wm * 32 + i * 16) * 40 + ko], 40);
                wmma::load_matrix_sync(aL[i], &AsL[(wm * 32 + i * 16) * 40 + ko], 40);
            }
            #pragma unroll
            for (int j = 0; j < 2; j++) {
                if (BT) {
                    wmma::fragment<wmma::matrix_b, 16, 16, 16, __nv_bfloat16, wmma::col_major> bH, bL;
                    wmma::load_matrix_sync(bH, &BsH[(wn * 32 + j * 16) * 40 + ko], 40);
                    wmma::load_matrix_sync(bL, &BsL[(wn * 32 + j * 16) * 40 + ko], 40);
                    #pragma unroll
                    for (int i = 0; i < 2; i++) {
                        wmma::mma_sync(acc[i][j], aH[i], bH, acc[i][j]);
                        wmma::mma_sync(acc[i][j], aH[i], bL, acc[i][j]);
                        wmma::mma_sync(acc[i][j], aL[i], bH, acc[i][j]);
                    }
                } else {
                    wmma::fragment<wmma::matrix_b, 16, 16, 16, __nv_bfloat16, wmma::row_major> bH, bL;
                    wmma::load_matrix_sync(bH, &BsH[ko * BLD + wn * 32 + j * 16], BLD);
                    wmma::load_matrix_sync(bL, &BsL[ko * BLD + wn * 32 + j * 16], BLD);
                    #pragma unroll
                    for (int i = 0; i < 2; i++) {
                        wmma::mma_sync(acc[i][j], aH[i], bH, acc[i][j]);
                        wmma::mma_sync(acc[i][j], aH[i], bL, acc[i][j]);
                        wmma::mma_sync(acc[i][j], aL[i], bH, acc[i][j]);
                    }
                }
            }
        }
        if (c + 1 < nch) {
            CPA_WAIT0();
            __syncthreads();
            buf ^= 1;
        }
    }

    float sc = scalep ? (1.0f / scalep[zo]) : 1.0f;
    if (EPI == 0) {
        #pragma unroll
        for (int i = 0; i < 2; i++)
            #pragma unroll
            for (int j = 0; j < 2; j++) {
                #pragma unroll
                for (int e = 0; e < acc[i][j].num_elements; e++) acc[i][j].x[e] *= sc;
                wmma::store_matrix_sync(
                    &C[(size_t)(m0 + wm * 32 + i * 16) * ldc + n0 + wn * 32 + j * 16],
                    acc[i][j], ldc, wmma::mem_row_major);
            }
    } else {
        __syncthreads();    // all compute done before aliasing smem as fp32 scratch
        float* Cs = (float*)sraw + warp * (32 * 36);
        #pragma unroll
        for (int i = 0; i < 2; i++)
            #pragma unroll
            for (int j = 0; j < 2; j++)
                wmma::store_matrix_sync(Cs + (i * 16) * 36 + j * 16, acc[i][j], 36,
                                        wmma::mem_row_major);
        __syncwarp();
        int grow = m0 + wm * 32 + lane;
        int gcol = n0 + wn * 32;
        const float* src = Cs + lane * 36;
        float v[32];
        #pragma unroll
        for (int c2 = 0; c2 < 32; c2++) v[c2] = src[c2] * sc;
        if (EPI == 1 || EPI == 3) {
            #pragma unroll
            for (int q = 0; q < 8; q++)
                *(float4*)&C[(size_t)grow * ldc + gcol + q * 4] =
                    make_float4(v[q*4], v[q*4+1], v[q*4+2], v[q*4+3]);
        }
        if (EPI == 1 || EPI == 2) {
            #pragma unroll
            for (int q = 0; q < 4; q++) {
                union { __nv_bfloat16 b[8]; uint4 u; } ph, pl;
                #pragma unroll
                for (int e = 0; e < 8; e++) cvt_hl(v[q*8 + e], ph.b[e], pl.b[e]);
                *(uint4*)&Ch[(size_t)grow * ldc + gcol + q * 8] = ph.u;
                *(uint4*)&Cl[(size_t)grow * ldc + gcol + q * 8] = pl.u;
            }
        }
        if (EPI == 2 && attnp) {
            int b = grow >> 9, n = grow & 511;
            int h = gcol >> 8, cb = gcol & 255;
            const float* ai = attnp + h * (2*CDH) + cb;
            const float* aj = ai + CDH;
            float si = 0.f, sj = 0.f;
            #pragma unroll
            for (int c2 = 0; c2 < 32; c2++) { si += v[c2] * ai[c2]; sj += v[c2] * aj[c2]; }
            atomicAdd(&g_si[(b*CH + h)*CN + n], si);
            atomicAdd(&g_sj[(b*CH + h)*CN + n], sj);
        }
        if (EPI == 3) {
            float s = 0.f, q = 0.f;
            const float* col = Cs + lane;
            #pragma unroll
            for (int r = 0; r < 32; r++) {
                float vv = col[r * 36] * sc;
                s += vv; q += vv * vv;
            }
            atomicAdd(&bsum[gcol + lane], s);
            atomicAdd(&bsq[gcol + lane], q);
        }
    }
}

// ---- leakyrelu + row softmax -> alpha (bf16 hi/lo): warp per row, no block sync ----
__global__ void k_alpha() {          // grid 512, block 256 (8 warps = 8 rows)
    int w = threadIdx.x >> 5, lane = threadIdx.x & 31;
    int row = blockIdx.x * 8 + w;    // (b*H + h)*512 + i
    int bh = row >> 9;
    float s_i = g_si[row];
    const float* sjr = g_sj + bh * CN;
    float e[16];
    float m = -INFINITY;
    #pragma unroll
    for (int q = 0; q < 16; q++) {
        float v = s_i + sjr[lane + 32*q];
        v = v >= 0.f ? v : 0.2f * v;
        e[q] = v;
        m = fmaxf(m, v);
    }
    #pragma unroll
    for (int o = 16; o; o >>= 1) m = fmaxf(m, __shfl_xor_sync(0xffffffffu, m, o));
    float s = 0.f;
    #pragma unroll
    for (int q = 0; q < 16; q++) { e[q] = expf(e[q] - m); s += e[q]; }
    #pragma unroll
    for (int o = 16; o; o >>= 1) s += __shfl_xor_sync(0xffffffffu, s, o);
    float inv = 1.f / s;
    size_t base = (size_t)row * CN + lane;
    #pragma unroll
    for (int q = 0; q < 16; q++) {
        __nv_bfloat16 h, l;
        cvt_hl(e[q] * inv, h, l);
        g_alh[base + 32*q] = h;
        g_all[base + 32*q] = l;
    }
}

// --- edge scores + fused radix pass A (hist + max); 32x32 tile, 2x2 microtile ---
__global__ void __launch_bounds__(256) k_edge(
    const float* __restrict__ b1, const float* __restrict__ w2,
    const float* __restrict__ b2)
{
    int b = blockIdx.z;
    int i0 = blockIdx.y * 32, j0 = blockIdx.x * 32;
    __shared__ __align__(16) float Pi[32][132], Pj[32][132];
    __shared__ float B1s[128], W2s[128];
    __shared__ unsigned shk[8];
    const float* pi = g_pij;
    const float* pj = g_pij + (size_t)CB*CN*CAH;
    int t = threadIdx.x;
    int ti = t >> 4, tj = t & 15;
    float acc[2][2] = {};
    for (int a0 = 0; a0 < CAH; a0 += 128) {
        if (t < 128) { B1s[t] = b1[a0 + t]; W2s[t] = w2[a0 + t]; }
        #pragma unroll
        for (int c = 0; c < 4; c++) {
            int q = t + 256 * c;            // 0..1023 over 32 rows x 32 float4
            int r = q >> 5, nc = (q & 31) * 4;
            *(float4*)&Pi[r][nc] = *(const float4*)&pi[(size_t)(b*CN + i0 + r) * CAH + a0 + nc];
            *(float4*)&Pj[r][nc] = *(const float4*)&pj[(size_t)(b*CN + j0 + r) * CAH + a0 + nc];
        }
        __syncthreads();
        #pragma unroll 8
        for (int a = 0; a < 128; a += 4) {
            float4 u0 = *(const float4*)&Pi[2*ti][a];
            float4 u1 = *(const float4*)&Pi[2*ti + 1][a];
            float4 v0 = *(const float4*)&Pj[2*tj][a];
            float4 v1 = *(const float4*)&Pj[2*tj + 1][a];
            float4 bb = *(const float4*)&B1s[a];
            float4 ww = *(const float4*)&W2s[a];
            #define EDGE_E(ue, ve, be, we) { \
                float p00 = ue.x + ve.x + be; float p01 = ue.x + ve.y + be; \
                float p10 = ue.y + ve.x + be; float p11 = ue.y + ve.y + be; \
                acc[0][0] += fmaxf(p00, 0.f) * we; \
                acc[0][1] += fmaxf(p01, 0.f) * we; \
                acc[1][0] += fmaxf(p10, 0.f) * we; \
                acc[1][1] += fmaxf(p11, 0.f) * we; }
            { float2 uu = make_float2(u0.x, u1.x), vv = make_float2(v0.x, v1.x); EDGE_E(uu, vv, bb.x, ww.x); }
            { float2 uu = make_float2(u0.y, u1.y), vv = make_float2(v0.y, v1.y); EDGE_E(uu, vv, bb.y, ww.y); }
            { float2 uu = make_float2(u0.z, u1.z), vv = make_float2(v0.z, v1.z); EDGE_E(uu, vv, bb.z, ww.z); }
            { float2 uu = make_float2(u0.w, u1.w), vv = make_float2(v0.w, v1.w); EDGE_E(uu, vv, bb.w, ww.w); }
            #undef EDGE_E
        }
        __syncthreads();
    }
    float bias = b2[0];
    unsigned lm = 0;
    #pragma unroll
    for (int r = 0; r < 2; r++) {
        float o0 = acc[r][0] + bias, o1 = acc[r][1] + bias;
        unsigned k0 = key_of(o0), k1 = key_of(o1);
        atomicAdd(&g_hist[(b << 16) + (k0 >> 16)], 1u);
        atomicAdd(&g_hist[(b << 16) + (k1 >> 16)], 1u);
        lm = max(lm, max(k0, k1));
        *(float2*)&g_edge[(size_t)b * CNN + (i0 + 2*ti + r) * CN + j0 + 2*tj] =
            make_float2(o0, o1);
    }
    int lane = t & 31, w = t >> 5;
#pragma unroll
    for (int o = 16; o; o >>= 1) lm = max(lm, __shfl_xor_sync(0xffffffffu, lm, o));
    if (!lane) shk[w] = lm;
    __syncthreads();
    if (t == 0) {
        unsigned v = shk[0];
        for (int q = 1; q < 8; q++) v = max(v, shk[q]);
        atomicMax(&g_maxkey[b], v);
    }
}

__global__ void k_scan1() {
    int b = blockIdx.x;
    unsigned* h = g_hist + (b << 16);
    __shared__ unsigned part[1024];
    int t = threadIdx.x;
    unsigned s = 0;
    for (int i = 0; i < 64; i++) s += h[t*64 + i];
    part[t] = s;
    __syncthreads();
    for (int off = 1; off < 1024; off <<= 1) {
        unsigned v = (t >= off) ? part[t - off] : 0u;
        __syncthreads();
        if (t >= off) part[t] += v;
        __syncthreads();
    }
    unsigned r = RSEL;
    unsigned pre = t ? part[t-1] : 0u;
    if (pre <= r && r < part[t]) {
        unsigned rem = r - pre;
        for (int i = 0; i < 64; i++) {
            unsigned c = h[t*64 + i];
            if (rem < c) { g_selhi[b] = (unsigned)(t*64 + i); g_rank2[b] = rem; break; }
            rem -= c;
        }
    }
    __syncthreads();
    for (int i = t; i < 65536; i += 1024) h[i] = 0;   // re-zero for pass B
}

__global__ void k_passB() {
    int b = blockIdx.y;
    const float* e = g_edge + (size_t)b * CNN;
    unsigned hi = g_selhi[b];
    for (int idx = blockIdx.x * blockDim.x + threadIdx.x; idx < CNN;
         idx += gridDim.x * blockDim.x) {
        unsigned key = key_of(e[idx]);
        if ((key >> 16) == hi) atomicAdd(&g_hist[(b << 16) + (key & 0xFFFFu)], 1u);
    }
}

__global__ void k_scan2() {
    int b = blockIdx.x;
    unsigned* h = g_hist + (b << 16);
    __shared__ unsigned part[1024];
    int t = threadIdx.x;
    unsigned s = 0;
    for (int i = 0; i < 64; i++) s += h[t*64 + i];
    part[t] = s;
    __syncthreads();
    for (int off = 1; off < 1024; off <<= 1) {
        unsigned v = (t >= off) ? part[t - off] : 0u;
        __syncthreads();
        if (t >= off) part[t] += v;
        __syncthreads();
    }
    unsigned r = g_rank2[b];
    unsigned pre = t ? part[t-1] : 0u;
    if (pre <= r && r < part[t]) {
        unsigned rem = r - pre;
        for (int i = 0; i < 64; i++) {
            unsigned c = h[t*64 + i];
            if (rem < c) {
                unsigned key = (g_selhi[b] << 16) | (unsigned)(t*64 + i);
                g_thr[b] = key_inv(key);
                break;
            }
            rem -= c;
        }
    }
}

// --------- masked exp (unnormalized) -> bf16 hi/lo cm + partial sums ---------
__global__ void k_maskexp() {
    int b = blockIdx.y;
    const float* e = g_edge + (size_t)b * CNN;
    __nv_bfloat16* cmh = g_cmh + (size_t)b * CNN;
    __nv_bfloat16* cml = g_cml + (size_t)b * CNN;
    float zmax = key_inv(g_maxkey[b]);
    float th = g_thr[b];
    float ls = 0.f;
    for (int idx = blockIdx.x * blockDim.x + threadIdx.x; idx < CNN;
         idx += gridDim.x * blockDim.x) {
        float z = e[idx];
        float v = 0.f;
        if (z >= th) v = expf((z - zmax) * 2.0f);   // 1/TEMP = 2
        __nv_bfloat16 h, l;
        cvt_hl(v, h, l);
        cmh[idx] = h; cml[idx] = l;
        ls += v;
    }
    __shared__ float sh[8];
    int t = threadIdx.x, lane = t & 31, w = t >> 5;
#pragma unroll
    for (int o = 16; o; o >>= 1) ls += __shfl_xor_sync(0xffffffffu, ls, o);
    if (!lane) sh[w] = ls;
    __syncthreads();
    if (t == 0) {
        float v = sh[0];
        for (int q = 1; q < 8; q++) v += sh[q];
        atomicAdd(&g_msum[b], v);
    }
}

// sum 4 K-split partials of h4, write h4, accumulate BN2 stats
__global__ void k_bnstats4() {
    int row0 = blockIdx.x * 32;
    int c = threadIdx.x;    // 128
    const long long S = (long long)CB * CN * COUT;
    float s = 0.f, q = 0.f;
    for (int r = 0; r < 32; r++) {
        size_t idx = (size_t)(row0 + r) * COUT + c;
        float v = g_h4p[idx] + g_h4p[idx + S] + g_h4p[idx + 2*S] + g_h4p[idx + 3*S];
        g_h4[idx] = v;
        s += v; q += v * v;
    }
    atomicAdd(&g_bs2[c], s);
    atomicAdd(&g_bq2[c], q);
}

// BN1 scale/shift computed inline; apply + relu on h2 -> bf16 hi/lo
__global__ void k_bnrelu2(const float* __restrict__ g, const float* __restrict__ bt) {
    const int total = CB * CN * CHID;
    const float invn = 1.f / (CB * CN);
    for (int idx = blockIdx.x * blockDim.x + threadIdx.x; idx < total;
         idx += gridDim.x * blockDim.x) {
        int c = idx & (CHID - 1);
        float mean = g_bs1[c] * invn;
        float var = g_bq1[c] * invn - mean * mean;
        float sc = g[c] * rsqrtf(var + 1e-5f);
        float sh = bt[c] - mean * sc;
        float v = fmaxf(g_h2[idx] * sc + sh, 0.f);
        __nv_bfloat16 h, l;
        cvt_hl(v, h, l);
        g_h2h[idx] = h; g_h2l[idx] = l;
    }
}

// ------- BN2 (inline scale/shift) + relu + partial sums over N chunks -------
__global__ void k_feat2(const float* __restrict__ g, const float* __restrict__ bt) {
    int blk = blockIdx.x;           // CB*16 blocks
    int b = blk >> 4, chunk = blk & 15;
    int c = threadIdx.x;            // 128
    const float invn = 1.f / (CB * CN);
    float mean = g_bs2[c] * invn;
    float var = g_bq2[c] * invn - mean * mean;
    float sc = g[c] * rsqrtf(var + 1e-5f);
    float sh = bt[c] - mean * sc;
    float s = 0.f;
    int n0 = chunk * 32;
    for (int r = 0; r < 32; r++) {
        float v = g_h4[(size_t)(b*CN + n0 + r) * COUT + c] * sc + sh;
        s += fmaxf(v, 0.f);
    }
    atomicAdd(&g_feat[b*COUT + c], s);
}

// ---------------- classifier (1/CN folded in) ----------------
__global__ void k_cls(const float* __restrict__ cw, const float* __restrict__ cb,
                      float* __restrict__ out) {
    int w = threadIdx.x >> 5, lane = threadIdx.x & 31;
    if (w < CB * CNCLS) {
        int b = w / CNCLS, c = w % CNCLS;
        float s = 0.f;
        for (int f = lane; f < COUT; f += 32)
            s += g_feat[b*COUT + f] * cw[c*COUT + f];
#pragma unroll
        for (int o = 16; o; o >>= 1) s += __shfl_xor_sync(0xffffffffu, s, o);
        if (!lane) out[b*CNCLS + c] = s * (1.f / CN) + cb[c];
    }
}

// ---------------- host launch ----------------
extern "C" void kernel_launch(void* const* d_in, const int* in_sizes, int n_in,
                              void* d_out, int out_size) {
    (void)in_sizes; (void)n_in; (void)out_size;
    const float* x    = (const float*)d_in[0];
    const float* Wg   = (const float*)d_in[1];
    const float* attn = (const float*)d_in[2];
    const float* W1   = (const float*)d_in[3];
    const float* b1   = (const float*)d_in[4];
    const float* w2   = (const float*)d_in[5];
    const float* b2   = (const float*)d_in[6];
    const float* gc1w = (const float*)d_in[7];
    /* gc1_b (8) cancels in BN */
    const float* bn1g = (const float*)d_in[9];
    const float* bn1b = (const float*)d_in[10];
    const float* gc2w = (const float*)d_in[11];
    /* gc2_b (12) cancels in BN */
    const float* bn2g = (const float*)d_in[13];
    const float* bn2b = (const float*)d_in[14];
    const float* clsw = (const float*)d_in[15];
    const float* clsb = (const float*)d_in[16];
    float* out = (float*)d_out;

    float *pij, *h2, *h4p;
    float *bs1, *bq1, *bs2, *bq2, *msum;
    cudaGetSymbolAddress((void**)&pij, g_pij);
    cudaGetSymbolAddress((void**)&h2,  g_h2);
    cudaGetSymbolAddress((void**)&h4p, g_h4p);
    cudaGetSymbolAddress((void**)&msum, g_msum);
    cudaGetSymbolAddress((void**)&bs1, g_bs1);
    cudaGetSymbolAddress((void**)&bq1, g_bq1);
    cudaGetSymbolAddress((void**)&bs2, g_bs2);
    cudaGetSymbolAddress((void**)&bq2, g_bq2);

    __nv_bfloat16 *xh,*xl,*Wgh,*Wgl,*hph,*hpl,*alh,*all,*nfh,*nfl,*W1h,*W1l;
    __nv_bfloat16 *cmh,*cml,*h1h,*h1l,*gc1h,*gc1l,*h2h,*h2l,*h3h,*h3l,*gc2h,*gc2l;
    cudaGetSymbolAddress((void**)&xh,  g_xh);   cudaGetSymbolAddress((void**)&xl,  g_xl);
    cudaGetSymbolAddress((void**)&Wgh, g_Wgh);  cudaGetSymbolAddress((void**)&Wgl, g_Wgl);
    cudaGetSymbolAddress((void**)&hph, g_hph);  cudaGetSymbolAddress((void**)&hpl, g_hpl);
    cudaGetSymbolAddress((void**)&alh, g_alh);  cudaGetSymbolAddress((void**)&all, g_all);
    cudaGetSymbolAddress((void**)&nfh, g_nfh);  cudaGetSymbolAddress((void**)&nfl, g_nfl);
    cudaGetSymbolAddress((void**)&W1h, g_W1h);  cudaGetSymbolAddress((void**)&W1l, g_W1l);
    cudaGetSymbolAddress((void**)&cmh, g_cmh);  cudaGetSymbolAddress((void**)&cml, g_cml);
    cudaGetSymbolAddress((void**)&h1h, g_h1h);  cudaGetSymbolAddress((void**)&h1l, g_h1l);
    cudaGetSymbolAddress((void**)&gc1h,g_gc1h); cudaGetSymbolAddress((void**)&gc1l,g_gc1l);
    cudaGetSymbolAddress((void**)&h2h, g_h2h);  cudaGetSymbolAddress((void**)&h2l, g_h2l);
    cudaGetSymbolAddress((void**)&h3h, g_h3h);  cudaGetSymbolAddress((void**)&h3l, g_h3l);
    cudaGetSymbolAddress((void**)&gc2h,g_gc2h); cudaGetSymbolAddress((void**)&gc2l,g_gc2l);

    // dynamic smem sizes (double-buffered staging; epilogue scratch is smaller)
    const int SM128T = 2 * (2*64*40 + 2*128*40) * 2;     // 61440
    const int SM128F = 2 * (2*64*40 + 2*32*136) * 2;     // 55296
    const int SM64T  = 2 * (2*64*40 + 2*64*40) * 2;      // 40960
    const int SM64F  = 2 * (2*64*40 + 2*32*72) * 2;      // 38912
    cudaFuncSetAttribute(gemm_w<128, true, 2>,  cudaFuncAttributeMaxDynamicSharedMemorySize, SM128T);
    cudaFuncSetAttribute(gemm_w<128, false, 2>, cudaFuncAttributeMaxDynamicSharedMemorySize, SM128F);
    cudaFuncSetAttribute(gemm_w<64, true, 0>,   cudaFuncAttributeMaxDynamicSharedMemorySize, SM64T);
    cudaFuncSetAttribute(gemm_w<64, true, 3>,   cudaFuncAttributeMaxDynamicSharedMemorySize, SM64T);
    cudaFuncSetAttribute(gemm_w<64, false, 2>,  cudaFuncAttributeMaxDynamicSharedMemorySize, SM64F);

    k_zero<<<512, 256>>>();

    // fused one-shot conversions of all 5 external inputs
    k_cvt5<<<784, 256>>>(x, Wg, W1, gc1w, gc2w);

    // hp = x @ Wg^T  (bf16 hi/lo only; s_i/s_j fused via attn)
    gemm_w<128, true, 2><<<dim3(CF/128, (CB*CN)/64, 1), 256, SM128T>>>(
        xh, xl, Wgh, Wgl, (float*)0, hph, hpl, CF, CF, CF, CF,
        1, 0,0, 0,0, 0,0, (const float*)0, attn, (float*)0, (float*)0);

    k_alpha<<<512, 256>>>();

    // node_feats: per (b,h)  alpha(512x512) @ hp_bh -> nf (bf16 hi/lo only)
    gemm_w<128, false, 2><<<dim3(CDH/128, CN/64, CB*CH), 256, SM128F>>>(
        alh, all, hph, hpl, (float*)0, nfh, nfl, CN, CN, CF, CF,
        CH, (long long)CH*CNN, (long long)CNN,
        (long long)CN*CF, (long long)CDH,
        (long long)CN*CF, (long long)CDH, (const float*)0,
        (const float*)0, (float*)0, (float*)0);

    // pi / pj = nf @ W1i^T / W1j^T   (fp32 only)
    gemm_w<64, true, 0><<<dim3(CAH/64, (CB*CN)/64, 2), 128, SM64T>>>(
        nfh, nfl, W1h, W1l, pij, (__nv_bfloat16*)0, (__nv_bfloat16*)0, CF, CF, 2*CF, CAH,
        1, 0, 0, (long long)CF, 0, (long long)CB*CN*CAH, 0, (const float*)0,
        (const float*)0, (float*)0, (float*)0);

    // edge scores + fused radix pass A
    k_edge<<<dim3(CN/32, CN/32, CB), 256>>>(b1, w2, b2);

    // exact top-k threshold, then masked exp (norm reciprocal folded into gemms)
    k_scan1<<<CB, 1024>>>();
    k_passB<<<dim3(128, CB), 256>>>();
    k_scan2<<<CB, 1024>>>();
    k_maskexp<<<dim3(128, CB), 256>>>();

    // h1 = (cm/Z) @ nf  (bf16 hi/lo only), 1/Z folded in
    gemm_w<128, false, 2><<<dim3(CF/128, CN/64, CB), 256, SM128F>>>(
        cmh, cml, nfh, nfl, (float*)0, h1h, h1l, CN, CN, CF, CF,
        1, (long long)CNN, 0, (long long)CN*CF, 0, (long long)CN*CF, 0, msum,
        (const float*)0, (float*)0, (float*)0);

    // h2 = h1 @ gc1_w^T  (fp32 + fused BN1 stats)   [gc1_b cancels in BN]
    gemm_w<64, true, 3><<<dim3(CHID/64, (CB*CN)/64, 1), 128, SM64T>>>(
        h1h, h1l, gc1h, gc1l, h2, (__nv_bfloat16*)0, (__nv_bfloat16*)0, CF, CF, CF, CHID,
        1, 0,0, 0,0, 0,0, (const float*)0, (const float*)0, bs1, bq1);

    k_bnrelu2<<<256, 256>>>(bn1g, bn1b);

    // h3 = (cm/Z) @ h2  (bf16 hi/lo only), 1/Z folded in
    gemm_w<64, false, 2><<<dim3(CHID/64, CN/64, CB), 128, SM64F>>>(
        cmh, cml, h2h, h2l, (float*)0, h3h, h3l, CN, CN, CHID, CHID,
        1, (long long)CNN, 0, (long long)CN*CHID, 0, (long long)CN*CHID, 0, msum,
        (const float*)0, (float*)0, (float*)0);

    // h4 = h3 @ gc2_w^T  (K-split x4 partials, fp32)
    gemm_w<64, true, 0><<<dim3(COUT/64, (CB*CN)/64, 4), 128, SM64T>>>(
        h3h, h3l, gc2h, gc2l, h4p, (__nv_bfloat16*)0, (__nv_bfloat16*)0, CHID/4, CHID, CHID, COUT,
        1, 128, 0, 128, 0, (long long)CB*CN*COUT, 0, (const float*)0,
        (const float*)0, (float*)0, (float*)0);

    k_bnstats4<<<(CB*CN)/32, COUT>>>();
    k_feat2<<<CB*16, COUT>>>(bn2g, bn2b);
    k_cls<<<1, 640>>>(clsw, clsb, out);
}